// round 6
// baseline (speedup 1.0000x reference)
#include <cuda_runtime.h>

#define BATCH 2
#define NPTS  16384
#define KNN   24
#define DPTS  64
#define DM    128
#define PDIM  60
#define NP    (BATCH*NPTS)       /* 32768 query points   */
#define NR    (NP*KNN)           /* 786432 point-neighbor rows */
#define RES_ELEMS (NP*DM)        /* 4194304 */

/* ---- scratch (static device globals: allocation-free) ---- */
__device__ float d_x [NP*DM];                 /* 16 MB  : fc1 output      */
__device__ float d_pe[(size_t)NR*DM];         /* 402 MB : pos encoding    */
__device__ float d_t [(size_t)NR*DM];         /* 402 MB : relu(h@g1+b1)   */
__device__ float d_r [NP*DM];                 /* 16 MB  : pre-fc2 reduce  */

__constant__ float c_omega[10] = {
  1.0f, 0.398107170553497250f, 0.158489319246111348f, 0.063095734448019331f,
  0.025118864315095794f, 0.01f, 0.003981071705534973f, 0.001584893192461114f,
  0.000630957344480193f, 0.000251188643150958f };

/* =========================================================================
 * K1: x = features @ fc1_w + fc1_b            rows=32768, 64 -> 128
 * block = 256 thr, tile = 64 rows; thread (f, rg) owns 32 rows x 1 col
 * ========================================================================= */
__global__ void k_fc1(const float* __restrict__ feat,
                      const float* __restrict__ w,
                      const float* __restrict__ bias)
{
    extern __shared__ float sm[];
    float* ws = sm;               /* 64*128           */
    float* fs = sm + 64*128;      /* [64][68] feat^T  */
    int t = threadIdx.x, f = t & 127, rg = t >> 7, rb = rg * 32;
    for (int i = t; i < 64*128; i += 256) ws[i] = w[i];
    int r0 = blockIdx.x * 64;
    for (int idx = t; idx < 64*64; idx += 256) {
        int j = idx & 63, r = idx >> 6;
        fs[j*68 + r] = feat[(r0 + r)*64 + j];
    }
    __syncthreads();
    float b = bias[f];
    float acc[32];
#pragma unroll
    for (int i = 0; i < 32; i++) acc[i] = b;
#pragma unroll 2
    for (int j = 0; j < 64; j++) {
        float wv = ws[j*128 + f];
        const float4* rowp = (const float4*)(fs + j*68 + rb);
#pragma unroll
        for (int q = 0; q < 8; q++) {
            float4 v = rowp[q];
            acc[4*q+0] = fmaf(v.x, wv, acc[4*q+0]);
            acc[4*q+1] = fmaf(v.y, wv, acc[4*q+1]);
            acc[4*q+2] = fmaf(v.z, wv, acc[4*q+2]);
            acc[4*q+3] = fmaf(v.w, wv, acc[4*q+3]);
        }
    }
#pragma unroll
    for (int i = 0; i < 32; i++) d_x[(r0 + rb + i)*128 + f] = acc[i];
}

/* =========================================================================
 * K2 (fused): per 64-row tile of the (b,n,k) row space:
 *   e  = sincos_pos_embed(xyz[p] - knn_xyz[row])           [64][60]
 *   t1 = relu(e @ d1 + b1)                                 [64][128]
 *   pe = t1 @ d2 + b2                 -> d_pe              [64][128]
 *   h  = x[p] - x[knn] + pe
 *   t  = relu(h @ g1 + b3)            -> d_t               [64][128]
 * persistent: d1,d2,g1 stay smem-resident. 256 thr, 1 block/SM (208 KB smem)
 * ========================================================================= */
__global__ void k_main(const float* __restrict__ xyz,
                       const int*   __restrict__ knn_idx,
                       const float* __restrict__ knn_xyz,
                       const float* __restrict__ d1w, const float* __restrict__ d1b,
                       const float* __restrict__ d2w, const float* __restrict__ d2b,
                       const float* __restrict__ g1w, const float* __restrict__ g1b)
{
    extern __shared__ float sm[];
    float* d1s = sm;                  /* 60*128  =  7680 */
    float* d2s = d1s + 60*128;        /* 128*128 = 16384 */
    float* g1s = d2s + 128*128;       /* 128*128 = 16384 */
    float* es  = g1s + 128*128;       /* [60][68] =  4080 */
    float* hs  = es  + 60*68;         /* [128][68] = 8704 */
    int t = threadIdx.x, f = t & 127, rg = t >> 7, rb = rg * 32;
    for (int i = t; i < 60*128;  i += 256) d1s[i] = d1w[i];
    for (int i = t; i < 128*128; i += 256) d2s[i] = d2w[i];
    for (int i = t; i < 128*128; i += 256) g1s[i] = g1w[i];
    float b1 = d1b[f], b2 = d2b[f], b3 = g1b[f];
    __syncthreads();

    for (int tile = blockIdx.x; tile < NR/64; tile += gridDim.x) {
        int row0 = tile * 64;
        /* ---- sincos embedding: 192 threads, thread = (row, coord) ---- */
        if (t < 192) {
            int r = t & 63, c = t >> 6;
            int grow = row0 + r;
            int p = grow / KNN;
            float g = xyz[p*3 + c] - knn_xyz[(size_t)grow*3 + c];
#pragma unroll
            for (int j = 0; j < 10; j++) {
                float a = g * c_omega[j];
                es[(c*20 + j     )*68 + r] = __sinf(a);
                es[(c*20 + 10 + j)*68 + r] = __cosf(a);
            }
        }
        __syncthreads();

        /* ---- GEMM1: t1 = relu(e @ d1 + b1) -> hs (transposed) ---- */
        float acc[32];
#pragma unroll
        for (int i = 0; i < 32; i++) acc[i] = b1;
#pragma unroll 2
        for (int j = 0; j < 60; j++) {
            float wv = d1s[j*128 + f];
            const float4* rowp = (const float4*)(es + j*68 + rb);
#pragma unroll
            for (int q = 0; q < 8; q++) {
                float4 v = rowp[q];
                acc[4*q+0] = fmaf(v.x, wv, acc[4*q+0]);
                acc[4*q+1] = fmaf(v.y, wv, acc[4*q+1]);
                acc[4*q+2] = fmaf(v.z, wv, acc[4*q+2]);
                acc[4*q+3] = fmaf(v.w, wv, acc[4*q+3]);
            }
        }
#pragma unroll
        for (int i = 0; i < 32; i++) hs[f*68 + rb + i] = fmaxf(acc[i], 0.0f);
        __syncthreads();

        /* ---- GEMM2: pe = t1 @ d2 + b2 ---- */
        float pe[32];
#pragma unroll
        for (int i = 0; i < 32; i++) pe[i] = b2;
#pragma unroll 2
        for (int j = 0; j < 128; j++) {
            float wv = d2s[j*128 + f];
            const float4* rowp = (const float4*)(hs + j*68 + rb);
#pragma unroll
            for (int q = 0; q < 8; q++) {
                float4 v = rowp[q];
                pe[4*q+0] = fmaf(v.x, wv, pe[4*q+0]);
                pe[4*q+1] = fmaf(v.y, wv, pe[4*q+1]);
                pe[4*q+2] = fmaf(v.z, wv, pe[4*q+2]);
                pe[4*q+3] = fmaf(v.w, wv, pe[4*q+3]);
            }
        }
        __syncthreads();   /* all reads of t1 in hs are done */

        /* ---- write pe, build h = x[p] - x[knn] + pe into hs ---- */
#pragma unroll
        for (int i = 0; i < 32; i++) {
            int grow = row0 + rb + i;
            d_pe[(size_t)grow*128 + f] = pe[i];
            int p  = grow / KNN;
            int bb = p >> 14;                      /* p / NPTS */
            int gi = (bb << 14) + knn_idx[grow];
            float h = d_x[p*128 + f] - d_x[gi*128 + f] + pe[i];
            hs[f*68 + rb + i] = h;
        }
        __syncthreads();

        /* ---- GEMM3: t = relu(h @ g1 + b3) -> d_t ---- */
        float a3[32];
#pragma unroll
        for (int i = 0; i < 32; i++) a3[i] = b3;
#pragma unroll 2
        for (int j = 0; j < 128; j++) {
            float wv = g1s[j*128 + f];
            const float4* rowp = (const float4*)(hs + j*68 + rb);
#pragma unroll
            for (int q = 0; q < 8; q++) {
                float4 v = rowp[q];
                a3[4*q+0] = fmaf(v.x, wv, a3[4*q+0]);
                a3[4*q+1] = fmaf(v.y, wv, a3[4*q+1]);
                a3[4*q+2] = fmaf(v.z, wv, a3[4*q+2]);
                a3[4*q+3] = fmaf(v.w, wv, a3[4*q+3]);
            }
        }
#pragma unroll
        for (int i = 0; i < 32; i++)
            d_t[(size_t)(row0 + rb + i)*128 + f] = fmaxf(a3[i], 0.0f);
        __syncthreads();   /* tile buffers reused next iteration */
    }
}

/* =========================================================================
 * K3: per point p (128 thr = one channel each):
 *   logits = t @ g2 + b2 ; softmax over k ; attn -> d_out
 *   r[f]   = sum_k attn[k][f] * (x[knn] + pe)[k][f]   -> d_r
 * persistent, g2 smem-resident, 2 blocks/SM.
 * ========================================================================= */
__global__ void k_attn(const int* __restrict__ knn_idx,
                       const float* __restrict__ g2w, const float* __restrict__ g2b,
                       float* __restrict__ out_attn)
{
    extern __shared__ float sm[];
    float* g2s = sm;              /* 128*128  */
    float* ts  = sm + 128*128;    /* [128][28] t^T for one point */
    int f = threadIdx.x;
    for (int i = f; i < 128*128; i += 128) g2s[i] = g2w[i];
    float b = g2b[f];
    __syncthreads();
    const float scale = 0.0883883476483184406f;   /* 1/sqrt(128) */

    for (int p = blockIdx.x; p < NP; p += gridDim.x) {
        int base = p * KNN;
#pragma unroll
        for (int k = 0; k < KNN; k++)
            ts[f*28 + k] = d_t[(size_t)(base + k)*128 + f];
        __syncthreads();

        float acc[KNN];
#pragma unroll
        for (int k = 0; k < KNN; k++) acc[k] = b;
#pragma unroll 2
        for (int j = 0; j < 128; j++) {
            float wv = g2s[j*128 + f];
            const float4* rowp = (const float4*)(ts + j*28);
#pragma unroll
            for (int q = 0; q < 6; q++) {
                float4 v = rowp[q];
                acc[4*q+0] = fmaf(v.x, wv, acc[4*q+0]);
                acc[4*q+1] = fmaf(v.y, wv, acc[4*q+1]);
                acc[4*q+2] = fmaf(v.z, wv, acc[4*q+2]);
                acc[4*q+3] = fmaf(v.w, wv, acc[4*q+3]);
            }
        }
        /* softmax over k, fully in registers (thread owns channel f) */
        float m = -1e30f;
#pragma unroll
        for (int k = 0; k < KNN; k++) { acc[k] *= scale; m = fmaxf(m, acc[k]); }
        float s = 0.0f;
#pragma unroll
        for (int k = 0; k < KNN; k++) { acc[k] = __expf(acc[k] - m); s += acc[k]; }
        float inv = 1.0f / s;

        int bb = p >> 14;
        float rv = 0.0f;
#pragma unroll
        for (int k = 0; k < KNN; k++) {
            float a = acc[k] * inv;
            int grow = base + k;
            out_attn[(size_t)grow*128 + f] = a;
            int gi = (bb << 14) + knn_idx[grow];
            float wv = d_x[gi*128 + f] + d_pe[(size_t)grow*128 + f];
            rv = fmaf(a, wv, rv);
        }
        d_r[p*128 + f] = rv;
        __syncthreads();   /* before ts is overwritten for next point */
    }
}

/* =========================================================================
 * K4: res = r @ fc2 + fc2_b + x  -> d_out[0 .. NP*128)
 * ========================================================================= */
__global__ void k_fc2(const float* __restrict__ w, const float* __restrict__ bias,
                      float* __restrict__ out_res)
{
    extern __shared__ float sm[];
    float* ws = sm;               /* 128*128  */
    float* rs = sm + 128*128;     /* [128][68] */
    int t = threadIdx.x, f = t & 127, rg = t >> 7, rb = rg * 32;
    for (int i = t; i < 128*128; i += 256) ws[i] = w[i];
    int r0 = blockIdx.x * 64;
    for (int idx = t; idx < 64*128; idx += 256) {
        int j = idx & 127, r = idx >> 7;
        rs[j*68 + r] = d_r[(r0 + r)*128 + j];
    }
    __syncthreads();
    float b = bias[f];
    float acc[32];
#pragma unroll
    for (int i = 0; i < 32; i++) acc[i] = b;
#pragma unroll 2
    for (int j = 0; j < 128; j++) {
        float wv = ws[j*128 + f];
        const float4* rowp = (const float4*)(rs + j*68 + rb);
#pragma unroll
        for (int q = 0; q < 8; q++) {
            float4 v = rowp[q];
            acc[4*q+0] = fmaf(v.x, wv, acc[4*q+0]);
            acc[4*q+1] = fmaf(v.y, wv, acc[4*q+1]);
            acc[4*q+2] = fmaf(v.z, wv, acc[4*q+2]);
            acc[4*q+3] = fmaf(v.w, wv, acc[4*q+3]);
        }
    }
#pragma unroll
    for (int i = 0; i < 32; i++) {
        int row = r0 + rb + i;
        out_res[row*128 + f] = acc[i] + d_x[row*128 + f];
    }
}

/* ========================================================================= */
extern "C" void kernel_launch(void* const* d_in, const int* in_sizes, int n_in,
                              void* d_out, int out_size)
{
    const float* feat = (const float*)d_in[0];
    const float* xyz  = (const float*)d_in[1];
    const int*   knn  = (const int*  )d_in[2];
    const float* kxyz = (const float*)d_in[3];
    const float* fc1w = (const float*)d_in[4];
    const float* fc1b = (const float*)d_in[5];
    const float* fc2w = (const float*)d_in[6];
    const float* fc2b = (const float*)d_in[7];
    const float* d1w  = (const float*)d_in[8];
    const float* d1b  = (const float*)d_in[9];
    const float* d2w  = (const float*)d_in[10];
    const float* d2b  = (const float*)d_in[11];
    const float* g1w  = (const float*)d_in[12];
    const float* g1b  = (const float*)d_in[13];
    const float* g2w  = (const float*)d_in[14];
    const float* g2b  = (const float*)d_in[15];
    float* out = (float*)d_out;

    int sms = 148;
    cudaDeviceGetAttribute(&sms, cudaDevAttrMultiProcessorCount, 0);

    size_t sm1  = (size_t)(64*128 + 64*68) * 4;                              /* 50176  */
    size_t sm23 = (size_t)(60*128 + 2*128*128 + 60*68 + 128*68) * 4;         /* 212928 */
    size_t sm4  = (size_t)(128*128 + 128*28) * 4;                            /* 79872  */
    size_t sm5  = (size_t)(128*128 + 128*68) * 4;                            /* 100352 */

    cudaFuncSetAttribute(k_fc1,  cudaFuncAttributeMaxDynamicSharedMemorySize, (int)sm1);
    cudaFuncSetAttribute(k_main, cudaFuncAttributeMaxDynamicSharedMemorySize, (int)sm23);
    cudaFuncSetAttribute(k_attn, cudaFuncAttributeMaxDynamicSharedMemorySize, (int)sm4);
    cudaFuncSetAttribute(k_fc2,  cudaFuncAttributeMaxDynamicSharedMemorySize, (int)sm5);

    k_fc1 <<<NP/64, 256, sm1 >>>(feat, fc1w, fc1b);
    k_main<<<sms,   256, sm23>>>(xyz, knn, kxyz, d1w, d1b, d2w, d2b, g1w, g1b);
    k_attn<<<2*sms, 128, sm4 >>>(knn, g2w, g2b, out + RES_ELEMS);
    k_fc2 <<<NP/64, 256, sm5 >>>(fc2w, fc2b, out);
}

// round 7
// speedup vs baseline: 1.6454x; 1.6454x over previous
#include <cuda_runtime.h>

#define BATCH 2
#define NPTS  16384
#define KNN   24
#define DPTS  64
#define DM    128
#define PDIM  60
#define NP    (BATCH*NPTS)       /* 32768 query points   */
#define NR    (NP*KNN)           /* 786432 point-neighbor rows */
#define RES_ELEMS (NP*DM)        /* 4194304 */

typedef unsigned long long u64;

/* ---- packed dual-fp32 FMA (sm_103a FFMA2, only reachable via PTX) ---- */
__device__ __forceinline__ u64 pack2(float x, float y) {
    u64 r;
    asm("mov.b64 %0, {%1, %2};" : "=l"(r)
        : "r"(__float_as_uint(x)), "r"(__float_as_uint(y)));
    return r;
}
__device__ __forceinline__ void unpack2(u64 v, float& x, float& y) {
    unsigned lo, hi;
    asm("mov.b64 {%0, %1}, %2;" : "=r"(lo), "=r"(hi) : "l"(v));
    x = __uint_as_float(lo); y = __uint_as_float(hi);
}
__device__ __forceinline__ void ffma2(u64& d, u64 a, u64 b) {
    asm("fma.rn.f32x2 %0, %1, %2, %0;" : "+l"(d) : "l"(a), "l"(b));
}

/* ---- scratch (static device globals: allocation-free) ---- */
__device__ float d_x [NP*DM];                 /* 16 MB  : fc1 output      */
__device__ float d_pe[(size_t)NR*DM];         /* 402 MB : pos encoding    */
__device__ float d_t [(size_t)NR*DM];         /* 402 MB : relu(h@g1+b1)   */
__device__ float d_r [NP*DM];                 /* 16 MB  : pre-fc2 reduce  */

__constant__ float c_omega[10] = {
  1.0f, 0.398107170553497250f, 0.158489319246111348f, 0.063095734448019331f,
  0.025118864315095794f, 0.01f, 0.003981071705534973f, 0.001584893192461114f,
  0.000630957344480193f, 0.000251188643150958f };

/* =========================================================================
 * K1: x = features @ fc1_w + fc1_b            rows=32768, 64 -> 128
 * block = 256 thr, tile = 64 rows; thread (f, rg) owns 32 rows x 1 col
 * Accumulators packed as 16 fp32x2 pairs along the row dimension.
 * ========================================================================= */
__global__ void k_fc1(const float* __restrict__ feat,
                      const float* __restrict__ w,
                      const float* __restrict__ bias)
{
    extern __shared__ float sm[];
    float* ws = sm;               /* 64*128           */
    float* fs = sm + 64*128;      /* [64][68] feat^T  */
    int t = threadIdx.x, f = t & 127, rg = t >> 7, rb = rg * 32;
    for (int i = t; i < 64*128; i += 256) ws[i] = w[i];
    int r0 = blockIdx.x * 64;
    for (int idx = t; idx < 64*64; idx += 256) {
        int j = idx & 63, r = idx >> 6;
        fs[j*68 + r] = feat[(r0 + r)*64 + j];
    }
    __syncthreads();
    float b = bias[f];
    u64 bp = pack2(b, b);
    u64 acc[16];
#pragma unroll
    for (int i = 0; i < 16; i++) acc[i] = bp;
#pragma unroll 2
    for (int j = 0; j < 64; j++) {
        float wv = ws[j*128 + f];
        u64 wvp = pack2(wv, wv);
        const ulonglong2* rowp = (const ulonglong2*)(fs + j*68 + rb);
#pragma unroll
        for (int q = 0; q < 8; q++) {
            ulonglong2 v = rowp[q];
            ffma2(acc[2*q+0], v.x, wvp);
            ffma2(acc[2*q+1], v.y, wvp);
        }
    }
#pragma unroll
    for (int i = 0; i < 16; i++) {
        float lo, hi; unpack2(acc[i], lo, hi);
        d_x[(r0 + rb + 2*i    )*128 + f] = lo;
        d_x[(r0 + rb + 2*i + 1)*128 + f] = hi;
    }
}

/* =========================================================================
 * K2 (fused): per 64-row tile of the (b,n,k) row space:
 *   e  = sincos_pos_embed(xyz[p] - knn_xyz[row])           [64][60]
 *   t1 = relu(e @ d1 + b1)                                 [64][128]
 *   pe = t1 @ d2 + b2                 -> d_pe              [64][128]
 *   h  = x[p] - x[knn] + pe
 *   t  = relu(h @ g1 + b3)            -> d_t               [64][128]
 * persistent: d1,d2,g1 stay smem-resident. 256 thr, 1 block/SM (208 KB smem)
 * All GEMMs use packed fp32x2 FMA.
 * ========================================================================= */
__global__ void k_main(const float* __restrict__ xyz,
                       const int*   __restrict__ knn_idx,
                       const float* __restrict__ knn_xyz,
                       const float* __restrict__ d1w, const float* __restrict__ d1b,
                       const float* __restrict__ d2w, const float* __restrict__ d2b,
                       const float* __restrict__ g1w, const float* __restrict__ g1b)
{
    extern __shared__ float sm[];
    float* d1s = sm;                  /* 60*128  =  7680 */
    float* d2s = d1s + 60*128;        /* 128*128 = 16384 */
    float* g1s = d2s + 128*128;       /* 128*128 = 16384 */
    float* es  = g1s + 128*128;       /* [60][68] =  4080 */
    float* hs  = es  + 60*68;         /* [128][68] = 8704 */
    int t = threadIdx.x, f = t & 127, rg = t >> 7, rb = rg * 32;
    for (int i = t; i < 60*128;  i += 256) d1s[i] = d1w[i];
    for (int i = t; i < 128*128; i += 256) d2s[i] = d2w[i];
    for (int i = t; i < 128*128; i += 256) g1s[i] = g1w[i];
    float b1 = d1b[f], b2 = d2b[f], b3 = g1b[f];
    u64 b1p = pack2(b1, b1), b2p = pack2(b2, b2), b3p = pack2(b3, b3);
    __syncthreads();

    for (int tile = blockIdx.x; tile < NR/64; tile += gridDim.x) {
        int row0 = tile * 64;
        /* ---- sincos embedding: 192 threads, thread = (row, coord) ---- */
        if (t < 192) {
            int r = t & 63, c = t >> 6;
            int grow = row0 + r;
            int p = grow / KNN;
            float g = xyz[p*3 + c] - knn_xyz[(size_t)grow*3 + c];
#pragma unroll
            for (int j = 0; j < 10; j++) {
                float a = g * c_omega[j];
                es[(c*20 + j     )*68 + r] = __sinf(a);
                es[(c*20 + 10 + j)*68 + r] = __cosf(a);
            }
        }
        __syncthreads();

        /* ---- GEMM1: t1 = relu(e @ d1 + b1) -> hs (transposed) ---- */
        u64 acc[16];
#pragma unroll
        for (int i = 0; i < 16; i++) acc[i] = b1p;
#pragma unroll 2
        for (int j = 0; j < 60; j++) {
            float wv = d1s[j*128 + f];
            u64 wvp = pack2(wv, wv);
            const ulonglong2* rowp = (const ulonglong2*)(es + j*68 + rb);
#pragma unroll
            for (int q = 0; q < 8; q++) {
                ulonglong2 v = rowp[q];
                ffma2(acc[2*q+0], v.x, wvp);
                ffma2(acc[2*q+1], v.y, wvp);
            }
        }
#pragma unroll
        for (int i = 0; i < 16; i++) {
            float lo, hi; unpack2(acc[i], lo, hi);
            hs[f*68 + rb + 2*i    ] = fmaxf(lo, 0.0f);
            hs[f*68 + rb + 2*i + 1] = fmaxf(hi, 0.0f);
        }
        __syncthreads();

        /* ---- GEMM2: pe = t1 @ d2 + b2 ---- */
        u64 pep[16];
#pragma unroll
        for (int i = 0; i < 16; i++) pep[i] = b2p;
#pragma unroll 2
        for (int j = 0; j < 128; j++) {
            float wv = d2s[j*128 + f];
            u64 wvp = pack2(wv, wv);
            const ulonglong2* rowp = (const ulonglong2*)(hs + j*68 + rb);
#pragma unroll
            for (int q = 0; q < 8; q++) {
                ulonglong2 v = rowp[q];
                ffma2(pep[2*q+0], v.x, wvp);
                ffma2(pep[2*q+1], v.y, wvp);
            }
        }
        __syncthreads();   /* all reads of t1 in hs are done */

        /* ---- write pe, build h = x[p] - x[knn] + pe into hs ---- */
#pragma unroll
        for (int i = 0; i < 16; i++) {
            float pl, ph; unpack2(pep[i], pl, ph);
#pragma unroll
            for (int s = 0; s < 2; s++) {
                float pv = s ? ph : pl;
                int grow = row0 + rb + 2*i + s;
                d_pe[(size_t)grow*128 + f] = pv;
                int p  = grow / KNN;
                int bb = p >> 14;                      /* p / NPTS */
                int gi = (bb << 14) + knn_idx[grow];
                float h = d_x[p*128 + f] - d_x[gi*128 + f] + pv;
                hs[f*68 + rb + 2*i + s] = h;
            }
        }
        __syncthreads();

        /* ---- GEMM3: t = relu(h @ g1 + b3) -> d_t ---- */
        u64 a3[16];
#pragma unroll
        for (int i = 0; i < 16; i++) a3[i] = b3p;
#pragma unroll 2
        for (int j = 0; j < 128; j++) {
            float wv = g1s[j*128 + f];
            u64 wvp = pack2(wv, wv);
            const ulonglong2* rowp = (const ulonglong2*)(hs + j*68 + rb);
#pragma unroll
            for (int q = 0; q < 8; q++) {
                ulonglong2 v = rowp[q];
                ffma2(a3[2*q+0], v.x, wvp);
                ffma2(a3[2*q+1], v.y, wvp);
            }
        }
#pragma unroll
        for (int i = 0; i < 16; i++) {
            float lo, hi; unpack2(a3[i], lo, hi);
            d_t[(size_t)(row0 + rb + 2*i    )*128 + f] = fmaxf(lo, 0.0f);
            d_t[(size_t)(row0 + rb + 2*i + 1)*128 + f] = fmaxf(hi, 0.0f);
        }
        __syncthreads();   /* tile buffers reused next iteration */
    }
}

/* =========================================================================
 * K3: per point p (128 thr = one channel each):
 *   logits = t @ g2 + b2 ; softmax over k ; attn -> d_out
 *   r[f]   = sum_k attn[k][f] * (x[knn] + pe)[k][f]   -> d_r
 * persistent, g2 smem-resident, 2 blocks/SM. fp32x2 FMA along k.
 * ========================================================================= */
__global__ void k_attn(const int* __restrict__ knn_idx,
                       const float* __restrict__ g2w, const float* __restrict__ g2b,
                       float* __restrict__ out_attn)
{
    extern __shared__ float sm[];
    float* g2s = sm;              /* 128*128  */
    float* ts  = sm + 128*128;    /* [128][28] t^T for one point */
    int f = threadIdx.x;
    for (int i = f; i < 128*128; i += 128) g2s[i] = g2w[i];
    float b = g2b[f];
    u64 bp = pack2(b, b);
    __syncthreads();
    const float scale = 0.0883883476483184406f;   /* 1/sqrt(128) */

    for (int p = blockIdx.x; p < NP; p += gridDim.x) {
        int base = p * KNN;
#pragma unroll
        for (int k = 0; k < KNN; k++)
            ts[f*28 + k] = d_t[(size_t)(base + k)*128 + f];
        __syncthreads();

        u64 accp[12];
#pragma unroll
        for (int k = 0; k < 12; k++) accp[k] = bp;
#pragma unroll 2
        for (int j = 0; j < 128; j++) {
            float wv = g2s[j*128 + f];
            u64 wvp = pack2(wv, wv);
            const ulonglong2* rowp = (const ulonglong2*)(ts + j*28);
#pragma unroll
            for (int q = 0; q < 6; q++) {
                ulonglong2 v = rowp[q];
                ffma2(accp[2*q+0], v.x, wvp);
                ffma2(accp[2*q+1], v.y, wvp);
            }
        }
        float acc[KNN];
#pragma unroll
        for (int k = 0; k < 12; k++) unpack2(accp[k], acc[2*k], acc[2*k+1]);

        /* softmax over k, fully in registers (thread owns channel f) */
        float m = -1e30f;
#pragma unroll
        for (int k = 0; k < KNN; k++) { acc[k] *= scale; m = fmaxf(m, acc[k]); }
        float s = 0.0f;
#pragma unroll
        for (int k = 0; k < KNN; k++) { acc[k] = __expf(acc[k] - m); s += acc[k]; }
        float inv = 1.0f / s;

        int bb = p >> 14;
        float rv = 0.0f;
#pragma unroll
        for (int k = 0; k < KNN; k++) {
            float a = acc[k] * inv;
            int grow = base + k;
            out_attn[(size_t)grow*128 + f] = a;
            int gi = (bb << 14) + knn_idx[grow];
            float wv = d_x[gi*128 + f] + d_pe[(size_t)grow*128 + f];
            rv = fmaf(a, wv, rv);
        }
        d_r[p*128 + f] = rv;
        __syncthreads();   /* before ts is overwritten for next point */
    }
}

/* =========================================================================
 * K4: res = r @ fc2 + fc2_b + x  -> d_out[0 .. NP*128)
 * ========================================================================= */
__global__ void k_fc2(const float* __restrict__ w, const float* __restrict__ bias,
                      float* __restrict__ out_res)
{
    extern __shared__ float sm[];
    float* ws = sm;               /* 128*128  */
    float* rs = sm + 128*128;     /* [128][68] */
    int t = threadIdx.x, f = t & 127, rg = t >> 7, rb = rg * 32;
    for (int i = t; i < 128*128; i += 256) ws[i] = w[i];
    int r0 = blockIdx.x * 64;
    for (int idx = t; idx < 64*128; idx += 256) {
        int j = idx & 127, r = idx >> 7;
        rs[j*68 + r] = d_r[(r0 + r)*128 + j];
    }
    __syncthreads();
    float b = bias[f];
    u64 bp = pack2(b, b);
    u64 acc[16];
#pragma unroll
    for (int i = 0; i < 16; i++) acc[i] = bp;
#pragma unroll 2
    for (int j = 0; j < 128; j++) {
        float wv = ws[j*128 + f];
        u64 wvp = pack2(wv, wv);
        const ulonglong2* rowp = (const ulonglong2*)(rs + j*68 + rb);
#pragma unroll
        for (int q = 0; q < 8; q++) {
            ulonglong2 v = rowp[q];
            ffma2(acc[2*q+0], v.x, wvp);
            ffma2(acc[2*q+1], v.y, wvp);
        }
    }
#pragma unroll
    for (int i = 0; i < 16; i++) {
        float lo, hi; unpack2(acc[i], lo, hi);
        int row = r0 + rb + 2*i;
        out_res[ row     *128 + f] = lo + d_x[ row     *128 + f];
        out_res[(row + 1)*128 + f] = hi + d_x[(row + 1)*128 + f];
    }
}

/* ========================================================================= */
extern "C" void kernel_launch(void* const* d_in, const int* in_sizes, int n_in,
                              void* d_out, int out_size)
{
    const float* feat = (const float*)d_in[0];
    const float* xyz  = (const float*)d_in[1];
    const int*   knn  = (const int*  )d_in[2];
    const float* kxyz = (const float*)d_in[3];
    const float* fc1w = (const float*)d_in[4];
    const float* fc1b = (const float*)d_in[5];
    const float* fc2w = (const float*)d_in[6];
    const float* fc2b = (const float*)d_in[7];
    const float* d1w  = (const float*)d_in[8];
    const float* d1b  = (const float*)d_in[9];
    const float* d2w  = (const float*)d_in[10];
    const float* d2b  = (const float*)d_in[11];
    const float* g1w  = (const float*)d_in[12];
    const float* g1b  = (const float*)d_in[13];
    const float* g2w  = (const float*)d_in[14];
    const float* g2b  = (const float*)d_in[15];
    float* out = (float*)d_out;

    int sms = 148;
    cudaDeviceGetAttribute(&sms, cudaDevAttrMultiProcessorCount, 0);

    size_t sm1  = (size_t)(64*128 + 64*68) * 4;                              /* 50176  */
    size_t sm23 = (size_t)(60*128 + 2*128*128 + 60*68 + 128*68) * 4;         /* 212928 */
    size_t sm4  = (size_t)(128*128 + 128*28) * 4;                            /* 79872  */
    size_t sm5  = (size_t)(128*128 + 128*68) * 4;                            /* 100352 */

    cudaFuncSetAttribute(k_fc1,  cudaFuncAttributeMaxDynamicSharedMemorySize, (int)sm1);
    cudaFuncSetAttribute(k_main, cudaFuncAttributeMaxDynamicSharedMemorySize, (int)sm23);
    cudaFuncSetAttribute(k_attn, cudaFuncAttributeMaxDynamicSharedMemorySize, (int)sm4);
    cudaFuncSetAttribute(k_fc2,  cudaFuncAttributeMaxDynamicSharedMemorySize, (int)sm5);

    k_fc1 <<<NP/64, 256, sm1 >>>(feat, fc1w, fc1b);
    k_main<<<sms,   256, sm23>>>(xyz, knn, kxyz, d1w, d1b, d2w, d2b, g1w, g1b);
    k_attn<<<2*sms, 128, sm4 >>>(knn, g2w, g2b, out + RES_ELEMS);
    k_fc2 <<<NP/64, 256, sm5 >>>(fc2w, fc2b, out);
}

// round 8
// speedup vs baseline: 1.6458x; 1.0002x over previous
#include <cuda_runtime.h>

#define BATCH 2
#define NPTS  16384
#define KNN   24
#define DPTS  64
#define DM    128
#define PDIM  60
#define NP    (BATCH*NPTS)       /* 32768 query points   */
#define NR    (NP*KNN)           /* 786432 point-neighbor rows */
#define RES_ELEMS (NP*DM)        /* 4194304 */

typedef unsigned long long u64;

/* ---- packed dual-fp32 FMA (sm_103a FFMA2, only reachable via PTX) ---- */
__device__ __forceinline__ u64 pack2(float x, float y) {
    u64 r;
    asm("mov.b64 %0, {%1, %2};" : "=l"(r)
        : "r"(__float_as_uint(x)), "r"(__float_as_uint(y)));
    return r;
}
__device__ __forceinline__ void unpack2(u64 v, float& x, float& y) {
    unsigned lo, hi;
    asm("mov.b64 {%0, %1}, %2;" : "=r"(lo), "=r"(hi) : "l"(v));
    x = __uint_as_float(lo); y = __uint_as_float(hi);
}
__device__ __forceinline__ void ffma2(u64& d, u64 a, u64 b) {
    asm("fma.rn.f32x2 %0, %1, %2, %0;" : "+l"(d) : "l"(a), "l"(b));
}

/* ---- scratch (static device globals: allocation-free) ---- */
__device__ float d_x [NP*DM];                 /* 16 MB  : fc1 output      */
__device__ float d_pe[(size_t)NR*DM];         /* 402 MB : pos encoding    */
__device__ float d_t [(size_t)NR*DM];         /* 402 MB : relu(h@g1+b1)   */
__device__ float d_r [NP*DM];                 /* 16 MB  : pre-fc2 reduce  */

__constant__ float c_omega[10] = {
  1.0f, 0.398107170553497250f, 0.158489319246111348f, 0.063095734448019331f,
  0.025118864315095794f, 0.01f, 0.003981071705534973f, 0.001584893192461114f,
  0.000630957344480193f, 0.000251188643150958f };

/* =========================================================================
 * K1: x = features @ fc1_w + fc1_b            rows=32768, 64 -> 128
 * block = 256 thr, tile = 64 rows; thread (f, rg) owns 32 rows x 1 col
 * Accumulators packed as 16 fp32x2 pairs along the row dimension.
 * ========================================================================= */
__global__ void k_fc1(const float* __restrict__ feat,
                      const float* __restrict__ w,
                      const float* __restrict__ bias)
{
    extern __shared__ float sm[];
    float* ws = sm;               /* 64*128           */
    float* fs = sm + 64*128;      /* [64][68] feat^T  */
    int t = threadIdx.x, f = t & 127, rg = t >> 7, rb = rg * 32;
    for (int i = t; i < 64*128; i += 256) ws[i] = w[i];
    int r0 = blockIdx.x * 64;
    for (int idx = t; idx < 64*64; idx += 256) {
        int j = idx & 63, r = idx >> 6;
        fs[j*68 + r] = feat[(r0 + r)*64 + j];
    }
    __syncthreads();
    float b = bias[f];
    u64 bp = pack2(b, b);
    u64 acc[16];
#pragma unroll
    for (int i = 0; i < 16; i++) acc[i] = bp;
#pragma unroll 2
    for (int j = 0; j < 64; j++) {
        float wv = ws[j*128 + f];
        u64 wvp = pack2(wv, wv);
        const ulonglong2* rowp = (const ulonglong2*)(fs + j*68 + rb);
#pragma unroll
        for (int q = 0; q < 8; q++) {
            ulonglong2 v = rowp[q];
            ffma2(acc[2*q+0], v.x, wvp);
            ffma2(acc[2*q+1], v.y, wvp);
        }
    }
#pragma unroll
    for (int i = 0; i < 16; i++) {
        float lo, hi; unpack2(acc[i], lo, hi);
        d_x[(r0 + rb + 2*i    )*128 + f] = lo;
        d_x[(r0 + rb + 2*i + 1)*128 + f] = hi;
    }
}

/* =========================================================================
 * K2 (fused): per 64-row tile of the (b,n,k) row space:
 *   e  = sincos_pos_embed(xyz[p] - knn_xyz[row])           [64][60]
 *   t1 = relu(e @ d1 + b1)                                 [64][128]
 *   pe = t1 @ d2 + b2                 -> d_pe              [64][128]
 *   h  = x[p] - x[knn] + pe
 *   t  = relu(h @ g1 + b3)            -> d_t               [64][128]
 * persistent: d1,d2,g1 stay smem-resident. 256 thr, 1 block/SM (208 KB smem)
 * All GEMMs use packed fp32x2 FMA.
 * ========================================================================= */
__global__ void k_main(const float* __restrict__ xyz,
                       const int*   __restrict__ knn_idx,
                       const float* __restrict__ knn_xyz,
                       const float* __restrict__ d1w, const float* __restrict__ d1b,
                       const float* __restrict__ d2w, const float* __restrict__ d2b,
                       const float* __restrict__ g1w, const float* __restrict__ g1b)
{
    extern __shared__ float sm[];
    float* d1s = sm;                  /* 60*128  =  7680 */
    float* d2s = d1s + 60*128;        /* 128*128 = 16384 */
    float* g1s = d2s + 128*128;       /* 128*128 = 16384 */
    float* es  = g1s + 128*128;       /* [60][68] =  4080 */
    float* hs  = es  + 60*68;         /* [128][68] = 8704 */
    int t = threadIdx.x, f = t & 127, rg = t >> 7, rb = rg * 32;
    for (int i = t; i < 60*128;  i += 256) d1s[i] = d1w[i];
    for (int i = t; i < 128*128; i += 256) d2s[i] = d2w[i];
    for (int i = t; i < 128*128; i += 256) g1s[i] = g1w[i];
    float b1 = d1b[f], b2 = d2b[f], b3 = g1b[f];
    u64 b1p = pack2(b1, b1), b2p = pack2(b2, b2), b3p = pack2(b3, b3);
    __syncthreads();

    for (int tile = blockIdx.x; tile < NR/64; tile += gridDim.x) {
        int row0 = tile * 64;
        /* ---- sincos embedding: 192 threads, thread = (row, coord) ---- */
        if (t < 192) {
            int r = t & 63, c = t >> 6;
            int grow = row0 + r;
            int p = grow / KNN;
            float g = xyz[p*3 + c] - knn_xyz[(size_t)grow*3 + c];
#pragma unroll
            for (int j = 0; j < 10; j++) {
                float a = g * c_omega[j];
                es[(c*20 + j     )*68 + r] = __sinf(a);
                es[(c*20 + 10 + j)*68 + r] = __cosf(a);
            }
        }
        __syncthreads();

        /* ---- GEMM1: t1 = relu(e @ d1 + b1) -> hs (transposed) ---- */
        u64 acc[16];
#pragma unroll
        for (int i = 0; i < 16; i++) acc[i] = b1p;
#pragma unroll 2
        for (int j = 0; j < 60; j++) {
            float wv = d1s[j*128 + f];
            u64 wvp = pack2(wv, wv);
            const ulonglong2* rowp = (const ulonglong2*)(es + j*68 + rb);
#pragma unroll
            for (int q = 0; q < 8; q++) {
                ulonglong2 v = rowp[q];
                ffma2(acc[2*q+0], v.x, wvp);
                ffma2(acc[2*q+1], v.y, wvp);
            }
        }
#pragma unroll
        for (int i = 0; i < 16; i++) {
            float lo, hi; unpack2(acc[i], lo, hi);
            hs[f*68 + rb + 2*i    ] = fmaxf(lo, 0.0f);
            hs[f*68 + rb + 2*i + 1] = fmaxf(hi, 0.0f);
        }
        __syncthreads();

        /* ---- GEMM2: pe = t1 @ d2 + b2 ---- */
        u64 pep[16];
#pragma unroll
        for (int i = 0; i < 16; i++) pep[i] = b2p;
#pragma unroll 2
        for (int j = 0; j < 128; j++) {
            float wv = d2s[j*128 + f];
            u64 wvp = pack2(wv, wv);
            const ulonglong2* rowp = (const ulonglong2*)(hs + j*68 + rb);
#pragma unroll
            for (int q = 0; q < 8; q++) {
                ulonglong2 v = rowp[q];
                ffma2(pep[2*q+0], v.x, wvp);
                ffma2(pep[2*q+1], v.y, wvp);
            }
        }
        __syncthreads();   /* all reads of t1 in hs are done */

        /* ---- write pe, build h = x[p] - x[knn] + pe into hs ---- */
#pragma unroll
        for (int i = 0; i < 16; i++) {
            float pl, ph; unpack2(pep[i], pl, ph);
#pragma unroll
            for (int s = 0; s < 2; s++) {
                float pv = s ? ph : pl;
                int grow = row0 + rb + 2*i + s;
                d_pe[(size_t)grow*128 + f] = pv;
                int p  = grow / KNN;
                int bb = p >> 14;                      /* p / NPTS */
                int gi = (bb << 14) + knn_idx[grow];
                float h = d_x[p*128 + f] - d_x[gi*128 + f] + pv;
                hs[f*68 + rb + 2*i + s] = h;
            }
        }
        __syncthreads();

        /* ---- GEMM3: t = relu(h @ g1 + b3) -> d_t ---- */
        u64 a3[16];
#pragma unroll
        for (int i = 0; i < 16; i++) a3[i] = b3p;
#pragma unroll 2
        for (int j = 0; j < 128; j++) {
            float wv = g1s[j*128 + f];
            u64 wvp = pack2(wv, wv);
            const ulonglong2* rowp = (const ulonglong2*)(hs + j*68 + rb);
#pragma unroll
            for (int q = 0; q < 8; q++) {
                ulonglong2 v = rowp[q];
                ffma2(a3[2*q+0], v.x, wvp);
                ffma2(a3[2*q+1], v.y, wvp);
            }
        }
#pragma unroll
        for (int i = 0; i < 16; i++) {
            float lo, hi; unpack2(a3[i], lo, hi);
            d_t[(size_t)(row0 + rb + 2*i    )*128 + f] = fmaxf(lo, 0.0f);
            d_t[(size_t)(row0 + rb + 2*i + 1)*128 + f] = fmaxf(hi, 0.0f);
        }
        __syncthreads();   /* tile buffers reused next iteration */
    }
}

/* =========================================================================
 * K3: per point p (128 thr = one channel each):
 *   logits = t @ g2 + b2 ; softmax over k ; attn -> d_out
 *   r[f]   = sum_k attn[k][f] * (x[knn] + pe)[k][f]   -> d_r
 * persistent, g2 smem-resident, 2 blocks/SM. fp32x2 FMA along k.
 * ========================================================================= */
__global__ void k_attn(const int* __restrict__ knn_idx,
                       const float* __restrict__ g2w, const float* __restrict__ g2b,
                       float* __restrict__ out_attn)
{
    extern __shared__ float sm[];
    float* g2s = sm;              /* 128*128  */
    float* ts  = sm + 128*128;    /* [128][28] t^T for one point */
    int f = threadIdx.x;
    for (int i = f; i < 128*128; i += 128) g2s[i] = g2w[i];
    float b = g2b[f];
    u64 bp = pack2(b, b);
    __syncthreads();
    const float scale = 0.0883883476483184406f;   /* 1/sqrt(128) */

    for (int p = blockIdx.x; p < NP; p += gridDim.x) {
        int base = p * KNN;
#pragma unroll
        for (int k = 0; k < KNN; k++)
            ts[f*28 + k] = d_t[(size_t)(base + k)*128 + f];
        __syncthreads();

        u64 accp[12];
#pragma unroll
        for (int k = 0; k < 12; k++) accp[k] = bp;
#pragma unroll 2
        for (int j = 0; j < 128; j++) {
            float wv = g2s[j*128 + f];
            u64 wvp = pack2(wv, wv);
            const ulonglong2* rowp = (const ulonglong2*)(ts + j*28);
#pragma unroll
            for (int q = 0; q < 6; q++) {
                ulonglong2 v = rowp[q];
                ffma2(accp[2*q+0], v.x, wvp);
                ffma2(accp[2*q+1], v.y, wvp);
            }
        }
        float acc[KNN];
#pragma unroll
        for (int k = 0; k < 12; k++) unpack2(accp[k], acc[2*k], acc[2*k+1]);

        /* softmax over k, fully in registers (thread owns channel f) */
        float m = -1e30f;
#pragma unroll
        for (int k = 0; k < KNN; k++) { acc[k] *= scale; m = fmaxf(m, acc[k]); }
        float s = 0.0f;
#pragma unroll
        for (int k = 0; k < KNN; k++) { acc[k] = __expf(acc[k] - m); s += acc[k]; }
        float inv = 1.0f / s;

        int bb = p >> 14;
        float rv = 0.0f;
#pragma unroll
        for (int k = 0; k < KNN; k++) {
            float a = acc[k] * inv;
            int grow = base + k;
            out_attn[(size_t)grow*128 + f] = a;
            int gi = (bb << 14) + knn_idx[grow];
            float wv = d_x[gi*128 + f] + d_pe[(size_t)grow*128 + f];
            rv = fmaf(a, wv, rv);
        }
        d_r[p*128 + f] = rv;
        __syncthreads();   /* before ts is overwritten for next point */
    }
}

/* =========================================================================
 * K4: res = r @ fc2 + fc2_b + x  -> d_out[0 .. NP*128)
 * ========================================================================= */
__global__ void k_fc2(const float* __restrict__ w, const float* __restrict__ bias,
                      float* __restrict__ out_res)
{
    extern __shared__ float sm[];
    float* ws = sm;               /* 128*128  */
    float* rs = sm + 128*128;     /* [128][68] */
    int t = threadIdx.x, f = t & 127, rg = t >> 7, rb = rg * 32;
    for (int i = t; i < 128*128; i += 256) ws[i] = w[i];
    int r0 = blockIdx.x * 64;
    for (int idx = t; idx < 64*128; idx += 256) {
        int j = idx & 127, r = idx >> 7;
        rs[j*68 + r] = d_r[(r0 + r)*128 + j];
    }
    __syncthreads();
    float b = bias[f];
    u64 bp = pack2(b, b);
    u64 acc[16];
#pragma unroll
    for (int i = 0; i < 16; i++) acc[i] = bp;
#pragma unroll 2
    for (int j = 0; j < 128; j++) {
        float wv = ws[j*128 + f];
        u64 wvp = pack2(wv, wv);
        const ulonglong2* rowp = (const ulonglong2*)(rs + j*68 + rb);
#pragma unroll
        for (int q = 0; q < 8; q++) {
            ulonglong2 v = rowp[q];
            ffma2(acc[2*q+0], v.x, wvp);
            ffma2(acc[2*q+1], v.y, wvp);
        }
    }
#pragma unroll
    for (int i = 0; i < 16; i++) {
        float lo, hi; unpack2(acc[i], lo, hi);
        int row = r0 + rb + 2*i;
        out_res[ row     *128 + f] = lo + d_x[ row     *128 + f];
        out_res[(row + 1)*128 + f] = hi + d_x[(row + 1)*128 + f];
    }
}

/* ========================================================================= */
extern "C" void kernel_launch(void* const* d_in, const int* in_sizes, int n_in,
                              void* d_out, int out_size)
{
    const float* feat = (const float*)d_in[0];
    const float* xyz  = (const float*)d_in[1];
    const int*   knn  = (const int*  )d_in[2];
    const float* kxyz = (const float*)d_in[3];
    const float* fc1w = (const float*)d_in[4];
    const float* fc1b = (const float*)d_in[5];
    const float* fc2w = (const float*)d_in[6];
    const float* fc2b = (const float*)d_in[7];
    const float* d1w  = (const float*)d_in[8];
    const float* d1b  = (const float*)d_in[9];
    const float* d2w  = (const float*)d_in[10];
    const float* d2b  = (const float*)d_in[11];
    const float* g1w  = (const float*)d_in[12];
    const float* g1b  = (const float*)d_in[13];
    const float* g2w  = (const float*)d_in[14];
    const float* g2b  = (const float*)d_in[15];
    float* out = (float*)d_out;

    int sms = 148;
    cudaDeviceGetAttribute(&sms, cudaDevAttrMultiProcessorCount, 0);

    size_t sm1  = (size_t)(64*128 + 64*68) * 4;                              /* 50176  */
    size_t sm23 = (size_t)(60*128 + 2*128*128 + 60*68 + 128*68) * 4;         /* 212928 */
    size_t sm4  = (size_t)(128*128 + 128*28) * 4;                            /* 79872  */
    size_t sm5  = (size_t)(128*128 + 128*68) * 4;                            /* 100352 */

    cudaFuncSetAttribute(k_fc1,  cudaFuncAttributeMaxDynamicSharedMemorySize, (int)sm1);
    cudaFuncSetAttribute(k_main, cudaFuncAttributeMaxDynamicSharedMemorySize, (int)sm23);
    cudaFuncSetAttribute(k_attn, cudaFuncAttributeMaxDynamicSharedMemorySize, (int)sm4);
    cudaFuncSetAttribute(k_fc2,  cudaFuncAttributeMaxDynamicSharedMemorySize, (int)sm5);

    k_fc1 <<<NP/64, 256, sm1 >>>(feat, fc1w, fc1b);
    k_main<<<sms,   256, sm23>>>(xyz, knn, kxyz, d1w, d1b, d2w, d2b, g1w, g1b);
    k_attn<<<2*sms, 128, sm4 >>>(knn, g2w, g2b, out + RES_ELEMS);
    k_fc2 <<<NP/64, 256, sm5 >>>(fc2w, fc2b, out);
}

// round 10
// speedup vs baseline: 3.3820x; 2.0549x over previous
#include <cuda_runtime.h>
#include <cuda_bf16.h>
#include <cstdint>

#define BATCH 2
#define NPTS  16384
#define KNN   24
#define DM    128
#define NP    (BATCH*NPTS)
#define NR    (NP*KNN)
#define RES_ELEMS (NP*DM)
#define NT    (NR/128)          /* 6144 tiles of 128 rows */

typedef unsigned long long u64;
typedef unsigned int       u32;

/* ===================== generic-PTX MMA helpers ========================== */
__device__ __forceinline__ u32 smem_u32(const void* p){
    u32 a; asm("{ .reg .u64 t; cvta.to.shared.u64 t, %1; cvt.u32.u64 %0, t; }"
               : "=r"(a) : "l"(p));
    return a;
}
__device__ __forceinline__ void ldmA(u32* a, u32 addr){
    asm volatile("ldmatrix.sync.aligned.m8n8.x4.shared.b16 {%0,%1,%2,%3}, [%4];"
        : "=r"(a[0]), "=r"(a[1]), "=r"(a[2]), "=r"(a[3]) : "r"(addr));
}
__device__ __forceinline__ void ldmB(u32* b, u32 addr){
    asm volatile("ldmatrix.sync.aligned.m8n8.x2.shared.b16 {%0,%1}, [%2];"
        : "=r"(b[0]), "=r"(b[1]) : "r"(addr));
}
__device__ __forceinline__ void mma16816(float* c, const u32* a, const u32* b){
    asm volatile("mma.sync.aligned.m16n8k16.row.col.f32.bf16.bf16.f32 "
        "{%0,%1,%2,%3}, {%4,%5,%6,%7}, {%8,%9}, {%0,%1,%2,%3};"
        : "+f"(c[0]), "+f"(c[1]), "+f"(c[2]), "+f"(c[3])
        : "r"(a[0]), "r"(a[1]), "r"(a[2]), "r"(a[3]), "r"(b[0]), "r"(b[1]));
}

/* split fp32 pair into bf16x2 hi word + bf16x2 lo (residual) word */
__device__ __forceinline__ void split2(float a, float b, u32& hi, u32& lo){
    __nv_bfloat16 ah = __float2bfloat16(a), bh = __float2bfloat16(b);
    hi = (u32)__bfloat16_as_ushort(ah) | ((u32)__bfloat16_as_ushort(bh) << 16);
    lo = (u32)__bfloat16_as_ushort(__float2bfloat16(a - __bfloat162float(ah)))
       | ((u32)__bfloat16_as_ushort(__float2bfloat16(b - __bfloat162float(bh))) << 16);
}

/* weight [K x 128] row-major -> Bsm[n][k] bf16 hi/lo, row stride `stride` elems */
__device__ __forceinline__ void load_wt(const float* __restrict__ w, int K, int stride,
                                        char* bh, char* bl, int tid)
{
    for (int i = tid; i < K*128; i += 256) {
        int k = i >> 7, n = i & 127;
        float v = w[i];
        __nv_bfloat16 vh = __float2bfloat16(v);
        float vl = v - __bfloat162float(vh);
        int off = (n*stride + k)*2;
        *(__nv_bfloat16*)(bh + off) = vh;
        *(__nv_bfloat16*)(bl + off) = __float2bfloat16(vl);
    }
}

/* warp GEMM: C[32x64] = A[32xK] * B[Kx64]^T via 3-pass split-bf16 mma */
template<int KSTEPS, int AST, int BST>
__device__ __forceinline__ void wgemm(u32 aH, u32 aL, u32 bH, u32 bL,
                                      int m0, int n0, int lane, float C[2][8][4])
{
#pragma unroll
    for (int i = 0; i < 2; i++)
#pragma unroll
        for (int j = 0; j < 8; j++)
#pragma unroll
            for (int k = 0; k < 4; k++) C[i][j][k] = 0.0f;
    int arow = lane & 15, ach = lane >> 4;
    int brow = lane & 7,  bch = (lane >> 3) & 1;
#pragma unroll
    for (int ks = 0; ks < KSTEPS; ks++) {
        u32 Ah[2][4], Al[2][4];
#pragma unroll
        for (int mf = 0; mf < 2; mf++) {
            u32 off = (u32)(((m0 + mf*16 + arow)*AST + ks*16 + ach*8)*2);
            ldmA(Ah[mf], aH + off);
            ldmA(Al[mf], aL + off);
        }
        u32 Bh[8][2], Bl[8][2];
#pragma unroll
        for (int nf = 0; nf < 8; nf++) {
            u32 off = (u32)(((n0 + nf*8 + brow)*BST + ks*16 + bch*8)*2);
            ldmB(Bh[nf], bH + off);
            ldmB(Bl[nf], bL + off);
        }
#pragma unroll
        for (int nf = 0; nf < 8; nf++)
#pragma unroll
            for (int mf = 0; mf < 2; mf++) {
                mma16816(C[mf][nf], Ah[mf], Bh[nf]);
                mma16816(C[mf][nf], Ah[mf], Bl[nf]);
                mma16816(C[mf][nf], Al[mf], Bh[nf]);
            }
    }
}

/* ---- packed dual-fp32 FMA for scalar kernels ---- */
__device__ __forceinline__ u64 pack2(float x, float y){
    u64 r; asm("mov.b64 %0, {%1, %2};" : "=l"(r)
               : "r"(__float_as_uint(x)), "r"(__float_as_uint(y)));
    return r;
}
__device__ __forceinline__ void unpack2(u64 v, float& x, float& y){
    unsigned lo, hi; asm("mov.b64 {%0, %1}, %2;" : "=r"(lo), "=r"(hi) : "l"(v));
    x = __uint_as_float(lo); y = __uint_as_float(hi);
}
__device__ __forceinline__ void ffma2(u64& d, u64 a, u64 b){
    asm("fma.rn.f32x2 %0, %1, %2, %0;" : "+l"(d) : "l"(a), "l"(b));
}

/* ---- scratch ---- */
__device__ float d_x [NP*DM];
__device__ float d_pe[(size_t)NR*DM];
__device__ u32   d_hh[(size_t)NR*64];
__device__ u32   d_hl[(size_t)NR*64];
__device__ float d_lg[(size_t)NR*DM];
__device__ float d_r [NP*DM];

__constant__ float c_omega[10] = {
  1.0f, 0.398107170553497250f, 0.158489319246111348f, 0.063095734448019331f,
  0.025118864315095794f, 0.01f, 0.003981071705534973f, 0.001584893192461114f,
  0.000630957344480193f, 0.000251188643150958f };

/* =========================================================================
 * K1: x = features @ fc1_w + fc1_b  (scalar FFMA2)
 * ========================================================================= */
__global__ void k_fc1(const float* __restrict__ feat,
                      const float* __restrict__ w,
                      const float* __restrict__ bias)
{
    extern __shared__ float sm[];
    float* ws = sm;
    float* fs = sm + 64*128;
    int t = threadIdx.x, f = t & 127, rg = t >> 7, rb = rg * 32;
    for (int i = t; i < 64*128; i += 256) ws[i] = w[i];
    int r0 = blockIdx.x * 64;
    for (int idx = t; idx < 64*64; idx += 256) {
        int j = idx & 63, r = idx >> 6;
        fs[j*68 + r] = feat[(r0 + r)*64 + j];
    }
    __syncthreads();
    float b = bias[f];
    u64 bp = pack2(b, b);
    u64 acc[16];
#pragma unroll
    for (int i = 0; i < 16; i++) acc[i] = bp;
#pragma unroll 2
    for (int j = 0; j < 64; j++) {
        float wv = ws[j*128 + f];
        u64 wvp = pack2(wv, wv);
        const ulonglong2* rowp = (const ulonglong2*)(fs + j*68 + rb);
#pragma unroll
        for (int q = 0; q < 8; q++) {
            ulonglong2 v = rowp[q];
            ffma2(acc[2*q+0], v.x, wvp);
            ffma2(acc[2*q+1], v.y, wvp);
        }
    }
#pragma unroll
    for (int i = 0; i < 16; i++) {
        float lo, hi; unpack2(acc[i], lo, hi);
        d_x[(r0 + rb + 2*i    )*128 + f] = lo;
        d_x[(r0 + rb + 2*i + 1)*128 + f] = hi;
    }
}

/* ======================= smem layout offsets ============================ */
#define K2A_D1H 0
#define K2A_D1L 18432
#define K2A_D2H 36864
#define K2A_D2L 71680
#define K2A_EH  106496
#define K2A_EL  124928
#define K2A_TH  143360
#define K2A_TL  178176
#define K2A_B1  212992
#define K2A_B2  213504
#define K2A_SZ  214016

#define K2B_G1H 0
#define K2B_G1L 34816
#define K2B_G2H 69632
#define K2B_G2L 104448
#define K2B_HH  139264
#define K2B_HL  174080
#define K2B_B3  208896
#define K2B_B4  209408
#define K2B_SZ  209920

/* =========================================================================
 * K2a: per 128-row tile: embed -> G1(relu) -> G2 -> pe(fp32) + h(split bf16)
 * ========================================================================= */
__global__ void __launch_bounds__(256, 1)
k2a(const float* __restrict__ xyz, const int* __restrict__ knn_idx,
    const float* __restrict__ kxyz,
    const float* __restrict__ d1w, const float* __restrict__ d1b,
    const float* __restrict__ d2w, const float* __restrict__ d2b)
{
    extern __shared__ __align__(128) char smem[];
    int tid = threadIdx.x, lane = tid & 31, w = tid >> 5;
    int m0 = (w >> 1) * 32, n0 = (w & 1) * 64;
    float* b1s = (float*)(smem + K2A_B1);
    float* b2s = (float*)(smem + K2A_B2);

    load_wt(d1w, 60, 72, smem + K2A_D1H, smem + K2A_D1L, tid);
    /* zero pad k = 60..63 of d1 (read by ldmatrix) */
    for (int i = tid; i < 128*4; i += 256) {
        int n = i >> 2, k = 60 + (i & 3);
        *(__nv_bfloat16*)(smem + K2A_D1H + (n*72 + k)*2) = __float2bfloat16(0.0f);
        *(__nv_bfloat16*)(smem + K2A_D1L + (n*72 + k)*2) = __float2bfloat16(0.0f);
    }
    load_wt(d2w, 128, 136, smem + K2A_D2H, smem + K2A_D2L, tid);
    if (tid < 128) { b1s[tid] = d1b[tid]; b2s[tid] = d2b[tid]; }
    __syncthreads();

    u32 EH = smem_u32(smem + K2A_EH), EL = smem_u32(smem + K2A_EL);
    u32 TH = smem_u32(smem + K2A_TH), TL = smem_u32(smem + K2A_TL);
    u32 D1H = smem_u32(smem + K2A_D1H), D1L = smem_u32(smem + K2A_D1L);
    u32 D2H = smem_u32(smem + K2A_D2H), D2L = smem_u32(smem + K2A_D2L);

    for (int tile = blockIdx.x; tile < NT; tile += gridDim.x) {
        /* ---- embedding: 128 threads, one row each ---- */
        if (tid < 128) {
            int r = tid, grow = tile*128 + r;
            int p = grow / KNN;
            float e[64];
            e[60] = e[61] = e[62] = e[63] = 0.0f;
#pragma unroll
            for (int c = 0; c < 3; c++) {
                float g = xyz[p*3 + c] - kxyz[(size_t)grow*3 + c];
#pragma unroll
                for (int j = 0; j < 10; j++) {
                    float a = g * c_omega[j];
                    e[c*20 + j]      = __sinf(a);
                    e[c*20 + 10 + j] = __cosf(a);
                }
            }
#pragma unroll
            for (int q = 0; q < 32; q++) {
                u32 hi, lo; split2(e[2*q], e[2*q+1], hi, lo);
                *(u32*)(smem + K2A_EH + r*144 + 4*q) = hi;
                *(u32*)(smem + K2A_EL + r*144 + 4*q) = lo;
            }
        }
        __syncthreads();

        float C[2][8][4];
        /* ---- G1: t1 = relu(e @ d1 + b1) ---- */
        wgemm<4, 72, 72>(EH, EL, D1H, D1L, m0, n0, lane, C);
#pragma unroll
        for (int mf = 0; mf < 2; mf++) {
            int r1 = m0 + mf*16 + (lane >> 2);
#pragma unroll
            for (int nf = 0; nf < 8; nf++) {
                int c = n0 + nf*8 + (lane & 3)*2;
                float ba = b1s[c], bb = b1s[c+1];
                u32 hi, lo;
                split2(fmaxf(C[mf][nf][0] + ba, 0.0f), fmaxf(C[mf][nf][1] + bb, 0.0f), hi, lo);
                *(u32*)(smem + K2A_TH + r1*272 + 2*c) = hi;
                *(u32*)(smem + K2A_TL + r1*272 + 2*c) = lo;
                split2(fmaxf(C[mf][nf][2] + ba, 0.0f), fmaxf(C[mf][nf][3] + bb, 0.0f), hi, lo);
                *(u32*)(smem + K2A_TH + (r1+8)*272 + 2*c) = hi;
                *(u32*)(smem + K2A_TL + (r1+8)*272 + 2*c) = lo;
            }
        }
        __syncthreads();

        /* ---- G2: pe = t1 @ d2 + b2 ---- */
        wgemm<8, 136, 136>(TH, TL, D2H, D2L, m0, n0, lane, C);
#pragma unroll
        for (int mf = 0; mf < 2; mf++) {
            int rA = m0 + mf*16 + (lane >> 2), rB = rA + 8;
            int gA = tile*128 + rA, gB = tile*128 + rB;
            int pA = gA / KNN, pB = gB / KNN;
            int iA = ((pA >> 14) << 14) + knn_idx[gA];
            int iB = ((pB >> 14) << 14) + knn_idx[gB];
            const float* xpA = d_x + (size_t)pA*128;
            const float* xgA = d_x + (size_t)iA*128;
            const float* xpB = d_x + (size_t)pB*128;
            const float* xgB = d_x + (size_t)iB*128;
            float* peA = d_pe + (size_t)gA*128;
            float* peB = d_pe + (size_t)gB*128;
            u32* hhA = d_hh + (size_t)gA*64; u32* hlA = d_hl + (size_t)gA*64;
            u32* hhB = d_hh + (size_t)gB*64; u32* hlB = d_hl + (size_t)gB*64;
#pragma unroll
            for (int nf = 0; nf < 8; nf++) {
                int c = n0 + nf*8 + (lane & 3)*2;
                float ba = b2s[c], bb = b2s[c+1];
                float p0 = C[mf][nf][0] + ba, p1 = C[mf][nf][1] + bb;
                *(float2*)(peA + c) = make_float2(p0, p1);
                u32 hh, hl;
                split2(xpA[c] - xgA[c] + p0, xpA[c+1] - xgA[c+1] + p1, hh, hl);
                hhA[c >> 1] = hh; hlA[c >> 1] = hl;
                float p2 = C[mf][nf][2] + ba, p3 = C[mf][nf][3] + bb;
                *(float2*)(peB + c) = make_float2(p2, p3);
                split2(xpB[c] - xgB[c] + p2, xpB[c+1] - xgB[c+1] + p3, hh, hl);
                hhB[c >> 1] = hh; hlB[c >> 1] = hl;
            }
        }
        __syncthreads();
    }
}

/* =========================================================================
 * K2b: per 128-row tile: h -> G3(relu, in-place) -> G4 -> logits (fp32)
 * ========================================================================= */
__global__ void __launch_bounds__(256, 1)
k2b(const float* __restrict__ g1w, const float* __restrict__ g1b,
    const float* __restrict__ g2w, const float* __restrict__ g2b)
{
    extern __shared__ __align__(128) char smem[];
    int tid = threadIdx.x, lane = tid & 31, w = tid >> 5;
    int m0 = (w >> 1) * 32, n0 = (w & 1) * 64;
    float* b3s = (float*)(smem + K2B_B3);
    float* b4s = (float*)(smem + K2B_B4);

    load_wt(g1w, 128, 136, smem + K2B_G1H, smem + K2B_G1L, tid);
    load_wt(g2w, 128, 136, smem + K2B_G2H, smem + K2B_G2L, tid);
    if (tid < 128) { b3s[tid] = g1b[tid]; b4s[tid] = g2b[tid]; }
    __syncthreads();

    u32 HH = smem_u32(smem + K2B_HH), HL = smem_u32(smem + K2B_HL);
    u32 G1H = smem_u32(smem + K2B_G1H), G1L = smem_u32(smem + K2B_G1L);
    u32 G2H = smem_u32(smem + K2B_G2H), G2L = smem_u32(smem + K2B_G2L);

    for (int tile = blockIdx.x; tile < NT; tile += gridDim.x) {
        /* ---- load h (bf16x2 hi/lo) into smem ---- */
        for (int i = tid; i < 128*64; i += 256) {
            int r = i >> 6, q = i & 63;
            *(u32*)(smem + K2B_HH + r*272 + 4*q) = d_hh[(size_t)(tile*128 + r)*64 + q];
            *(u32*)(smem + K2B_HL + r*272 + 4*q) = d_hl[(size_t)(tile*128 + r)*64 + q];
        }
        __syncthreads();

        float C[2][8][4];
        /* ---- G3: t = relu(h @ g1 + b3) ---- */
        wgemm<8, 136, 136>(HH, HL, G1H, G1L, m0, n0, lane, C);
        __syncthreads();   /* all warps done reading Hsm before overwrite */
#pragma unroll
        for (int mf = 0; mf < 2; mf++) {
            int r1 = m0 + mf*16 + (lane >> 2);
#pragma unroll
            for (int nf = 0; nf < 8; nf++) {
                int c = n0 + nf*8 + (lane & 3)*2;
                float ba = b3s[c], bb = b3s[c+1];
                u32 hi, lo;
                split2(fmaxf(C[mf][nf][0] + ba, 0.0f), fmaxf(C[mf][nf][1] + bb, 0.0f), hi, lo);
                *(u32*)(smem + K2B_HH + r1*272 + 2*c) = hi;
                *(u32*)(smem + K2B_HL + r1*272 + 2*c) = lo;
                split2(fmaxf(C[mf][nf][2] + ba, 0.0f), fmaxf(C[mf][nf][3] + bb, 0.0f), hi, lo);
                *(u32*)(smem + K2B_HH + (r1+8)*272 + 2*c) = hi;
                *(u32*)(smem + K2B_HL + (r1+8)*272 + 2*c) = lo;
            }
        }
        __syncthreads();

        /* ---- G4: logits = t @ g2 + b4 ---- */
        wgemm<8, 136, 136>(HH, HL, G2H, G2L, m0, n0, lane, C);
#pragma unroll
        for (int mf = 0; mf < 2; mf++) {
            int rA = m0 + mf*16 + (lane >> 2), rB = rA + 8;
            float* lgA = d_lg + (size_t)(tile*128 + rA)*128;
            float* lgB = d_lg + (size_t)(tile*128 + rB)*128;
#pragma unroll
            for (int nf = 0; nf < 8; nf++) {
                int c = n0 + nf*8 + (lane & 3)*2;
                float ba = b4s[c], bb = b4s[c+1];
                *(float2*)(lgA + c) = make_float2(C[mf][nf][0] + ba, C[mf][nf][1] + bb);
                *(float2*)(lgB + c) = make_float2(C[mf][nf][2] + ba, C[mf][nf][3] + bb);
            }
        }
        __syncthreads();   /* all warps done reading Hsm before next tile load */
    }
}

/* =========================================================================
 * K3: softmax over k + aggregate. block = point p, thread = channel f.
 * ========================================================================= */
__global__ void k_soft(const int* __restrict__ knn_idx,
                       float* __restrict__ out_attn)
{
    int p = blockIdx.x, f = threadIdx.x;
    int base = p * KNN, bb = p >> 14;
    const float scale = 0.0883883476483184406f;   /* 1/sqrt(128) */
    float acc[KNN];
    float m = -1e30f;
#pragma unroll
    for (int k = 0; k < KNN; k++) {
        acc[k] = d_lg[(size_t)(base + k)*128 + f] * scale;
        m = fmaxf(m, acc[k]);
    }
    float s = 0.0f;
#pragma unroll
    for (int k = 0; k < KNN; k++) { acc[k] = __expf(acc[k] - m); s += acc[k]; }
    float inv = 1.0f / s;
    float rv = 0.0f;
#pragma unroll
    for (int k = 0; k < KNN; k++) {
        float a = acc[k] * inv;
        int grow = base + k;
        out_attn[(size_t)grow*128 + f] = a;
        int gi = (bb << 14) + knn_idx[grow];
        rv = fmaf(a, d_x[(size_t)gi*128 + f] + d_pe[(size_t)grow*128 + f], rv);
    }
    d_r[p*128 + f] = rv;
}

/* =========================================================================
 * K4: res = r @ fc2 + fc2_b + x  (scalar FFMA2)
 * ========================================================================= */
__global__ void k_fc2(const float* __restrict__ w, const float* __restrict__ bias,
                      float* __restrict__ out_res)
{
    extern __shared__ float sm[];
    float* ws = sm;
    float* rs = sm + 128*128;
    int t = threadIdx.x, f = t & 127, rg = t >> 7, rb = rg * 32;
    for (int i = t; i < 128*128; i += 256) ws[i] = w[i];
    int r0 = blockIdx.x * 64;
    for (int idx = t; idx < 64*128; idx += 256) {
        int j = idx & 127, r = idx >> 7;
        rs[j*68 + r] = d_r[(r0 + r)*128 + j];
    }
    __syncthreads();
    float b = bias[f];
    u64 bp = pack2(b, b);
    u64 acc[16];
#pragma unroll
    for (int i = 0; i < 16; i++) acc[i] = bp;
#pragma unroll 2
    for (int j = 0; j < 128; j++) {
        float wv = ws[j*128 + f];
        u64 wvp = pack2(wv, wv);
        const ulonglong2* rowp = (const ulonglong2*)(rs + j*68 + rb);
#pragma unroll
        for (int q = 0; q < 8; q++) {
            ulonglong2 v = rowp[q];
            ffma2(acc[2*q+0], v.x, wvp);
            ffma2(acc[2*q+1], v.y, wvp);
        }
    }
#pragma unroll
    for (int i = 0; i < 16; i++) {
        float lo, hi; unpack2(acc[i], lo, hi);
        int row = r0 + rb + 2*i;
        out_res[ row     *128 + f] = lo + d_x[ row     *128 + f];
        out_res[(row + 1)*128 + f] = hi + d_x[(row + 1)*128 + f];
    }
}

/* ========================================================================= */
extern "C" void kernel_launch(void* const* d_in, const int* in_sizes, int n_in,
                              void* d_out, int out_size)
{
    const float* feat = (const float*)d_in[0];
    const float* xyz  = (const float*)d_in[1];
    const int*   knn  = (const int*  )d_in[2];
    const float* kxyz = (const float*)d_in[3];
    const float* fc1w = (const float*)d_in[4];
    const float* fc1b = (const float*)d_in[5];
    const float* fc2w = (const float*)d_in[6];
    const float* fc2b = (const float*)d_in[7];
    const float* d1w  = (const float*)d_in[8];
    const float* d1b  = (const float*)d_in[9];
    const float* d2w  = (const float*)d_in[10];
    const float* d2b  = (const float*)d_in[11];
    const float* g1w  = (const float*)d_in[12];
    const float* g1b  = (const float*)d_in[13];
    const float* g2w  = (const float*)d_in[14];
    const float* g2b  = (const float*)d_in[15];
    float* out = (float*)d_out;

    int sms = 148;
    cudaDeviceGetAttribute(&sms, cudaDevAttrMultiProcessorCount, 0);

    size_t sm1 = (size_t)(64*128 + 64*68) * 4;
    size_t sm5 = (size_t)(128*128 + 128*68) * 4;

    cudaFuncSetAttribute(k_fc1, cudaFuncAttributeMaxDynamicSharedMemorySize, (int)sm1);
    cudaFuncSetAttribute(k2a,   cudaFuncAttributeMaxDynamicSharedMemorySize, K2A_SZ);
    cudaFuncSetAttribute(k2b,   cudaFuncAttributeMaxDynamicSharedMemorySize, K2B_SZ);
    cudaFuncSetAttribute(k_fc2, cudaFuncAttributeMaxDynamicSharedMemorySize, (int)sm5);

    k_fc1 <<<NP/64, 256, sm1   >>>(feat, fc1w, fc1b);
    k2a   <<<sms,   256, K2A_SZ>>>(xyz, knn, kxyz, d1w, d1b, d2w, d2b);
    k2b   <<<sms,   256, K2B_SZ>>>(g1w, g1b, g2w, g2b);
    k_soft<<<NP,    128        >>>(knn, out + RES_ELEMS);
    k_fc2 <<<NP/64, 256, sm5   >>>(fc2w, fc2b, out);
}

// round 11
// speedup vs baseline: 4.2876x; 1.2678x over previous
#include <cuda_runtime.h>
#include <cuda_bf16.h>
#include <cstdint>

#define BATCH 2
#define NPTS  16384
#define KNN   24
#define DM    128
#define NP    (BATCH*NPTS)
#define NR    (NP*KNN)
#define RES_ELEMS (NP*DM)
#define NT    (NR/128)          /* 6144 tiles of 128 rows */

typedef unsigned long long u64;
typedef unsigned int       u32;

/* ===================== generic-PTX MMA helpers ========================== */
__device__ __forceinline__ u32 smem_u32(const void* p){
    u32 a; asm("{ .reg .u64 t; cvta.to.shared.u64 t, %1; cvt.u32.u64 %0, t; }"
               : "=r"(a) : "l"(p));
    return a;
}
__device__ __forceinline__ void ldmA(u32* a, u32 addr){
    asm volatile("ldmatrix.sync.aligned.m8n8.x4.shared.b16 {%0,%1,%2,%3}, [%4];"
        : "=r"(a[0]), "=r"(a[1]), "=r"(a[2]), "=r"(a[3]) : "r"(addr));
}
__device__ __forceinline__ void ldmB4(u32* b, u32 addr){
    asm volatile("ldmatrix.sync.aligned.m8n8.x4.shared.b16 {%0,%1,%2,%3}, [%4];"
        : "=r"(b[0]), "=r"(b[1]), "=r"(b[2]), "=r"(b[3]) : "r"(addr));
}
__device__ __forceinline__ void mma16816(float* c, const u32* a, const u32* b){
    asm volatile("mma.sync.aligned.m16n8k16.row.col.f32.bf16.bf16.f32 "
        "{%0,%1,%2,%3}, {%4,%5,%6,%7}, {%8,%9}, {%0,%1,%2,%3};"
        : "+f"(c[0]), "+f"(c[1]), "+f"(c[2]), "+f"(c[3])
        : "r"(a[0]), "r"(a[1]), "r"(a[2]), "r"(a[3]), "r"(b[0]), "r"(b[1]));
}

/* pack two fp32 into bf16x2 word (round-to-nearest) */
__device__ __forceinline__ u32 pk(float a, float b){
    return (u32)__bfloat16_as_ushort(__float2bfloat16(a))
        | ((u32)__bfloat16_as_ushort(__float2bfloat16(b)) << 16);
}
/* split fp32 pair into bf16x2 hi word + bf16x2 lo (residual) word */
__device__ __forceinline__ void split2(float a, float b, u32& hi, u32& lo){
    __nv_bfloat16 ah = __float2bfloat16(a), bh = __float2bfloat16(b);
    hi = (u32)__bfloat16_as_ushort(ah) | ((u32)__bfloat16_as_ushort(bh) << 16);
    lo = (u32)__bfloat16_as_ushort(__float2bfloat16(a - __bfloat162float(ah)))
       | ((u32)__bfloat16_as_ushort(__float2bfloat16(b - __bfloat162float(bh))) << 16);
}

/* weight [K x 128] row-major -> Bsm[n][k] bf16 hi/lo, row stride `stride` elems */
__device__ __forceinline__ void load_wt(const float* __restrict__ w, int K, int stride,
                                        char* bh, char* bl, int tid)
{
    for (int i = tid; i < K*128; i += 256) {
        int k = i >> 7, n = i & 127;
        float v = w[i];
        __nv_bfloat16 vh = __float2bfloat16(v);
        float vl = v - __bfloat162float(vh);
        int off = (n*stride + k)*2;
        *(__nv_bfloat16*)(bh + off) = vh;
        *(__nv_bfloat16*)(bl + off) = __float2bfloat16(vl);
    }
}

/* 3-pass warp GEMM: C = A*B^T with A split (hi/lo) and B split (hi/lo) */
template<int KSTEPS, int AST, int BST>
__device__ __forceinline__ void wgemm3(u32 aH, u32 aL, u32 bH, u32 bL,
                                       int m0, int n0, int lane, float C[2][8][4])
{
#pragma unroll
    for (int i = 0; i < 2; i++)
#pragma unroll
        for (int j = 0; j < 8; j++)
#pragma unroll
            for (int k = 0; k < 4; k++) C[i][j][k] = 0.0f;
    int arow = lane & 15, ach = lane >> 4;
    int brow4 = ((lane >> 4) & 1)*8 + (lane & 7);
    int bk4   = ((lane >> 3) & 1)*8;
#pragma unroll
    for (int ks = 0; ks < KSTEPS; ks++) {
        u32 Ah[2][4], Al[2][4];
#pragma unroll
        for (int mf = 0; mf < 2; mf++) {
            u32 off = (u32)(((m0 + mf*16 + arow)*AST + ks*16 + ach*8)*2);
            ldmA(Ah[mf], aH + off);
            ldmA(Al[mf], aL + off);
        }
        u32 Bh[8][2], Bl[8][2];
#pragma unroll
        for (int nfp = 0; nfp < 4; nfp++) {
            u32 off = (u32)(((n0 + nfp*16 + brow4)*BST + ks*16 + bk4)*2);
            ldmB4(&Bh[nfp*2][0], bH + off);
            ldmB4(&Bl[nfp*2][0], bL + off);
        }
#pragma unroll
        for (int nf = 0; nf < 8; nf++)
#pragma unroll
            for (int mf = 0; mf < 2; mf++) {
                mma16816(C[mf][nf], Ah[mf], Bh[nf]);
                mma16816(C[mf][nf], Ah[mf], Bl[nf]);
                mma16816(C[mf][nf], Al[mf], Bh[nf]);
            }
    }
}

/* 2-pass warp GEMM: C = A*B^T with A single bf16, B split (hi/lo) */
template<int KSTEPS, int AST, int BST>
__device__ __forceinline__ void wgemm2(u32 aH, u32 bH, u32 bL,
                                       int m0, int n0, int lane, float C[2][8][4])
{
#pragma unroll
    for (int i = 0; i < 2; i++)
#pragma unroll
        for (int j = 0; j < 8; j++)
#pragma unroll
            for (int k = 0; k < 4; k++) C[i][j][k] = 0.0f;
    int arow = lane & 15, ach = lane >> 4;
    int brow4 = ((lane >> 4) & 1)*8 + (lane & 7);
    int bk4   = ((lane >> 3) & 1)*8;
#pragma unroll
    for (int ks = 0; ks < KSTEPS; ks++) {
        u32 Ah[2][4];
#pragma unroll
        for (int mf = 0; mf < 2; mf++) {
            u32 off = (u32)(((m0 + mf*16 + arow)*AST + ks*16 + ach*8)*2);
            ldmA(Ah[mf], aH + off);
        }
        u32 Bh[8][2], Bl[8][2];
#pragma unroll
        for (int nfp = 0; nfp < 4; nfp++) {
            u32 off = (u32)(((n0 + nfp*16 + brow4)*BST + ks*16 + bk4)*2);
            ldmB4(&Bh[nfp*2][0], bH + off);
            ldmB4(&Bl[nfp*2][0], bL + off);
        }
#pragma unroll
        for (int nf = 0; nf < 8; nf++)
#pragma unroll
            for (int mf = 0; mf < 2; mf++) {
                mma16816(C[mf][nf], Ah[mf], Bh[nf]);
                mma16816(C[mf][nf], Ah[mf], Bl[nf]);
            }
    }
}

/* ---- packed dual-fp32 FMA for scalar kernels ---- */
__device__ __forceinline__ u64 pack2(float x, float y){
    u64 r; asm("mov.b64 %0, {%1, %2};" : "=l"(r)
               : "r"(__float_as_uint(x)), "r"(__float_as_uint(y)));
    return r;
}
__device__ __forceinline__ void unpack2(u64 v, float& x, float& y){
    unsigned lo, hi; asm("mov.b64 {%0, %1}, %2;" : "=r"(lo), "=r"(hi) : "l"(v));
    x = __uint_as_float(lo); y = __uint_as_float(hi);
}
__device__ __forceinline__ void ffma2(u64& d, u64 a, u64 b){
    asm("fma.rn.f32x2 %0, %1, %2, %0;" : "+l"(d) : "l"(a), "l"(b));
}

/* ---- scratch ---- */
__device__ float d_x  [NP*DM];
__device__ float d_pe [(size_t)NR*DM];
__device__ u32   d_hh [(size_t)NR*64];     /* h as bf16x2 (hi only) */
__device__ u32   d_lgp[(size_t)NR*64];     /* logits as bf16x2      */
__device__ float d_r  [NP*DM];

__constant__ float c_omega[10] = {
  1.0f, 0.398107170553497250f, 0.158489319246111348f, 0.063095734448019331f,
  0.025118864315095794f, 0.01f, 0.003981071705534973f, 0.001584893192461114f,
  0.000630957344480193f, 0.000251188643150958f };

/* =========================================================================
 * K1: x = features @ fc1_w + fc1_b  (scalar FFMA2)
 * ========================================================================= */
__global__ void k_fc1(const float* __restrict__ feat,
                      const float* __restrict__ w,
                      const float* __restrict__ bias)
{
    extern __shared__ float sm[];
    float* ws = sm;
    float* fs = sm + 64*128;
    int t = threadIdx.x, f = t & 127, rg = t >> 7, rb = rg * 32;
    for (int i = t; i < 64*128; i += 256) ws[i] = w[i];
    int r0 = blockIdx.x * 64;
    for (int idx = t; idx < 64*64; idx += 256) {
        int j = idx & 63, r = idx >> 6;
        fs[j*68 + r] = feat[(r0 + r)*64 + j];
    }
    __syncthreads();
    float b = bias[f];
    u64 bp = pack2(b, b);
    u64 acc[16];
#pragma unroll
    for (int i = 0; i < 16; i++) acc[i] = bp;
#pragma unroll 2
    for (int j = 0; j < 64; j++) {
        float wv = ws[j*128 + f];
        u64 wvp = pack2(wv, wv);
        const ulonglong2* rowp = (const ulonglong2*)(fs + j*68 + rb);
#pragma unroll
        for (int q = 0; q < 8; q++) {
            ulonglong2 v = rowp[q];
            ffma2(acc[2*q+0], v.x, wvp);
            ffma2(acc[2*q+1], v.y, wvp);
        }
    }
#pragma unroll
    for (int i = 0; i < 16; i++) {
        float lo, hi; unpack2(acc[i], lo, hi);
        d_x[(r0 + rb + 2*i    )*128 + f] = lo;
        d_x[(r0 + rb + 2*i + 1)*128 + f] = hi;
    }
}

/* ======================= smem layout offsets ============================ */
#define K2A_D1H 0
#define K2A_D1L 18432
#define K2A_D2H 36864
#define K2A_D2L 71680
#define K2A_EH  106496
#define K2A_EL  124928
#define K2A_TH  143360
#define K2A_TL  178176
#define K2A_B1  212992
#define K2A_B2  213504
#define K2A_SZ  214016

#define K2B_G1H 0
#define K2B_G1L 34816
#define K2B_G2H 69632
#define K2B_G2L 104448
#define K2B_H0  139264
#define K2B_H1  174080
#define K2B_B3  208896
#define K2B_B4  209408
#define K2B_SZ  209920

/* =========================================================================
 * K2a: per 128-row tile: embed -> G1(relu) -> G2 -> pe(fp32) + h(bf16 hi)
 * ========================================================================= */
__global__ void __launch_bounds__(256, 1)
k2a(const float* __restrict__ xyz, const int* __restrict__ knn_idx,
    const float* __restrict__ kxyz,
    const float* __restrict__ d1w, const float* __restrict__ d1b,
    const float* __restrict__ d2w, const float* __restrict__ d2b)
{
    extern __shared__ __align__(128) char smem[];
    int tid = threadIdx.x, lane = tid & 31, w = tid >> 5;
    int m0 = (w >> 1) * 32, n0 = (w & 1) * 64;
    float* b1s = (float*)(smem + K2A_B1);
    float* b2s = (float*)(smem + K2A_B2);

    load_wt(d1w, 60, 72, smem + K2A_D1H, smem + K2A_D1L, tid);
    for (int i = tid; i < 128*4; i += 256) {
        int n = i >> 2, k = 60 + (i & 3);
        *(__nv_bfloat16*)(smem + K2A_D1H + (n*72 + k)*2) = __float2bfloat16(0.0f);
        *(__nv_bfloat16*)(smem + K2A_D1L + (n*72 + k)*2) = __float2bfloat16(0.0f);
    }
    load_wt(d2w, 128, 136, smem + K2A_D2H, smem + K2A_D2L, tid);
    if (tid < 128) { b1s[tid] = d1b[tid]; b2s[tid] = d2b[tid]; }
    __syncthreads();

    u32 EH = smem_u32(smem + K2A_EH), EL = smem_u32(smem + K2A_EL);
    u32 TH = smem_u32(smem + K2A_TH), TL = smem_u32(smem + K2A_TL);
    u32 D1H = smem_u32(smem + K2A_D1H), D1L = smem_u32(smem + K2A_D1L);
    u32 D2H = smem_u32(smem + K2A_D2H), D2L = smem_u32(smem + K2A_D2L);

    for (int tile = blockIdx.x; tile < NT; tile += gridDim.x) {
        /* ---- embedding: 128 threads, one row each ---- */
        if (tid < 128) {
            int r = tid, grow = tile*128 + r;
            int p = grow / KNN;
            float e[64];
            e[60] = e[61] = e[62] = e[63] = 0.0f;
#pragma unroll
            for (int c = 0; c < 3; c++) {
                float g = xyz[p*3 + c] - kxyz[(size_t)grow*3 + c];
#pragma unroll
                for (int j = 0; j < 10; j++) {
                    float a = g * c_omega[j];
                    e[c*20 + j]      = __sinf(a);
                    e[c*20 + 10 + j] = __cosf(a);
                }
            }
#pragma unroll
            for (int q = 0; q < 32; q++) {
                u32 hi, lo; split2(e[2*q], e[2*q+1], hi, lo);
                *(u32*)(smem + K2A_EH + r*144 + 4*q) = hi;
                *(u32*)(smem + K2A_EL + r*144 + 4*q) = lo;
            }
        }
        __syncthreads();

        float C[2][8][4];
        /* ---- G1: t1 = relu(e @ d1 + b1), 3-pass ---- */
        wgemm3<4, 72, 72>(EH, EL, D1H, D1L, m0, n0, lane, C);
#pragma unroll
        for (int mf = 0; mf < 2; mf++) {
            int r1 = m0 + mf*16 + (lane >> 2);
#pragma unroll
            for (int nf = 0; nf < 8; nf++) {
                int c = n0 + nf*8 + (lane & 3)*2;
                float ba = b1s[c], bb = b1s[c+1];
                u32 hi, lo;
                split2(fmaxf(C[mf][nf][0] + ba, 0.0f), fmaxf(C[mf][nf][1] + bb, 0.0f), hi, lo);
                *(u32*)(smem + K2A_TH + r1*272 + 2*c) = hi;
                *(u32*)(smem + K2A_TL + r1*272 + 2*c) = lo;
                split2(fmaxf(C[mf][nf][2] + ba, 0.0f), fmaxf(C[mf][nf][3] + bb, 0.0f), hi, lo);
                *(u32*)(smem + K2A_TH + (r1+8)*272 + 2*c) = hi;
                *(u32*)(smem + K2A_TL + (r1+8)*272 + 2*c) = lo;
            }
        }
        __syncthreads();

        /* ---- G2: pe = t1 @ d2 + b2, 3-pass ---- */
        wgemm3<8, 136, 136>(TH, TL, D2H, D2L, m0, n0, lane, C);
#pragma unroll
        for (int mf = 0; mf < 2; mf++) {
            int rA = m0 + mf*16 + (lane >> 2), rB = rA + 8;
            int gA = tile*128 + rA, gB = tile*128 + rB;
            int pA = gA / KNN, pB = gB / KNN;
            int iA = ((pA >> 14) << 14) + knn_idx[gA];
            int iB = ((pB >> 14) << 14) + knn_idx[gB];
            const float* xpA = d_x + (size_t)pA*128;
            const float* xgA = d_x + (size_t)iA*128;
            const float* xpB = d_x + (size_t)pB*128;
            const float* xgB = d_x + (size_t)iB*128;
            float* peA = d_pe + (size_t)gA*128;
            float* peB = d_pe + (size_t)gB*128;
            u32* hhA = d_hh + (size_t)gA*64;
            u32* hhB = d_hh + (size_t)gB*64;
#pragma unroll
            for (int nf = 0; nf < 8; nf++) {
                int c = n0 + nf*8 + (lane & 3)*2;
                float ba = b2s[c], bb = b2s[c+1];
                float p0 = C[mf][nf][0] + ba, p1 = C[mf][nf][1] + bb;
                *(float2*)(peA + c) = make_float2(p0, p1);
                hhA[c >> 1] = pk(xpA[c] - xgA[c] + p0, xpA[c+1] - xgA[c+1] + p1);
                float p2 = C[mf][nf][2] + ba, p3 = C[mf][nf][3] + bb;
                *(float2*)(peB + c) = make_float2(p2, p3);
                hhB[c >> 1] = pk(xpB[c] - xgB[c] + p2, xpB[c+1] - xgB[c+1] + p3);
            }
        }
        __syncthreads();
    }
}

/* ---- cp.async prefetch of one h tile (32 KB) into smem buffer ---- */
__device__ __forceinline__ void prefetch_h(char* dst, int tile, int tid)
{
    const u32* src = d_hh + (size_t)tile * 8192;
#pragma unroll
    for (int j = 0; j < 8; j++) {
        int wi = tid + j*256;                       /* 0..2047 16B chunks */
        u32 daddr = smem_u32(dst + (wi >> 4)*272 + (wi & 15)*16);
        asm volatile("cp.async.ca.shared.global [%0], [%1], 16;"
                     :: "r"(daddr), "l"(src + wi*4) : "memory");
    }
    asm volatile("cp.async.commit_group;" ::: "memory");
}

/* =========================================================================
 * K2b: per 128-row tile: h -> G3(relu, 2-pass) -> G4(2-pass) -> logits bf16
 * double-buffered cp.async h prefetch.
 * ========================================================================= */
__global__ void __launch_bounds__(256, 1)
k2b(const float* __restrict__ g1w, const float* __restrict__ g1b,
    const float* __restrict__ g2w, const float* __restrict__ g2b)
{
    extern __shared__ __align__(128) char smem[];
    int tid = threadIdx.x, lane = tid & 31, w = tid >> 5;
    int m0 = (w >> 1) * 32, n0 = (w & 1) * 64;
    float* b3s = (float*)(smem + K2B_B3);
    float* b4s = (float*)(smem + K2B_B4);

    load_wt(g1w, 128, 136, smem + K2B_G1H, smem + K2B_G1L, tid);
    load_wt(g2w, 128, 136, smem + K2B_G2H, smem + K2B_G2L, tid);
    if (tid < 128) { b3s[tid] = g1b[tid]; b4s[tid] = g2b[tid]; }

    u32 G1H = smem_u32(smem + K2B_G1H), G1L = smem_u32(smem + K2B_G1L);
    u32 G2H = smem_u32(smem + K2B_G2H), G2L = smem_u32(smem + K2B_G2L);
    char* hbuf[2] = { smem + K2B_H0, smem + K2B_H1 };
    u32 hadr[2] = { smem_u32(smem + K2B_H0), smem_u32(smem + K2B_H1) };

    int tile = blockIdx.x;
    if (tile < NT) prefetch_h(hbuf[0], tile, tid);
    __syncthreads();
    int cur = 0;

    for (; tile < NT; tile += gridDim.x, cur ^= 1) {
        asm volatile("cp.async.wait_group 0;" ::: "memory");
        __syncthreads();
        int nxt = tile + gridDim.x;
        if (nxt < NT) prefetch_h(hbuf[cur ^ 1], nxt, tid);

        float C[2][8][4];
        /* ---- G3: t = relu(h @ g1 + b3), 2-pass, A = h (single bf16) ---- */
        wgemm2<8, 136, 136>(hadr[cur], G1H, G1L, m0, n0, lane, C);
        __syncthreads();   /* all warps done reading h before overwrite */
#pragma unroll
        for (int mf = 0; mf < 2; mf++) {
            int r1 = m0 + mf*16 + (lane >> 2);
#pragma unroll
            for (int nf = 0; nf < 8; nf++) {
                int c = n0 + nf*8 + (lane & 3)*2;
                float ba = b3s[c], bb = b3s[c+1];
                *(u32*)(hbuf[cur] + r1*272 + 2*c) =
                    pk(fmaxf(C[mf][nf][0] + ba, 0.0f), fmaxf(C[mf][nf][1] + bb, 0.0f));
                *(u32*)(hbuf[cur] + (r1+8)*272 + 2*c) =
                    pk(fmaxf(C[mf][nf][2] + ba, 0.0f), fmaxf(C[mf][nf][3] + bb, 0.0f));
            }
        }
        __syncthreads();

        /* ---- G4: logits = t @ g2 + b4, 2-pass -> bf16x2 gmem ---- */
        wgemm2<8, 136, 136>(hadr[cur], G2H, G2L, m0, n0, lane, C);
#pragma unroll
        for (int mf = 0; mf < 2; mf++) {
            int rA = m0 + mf*16 + (lane >> 2), rB = rA + 8;
            u32* lgA = d_lgp + (size_t)(tile*128 + rA)*64;
            u32* lgB = d_lgp + (size_t)(tile*128 + rB)*64;
#pragma unroll
            for (int nf = 0; nf < 8; nf++) {
                int c = n0 + nf*8 + (lane & 3)*2;
                float ba = b4s[c], bb = b4s[c+1];
                lgA[c >> 1] = pk(C[mf][nf][0] + ba, C[mf][nf][1] + bb);
                lgB[c >> 1] = pk(C[mf][nf][2] + ba, C[mf][nf][3] + bb);
            }
        }
        __syncthreads();   /* all warps done reading t before next tile reuse */
    }
}

/* =========================================================================
 * K3: softmax over k + aggregate. block = point p, thread = channel f.
 * ========================================================================= */
__global__ void k_soft(const int* __restrict__ knn_idx,
                       float* __restrict__ out_attn)
{
    int p = blockIdx.x, f = threadIdx.x;
    int base = p * KNN, bb = p >> 14;
    const float scale = 0.0883883476483184406f;   /* 1/sqrt(128) */
    float acc[KNN];
    float m = -1e30f;
#pragma unroll
    for (int k = 0; k < KNN; k++) {
        u32 wv = d_lgp[(size_t)(base + k)*64 + (f >> 1)];
        unsigned short us = (f & 1) ? (unsigned short)(wv >> 16)
                                    : (unsigned short)(wv & 0xFFFF);
        __nv_bfloat16 hb = __ushort_as_bfloat16(us);
        acc[k] = __bfloat162float(hb) * scale;
        m = fmaxf(m, acc[k]);
    }
    float s = 0.0f;
#pragma unroll
    for (int k = 0; k < KNN; k++) { acc[k] = __expf(acc[k] - m); s += acc[k]; }
    float inv = 1.0f / s;
    float rv = 0.0f;
#pragma unroll
    for (int k = 0; k < KNN; k++) {
        float a = acc[k] * inv;
        int grow = base + k;
        out_attn[(size_t)grow*128 + f] = a;
        int gi = (bb << 14) + knn_idx[grow];
        rv = fmaf(a, d_x[(size_t)gi*128 + f] + d_pe[(size_t)grow*128 + f], rv);
    }
    d_r[p*128 + f] = rv;
}

/* =========================================================================
 * K4: res = r @ fc2 + fc2_b + x  (scalar FFMA2)
 * ========================================================================= */
__global__ void k_fc2(const float* __restrict__ w, const float* __restrict__ bias,
                      float* __restrict__ out_res)
{
    extern __shared__ float sm[];
    float* ws = sm;
    float* rs = sm + 128*128;
    int t = threadIdx.x, f = t & 127, rg = t >> 7, rb = rg * 32;
    for (int i = t; i < 128*128; i += 256) ws[i] = w[i];
    int r0 = blockIdx.x * 64;
    for (int idx = t; idx < 64*128; idx += 256) {
        int j = idx & 127, r = idx >> 7;
        rs[j*68 + r] = d_r[(r0 + r)*128 + j];
    }
    __syncthreads();
    float b = bias[f];
    u64 bp = pack2(b, b);
    u64 acc[16];
#pragma unroll
    for (int i = 0; i < 16; i++) acc[i] = bp;
#pragma unroll 2
    for (int j = 0; j < 128; j++) {
        float wv = ws[j*128 + f];
        u64 wvp = pack2(wv, wv);
        const ulonglong2* rowp = (const ulonglong2*)(rs + j*68 + rb);
#pragma unroll
        for (int q = 0; q < 8; q++) {
            ulonglong2 v = rowp[q];
            ffma2(acc[2*q+0], v.x, wvp);
            ffma2(acc[2*q+1], v.y, wvp);
        }
    }
#pragma unroll
    for (int i = 0; i < 16; i++) {
        float lo, hi; unpack2(acc[i], lo, hi);
        int row = r0 + rb + 2*i;
        out_res[ row     *128 + f] = lo + d_x[ row     *128 + f];
        out_res[(row + 1)*128 + f] = hi + d_x[(row + 1)*128 + f];
    }
}

/* ========================================================================= */
extern "C" void kernel_launch(void* const* d_in, const int* in_sizes, int n_in,
                              void* d_out, int out_size)
{
    const float* feat = (const float*)d_in[0];
    const float* xyz  = (const float*)d_in[1];
    const int*   knn  = (const int*  )d_in[2];
    const float* kxyz = (const float*)d_in[3];
    const float* fc1w = (const float*)d_in[4];
    const float* fc1b = (const float*)d_in[5];
    const float* fc2w = (const float*)d_in[6];
    const float* fc2b = (const float*)d_in[7];
    const float* d1w  = (const float*)d_in[8];
    const float* d1b  = (const float*)d_in[9];
    const float* d2w  = (const float*)d_in[10];
    const float* d2b  = (const float*)d_in[11];
    const float* g1w  = (const float*)d_in[12];
    const float* g1b  = (const float*)d_in[13];
    const float* g2w  = (const float*)d_in[14];
    const float* g2b  = (const float*)d_in[15];
    float* out = (float*)d_out;

    int sms = 148;
    cudaDeviceGetAttribute(&sms, cudaDevAttrMultiProcessorCount, 0);

    size_t sm1 = (size_t)(64*128 + 64*68) * 4;
    size_t sm5 = (size_t)(128*128 + 128*68) * 4;

    cudaFuncSetAttribute(k_fc1, cudaFuncAttributeMaxDynamicSharedMemorySize, (int)sm1);
    cudaFuncSetAttribute(k2a,   cudaFuncAttributeMaxDynamicSharedMemorySize, K2A_SZ);
    cudaFuncSetAttribute(k2b,   cudaFuncAttributeMaxDynamicSharedMemorySize, K2B_SZ);
    cudaFuncSetAttribute(k_fc2, cudaFuncAttributeMaxDynamicSharedMemorySize, (int)sm5);

    k_fc1 <<<NP/64, 256, sm1   >>>(feat, fc1w, fc1b);
    k2a   <<<sms,   256, K2A_SZ>>>(xyz, knn, kxyz, d1w, d1b, d2w, d2b);
    k2b   <<<sms,   256, K2B_SZ>>>(g1w, g1b, g2w, g2b);
    k_soft<<<NP,    128        >>>(knn, out + RES_ELEMS);
    k_fc2 <<<NP/64, 256, sm5   >>>(fc2w, fc2b, out);
}

// round 12
// speedup vs baseline: 5.0646x; 1.1812x over previous
#include <cuda_runtime.h>
#include <cuda_bf16.h>
#include <cstdint>

#define BATCH 2
#define NPTS  16384
#define KNN   24
#define DM    128
#define NP    (BATCH*NPTS)
#define NR    (NP*KNN)
#define RES_ELEMS (NP*DM)
#define NT    (NR/128)          /* 6144 tiles of 128 rows */

typedef unsigned long long u64;
typedef unsigned int       u32;

/* ===================== generic-PTX MMA helpers ========================== */
__device__ __forceinline__ u32 smem_u32(const void* p){
    u32 a; asm("{ .reg .u64 t; cvta.to.shared.u64 t, %1; cvt.u32.u64 %0, t; }"
               : "=r"(a) : "l"(p));
    return a;
}
__device__ __forceinline__ void ldmA(u32* a, u32 addr){
    asm volatile("ldmatrix.sync.aligned.m8n8.x4.shared.b16 {%0,%1,%2,%3}, [%4];"
        : "=r"(a[0]), "=r"(a[1]), "=r"(a[2]), "=r"(a[3]) : "r"(addr));
}
__device__ __forceinline__ void ldmB4(u32* b, u32 addr){
    asm volatile("ldmatrix.sync.aligned.m8n8.x4.shared.b16 {%0,%1,%2,%3}, [%4];"
        : "=r"(b[0]), "=r"(b[1]), "=r"(b[2]), "=r"(b[3]) : "r"(addr));
}
__device__ __forceinline__ void mma16816(float* c, const u32* a, const u32* b){
    asm volatile("mma.sync.aligned.m16n8k16.row.col.f32.bf16.bf16.f32 "
        "{%0,%1,%2,%3}, {%4,%5,%6,%7}, {%8,%9}, {%0,%1,%2,%3};"
        : "+f"(c[0]), "+f"(c[1]), "+f"(c[2]), "+f"(c[3])
        : "r"(a[0]), "r"(a[1]), "r"(a[2]), "r"(a[3]), "r"(b[0]), "r"(b[1]));
}

/* pack two fp32 into bf16x2 word (round-to-nearest) */
__device__ __forceinline__ u32 pk(float a, float b){
    return (u32)__bfloat16_as_ushort(__float2bfloat16(a))
        | ((u32)__bfloat16_as_ushort(__float2bfloat16(b)) << 16);
}

/* weight [K x 128] row-major -> Bsm[n][k] bf16 hi/lo, row stride `stride` elems */
__device__ __forceinline__ void load_wt(const float* __restrict__ w, int K, int stride,
                                        char* bh, char* bl, int tid)
{
    for (int i = tid; i < K*128; i += 256) {
        int k = i >> 7, n = i & 127;
        float v = w[i];
        __nv_bfloat16 vh = __float2bfloat16(v);
        float vl = v - __bfloat162float(vh);
        int off = (n*stride + k)*2;
        *(__nv_bfloat16*)(bh + off) = vh;
        *(__nv_bfloat16*)(bl + off) = __float2bfloat16(vl);
    }
}
/* weight [K x 128] row-major -> Bsm[n][k] bf16 hi only */
__device__ __forceinline__ void load_wt_hi(const float* __restrict__ w, int K, int stride,
                                           char* bh, int tid)
{
    for (int i = tid; i < K*128; i += 256) {
        int k = i >> 7, n = i & 127;
        int off = (n*stride + k)*2;
        *(__nv_bfloat16*)(bh + off) = __float2bfloat16(w[i]);
    }
}

/* 2-pass warp GEMM: C = A*B^T with A single bf16, B split (hi/lo) */
template<int KSTEPS, int AST, int BST>
__device__ __forceinline__ void wgemm2(u32 aH, u32 bH, u32 bL,
                                       int m0, int n0, int lane, float C[2][8][4])
{
#pragma unroll
    for (int i = 0; i < 2; i++)
#pragma unroll
        for (int j = 0; j < 8; j++)
#pragma unroll
            for (int k = 0; k < 4; k++) C[i][j][k] = 0.0f;
    int arow = lane & 15, ach = lane >> 4;
    int brow4 = ((lane >> 4) & 1)*8 + (lane & 7);
    int bk4   = ((lane >> 3) & 1)*8;
#pragma unroll
    for (int ks = 0; ks < KSTEPS; ks++) {
        u32 Ah[2][4];
#pragma unroll
        for (int mf = 0; mf < 2; mf++) {
            u32 off = (u32)(((m0 + mf*16 + arow)*AST + ks*16 + ach*8)*2);
            ldmA(Ah[mf], aH + off);
        }
        u32 Bh[8][2], Bl[8][2];
#pragma unroll
        for (int nfp = 0; nfp < 4; nfp++) {
            u32 off = (u32)(((n0 + nfp*16 + brow4)*BST + ks*16 + bk4)*2);
            ldmB4(&Bh[nfp*2][0], bH + off);
            ldmB4(&Bl[nfp*2][0], bL + off);
        }
#pragma unroll
        for (int nf = 0; nf < 8; nf++)
#pragma unroll
            for (int mf = 0; mf < 2; mf++) {
                mma16816(C[mf][nf], Ah[mf], Bh[nf]);
                mma16816(C[mf][nf], Ah[mf], Bl[nf]);
            }
    }
}

/* 1-pass warp GEMM: C = A*B^T, pure bf16 */
template<int KSTEPS, int AST, int BST>
__device__ __forceinline__ void wgemm1(u32 aH, u32 bH,
                                       int m0, int n0, int lane, float C[2][8][4])
{
#pragma unroll
    for (int i = 0; i < 2; i++)
#pragma unroll
        for (int j = 0; j < 8; j++)
#pragma unroll
            for (int k = 0; k < 4; k++) C[i][j][k] = 0.0f;
    int arow = lane & 15, ach = lane >> 4;
    int brow4 = ((lane >> 4) & 1)*8 + (lane & 7);
    int bk4   = ((lane >> 3) & 1)*8;
#pragma unroll
    for (int ks = 0; ks < KSTEPS; ks++) {
        u32 Ah[2][4];
#pragma unroll
        for (int mf = 0; mf < 2; mf++) {
            u32 off = (u32)(((m0 + mf*16 + arow)*AST + ks*16 + ach*8)*2);
            ldmA(Ah[mf], aH + off);
        }
        u32 Bh[8][2];
#pragma unroll
        for (int nfp = 0; nfp < 4; nfp++) {
            u32 off = (u32)(((n0 + nfp*16 + brow4)*BST + ks*16 + bk4)*2);
            ldmB4(&Bh[nfp*2][0], bH + off);
        }
#pragma unroll
        for (int nf = 0; nf < 8; nf++)
#pragma unroll
            for (int mf = 0; mf < 2; mf++)
                mma16816(C[mf][nf], Ah[mf], Bh[nf]);
    }
}

/* ---- packed dual-fp32 FMA for scalar kernels ---- */
__device__ __forceinline__ u64 pack2(float x, float y){
    u64 r; asm("mov.b64 %0, {%1, %2};" : "=l"(r)
               : "r"(__float_as_uint(x)), "r"(__float_as_uint(y)));
    return r;
}
__device__ __forceinline__ void unpack2(u64 v, float& x, float& y){
    unsigned lo, hi; asm("mov.b64 {%0, %1}, %2;" : "=r"(lo), "=r"(hi) : "l"(v));
    x = __uint_as_float(lo); y = __uint_as_float(hi);
}
__device__ __forceinline__ void ffma2(u64& d, u64 a, u64 b){
    asm("fma.rn.f32x2 %0, %1, %2, %0;" : "+l"(d) : "l"(a), "l"(b));
}

/* ---- scratch ---- */
__device__ float d_x  [NP*DM];
__device__ float d_pe [(size_t)NR*DM];
__device__ u32   d_hh [(size_t)NR*64];     /* h as bf16x2           */
__device__ u32   d_lgp[(size_t)NR*64];     /* logits as bf16x2      */
__device__ float d_r  [NP*DM];

__constant__ float c_omega[10] = {
  1.0f, 0.398107170553497250f, 0.158489319246111348f, 0.063095734448019331f,
  0.025118864315095794f, 0.01f, 0.003981071705534973f, 0.001584893192461114f,
  0.000630957344480193f, 0.000251188643150958f };

/* =========================================================================
 * K1: x = features @ fc1_w + fc1_b  (scalar FFMA2)
 * ========================================================================= */
__global__ void k_fc1(const float* __restrict__ feat,
                      const float* __restrict__ w,
                      const float* __restrict__ bias)
{
    extern __shared__ float sm[];
    float* ws = sm;
    float* fs = sm + 64*128;
    int t = threadIdx.x, f = t & 127, rg = t >> 7, rb = rg * 32;
    for (int i = t; i < 64*128; i += 256) ws[i] = w[i];
    int r0 = blockIdx.x * 64;
    for (int idx = t; idx < 64*64; idx += 256) {
        int j = idx & 63, r = idx >> 6;
        fs[j*68 + r] = feat[(r0 + r)*64 + j];
    }
    __syncthreads();
    float b = bias[f];
    u64 bp = pack2(b, b);
    u64 acc[16];
#pragma unroll
    for (int i = 0; i < 16; i++) acc[i] = bp;
#pragma unroll 2
    for (int j = 0; j < 64; j++) {
        float wv = ws[j*128 + f];
        u64 wvp = pack2(wv, wv);
        const ulonglong2* rowp = (const ulonglong2*)(fs + j*68 + rb);
#pragma unroll
        for (int q = 0; q < 8; q++) {
            ulonglong2 v = rowp[q];
            ffma2(acc[2*q+0], v.x, wvp);
            ffma2(acc[2*q+1], v.y, wvp);
        }
    }
#pragma unroll
    for (int i = 0; i < 16; i++) {
        float lo, hi; unpack2(acc[i], lo, hi);
        d_x[(r0 + rb + 2*i    )*128 + f] = lo;
        d_x[(r0 + rb + 2*i + 1)*128 + f] = hi;
    }
}

/* ======================= smem layout offsets ============================ */
#define K2A_D1H 0
#define K2A_D1L 18432
#define K2A_D2H 36864
#define K2A_D2L 71680
#define K2A_EH  106496
#define K2A_TH  124928
#define K2A_B1  159744
#define K2A_B2  160256
#define K2A_SZ  160768

#define K2B_G1H 0
#define K2B_G2H 34816
#define K2B_H0  69632
#define K2B_H1  104448
#define K2B_B3  139264
#define K2B_B4  139776
#define K2B_SZ  140288

/* =========================================================================
 * K2a: per 128-row tile: embed -> G1(relu, 2-pass) -> G2(2-pass)
 *      -> pe(fp32) + h(bf16 hi)
 * ========================================================================= */
__global__ void __launch_bounds__(256, 1)
k2a(const float* __restrict__ xyz, const int* __restrict__ knn_idx,
    const float* __restrict__ kxyz,
    const float* __restrict__ d1w, const float* __restrict__ d1b,
    const float* __restrict__ d2w, const float* __restrict__ d2b)
{
    extern __shared__ __align__(128) char smem[];
    int tid = threadIdx.x, lane = tid & 31, w = tid >> 5;
    int m0 = (w >> 1) * 32, n0 = (w & 1) * 64;
    float* b1s = (float*)(smem + K2A_B1);
    float* b2s = (float*)(smem + K2A_B2);

    load_wt(d1w, 60, 72, smem + K2A_D1H, smem + K2A_D1L, tid);
    for (int i = tid; i < 128*4; i += 256) {
        int n = i >> 2, k = 60 + (i & 3);
        *(__nv_bfloat16*)(smem + K2A_D1H + (n*72 + k)*2) = __float2bfloat16(0.0f);
        *(__nv_bfloat16*)(smem + K2A_D1L + (n*72 + k)*2) = __float2bfloat16(0.0f);
    }
    load_wt(d2w, 128, 136, smem + K2A_D2H, smem + K2A_D2L, tid);
    if (tid < 128) { b1s[tid] = d1b[tid]; b2s[tid] = d2b[tid]; }
    __syncthreads();

    u32 EH = smem_u32(smem + K2A_EH);
    u32 TH = smem_u32(smem + K2A_TH);
    u32 D1H = smem_u32(smem + K2A_D1H), D1L = smem_u32(smem + K2A_D1L);
    u32 D2H = smem_u32(smem + K2A_D2H), D2L = smem_u32(smem + K2A_D2L);

    for (int tile = blockIdx.x; tile < NT; tile += gridDim.x) {
        /* ---- embedding: 128 threads, one row each (bf16 hi only) ---- */
        if (tid < 128) {
            int r = tid, grow = tile*128 + r;
            int p = grow / KNN;
            float e[64];
            e[60] = e[61] = e[62] = e[63] = 0.0f;
#pragma unroll
            for (int c = 0; c < 3; c++) {
                float g = xyz[p*3 + c] - kxyz[(size_t)grow*3 + c];
#pragma unroll
                for (int j = 0; j < 10; j++) {
                    float a = g * c_omega[j];
                    e[c*20 + j]      = __sinf(a);
                    e[c*20 + 10 + j] = __cosf(a);
                }
            }
#pragma unroll
            for (int q = 0; q < 32; q++)
                *(u32*)(smem + K2A_EH + r*144 + 4*q) = pk(e[2*q], e[2*q+1]);
        }
        __syncthreads();

        float C[2][8][4];
        /* ---- G1: t1 = relu(e @ d1 + b1), 2-pass ---- */
        wgemm2<4, 72, 72>(EH, D1H, D1L, m0, n0, lane, C);
#pragma unroll
        for (int mf = 0; mf < 2; mf++) {
            int r1 = m0 + mf*16 + (lane >> 2);
#pragma unroll
            for (int nf = 0; nf < 8; nf++) {
                int c = n0 + nf*8 + (lane & 3)*2;
                float ba = b1s[c], bb = b1s[c+1];
                *(u32*)(smem + K2A_TH + r1*272 + 2*c) =
                    pk(fmaxf(C[mf][nf][0] + ba, 0.0f), fmaxf(C[mf][nf][1] + bb, 0.0f));
                *(u32*)(smem + K2A_TH + (r1+8)*272 + 2*c) =
                    pk(fmaxf(C[mf][nf][2] + ba, 0.0f), fmaxf(C[mf][nf][3] + bb, 0.0f));
            }
        }
        __syncthreads();

        /* ---- G2: pe = t1 @ d2 + b2, 2-pass ---- */
        wgemm2<8, 136, 136>(TH, D2H, D2L, m0, n0, lane, C);
#pragma unroll
        for (int mf = 0; mf < 2; mf++) {
            int rA = m0 + mf*16 + (lane >> 2), rB = rA + 8;
            int gA = tile*128 + rA, gB = tile*128 + rB;
            int pA = gA / KNN, pB = gB / KNN;
            int iA = ((pA >> 14) << 14) + knn_idx[gA];
            int iB = ((pB >> 14) << 14) + knn_idx[gB];
            const float* xpA = d_x + (size_t)pA*128;
            const float* xgA = d_x + (size_t)iA*128;
            const float* xpB = d_x + (size_t)pB*128;
            const float* xgB = d_x + (size_t)iB*128;
            float* peA = d_pe + (size_t)gA*128;
            float* peB = d_pe + (size_t)gB*128;
            u32* hhA = d_hh + (size_t)gA*64;
            u32* hhB = d_hh + (size_t)gB*64;
#pragma unroll
            for (int nf = 0; nf < 8; nf++) {
                int c = n0 + nf*8 + (lane & 3)*2;
                float ba = b2s[c], bb = b2s[c+1];
                float p0 = C[mf][nf][0] + ba, p1 = C[mf][nf][1] + bb;
                *(float2*)(peA + c) = make_float2(p0, p1);
                hhA[c >> 1] = pk(xpA[c] - xgA[c] + p0, xpA[c+1] - xgA[c+1] + p1);
                float p2 = C[mf][nf][2] + ba, p3 = C[mf][nf][3] + bb;
                *(float2*)(peB + c) = make_float2(p2, p3);
                hhB[c >> 1] = pk(xpB[c] - xgB[c] + p2, xpB[c+1] - xgB[c+1] + p3);
            }
        }
        __syncthreads();
    }
}

/* ---- cp.async prefetch of one h tile (32 KB) into smem buffer ---- */
__device__ __forceinline__ void prefetch_h(char* dst, int tile, int tid)
{
    const u32* src = d_hh + (size_t)tile * 8192;
#pragma unroll
    for (int j = 0; j < 8; j++) {
        int wi = tid + j*256;                       /* 0..2047 16B chunks */
        u32 daddr = smem_u32(dst + (wi >> 4)*272 + (wi & 15)*16);
        asm volatile("cp.async.ca.shared.global [%0], [%1], 16;"
                     :: "r"(daddr), "l"(src + wi*4) : "memory");
    }
    asm volatile("cp.async.commit_group;" ::: "memory");
}

/* =========================================================================
 * K2b: per 128-row tile: h -> G3(relu, 1-pass) -> G4(1-pass) -> logits bf16
 * double-buffered cp.async h prefetch.
 * ========================================================================= */
__global__ void __launch_bounds__(256, 1)
k2b(const float* __restrict__ g1w, const float* __restrict__ g1b,
    const float* __restrict__ g2w, const float* __restrict__ g2b)
{
    extern __shared__ __align__(128) char smem[];
    int tid = threadIdx.x, lane = tid & 31, w = tid >> 5;
    int m0 = (w >> 1) * 32, n0 = (w & 1) * 64;
    float* b3s = (float*)(smem + K2B_B3);
    float* b4s = (float*)(smem + K2B_B4);

    load_wt_hi(g1w, 128, 136, smem + K2B_G1H, tid);
    load_wt_hi(g2w, 128, 136, smem + K2B_G2H, tid);
    if (tid < 128) { b3s[tid] = g1b[tid]; b4s[tid] = g2b[tid]; }

    u32 G1H = smem_u32(smem + K2B_G1H);
    u32 G2H = smem_u32(smem + K2B_G2H);
    char* hbuf[2] = { smem + K2B_H0, smem + K2B_H1 };
    u32 hadr[2] = { smem_u32(smem + K2B_H0), smem_u32(smem + K2B_H1) };

    int tile = blockIdx.x;
    if (tile < NT) prefetch_h(hbuf[0], tile, tid);
    __syncthreads();
    int cur = 0;

    for (; tile < NT; tile += gridDim.x, cur ^= 1) {
        asm volatile("cp.async.wait_group 0;" ::: "memory");
        __syncthreads();
        int nxt = tile + gridDim.x;
        if (nxt < NT) prefetch_h(hbuf[cur ^ 1], nxt, tid);

        float C[2][8][4];
        /* ---- G3: t = relu(h @ g1 + b3), 1-pass ---- */
        wgemm1<8, 136, 136>(hadr[cur], G1H, m0, n0, lane, C);
        __syncthreads();   /* all warps done reading h before overwrite */
#pragma unroll
        for (int mf = 0; mf < 2; mf++) {
            int r1 = m0 + mf*16 + (lane >> 2);
#pragma unroll
            for (int nf = 0; nf < 8; nf++) {
                int c = n0 + nf*8 + (lane & 3)*2;
                float ba = b3s[c], bb = b3s[c+1];
                *(u32*)(hbuf[cur] + r1*272 + 2*c) =
                    pk(fmaxf(C[mf][nf][0] + ba, 0.0f), fmaxf(C[mf][nf][1] + bb, 0.0f));
                *(u32*)(hbuf[cur] + (r1+8)*272 + 2*c) =
                    pk(fmaxf(C[mf][nf][2] + ba, 0.0f), fmaxf(C[mf][nf][3] + bb, 0.0f));
            }
        }
        __syncthreads();

        /* ---- G4: logits = t @ g2 + b4, 1-pass -> bf16x2 gmem ---- */
        wgemm1<8, 136, 136>(hadr[cur], G2H, m0, n0, lane, C);
#pragma unroll
        for (int mf = 0; mf < 2; mf++) {
            int rA = m0 + mf*16 + (lane >> 2), rB = rA + 8;
            u32* lgA = d_lgp + (size_t)(tile*128 + rA)*64;
            u32* lgB = d_lgp + (size_t)(tile*128 + rB)*64;
#pragma unroll
            for (int nf = 0; nf < 8; nf++) {
                int c = n0 + nf*8 + (lane & 3)*2;
                float ba = b4s[c], bb = b4s[c+1];
                lgA[c >> 1] = pk(C[mf][nf][0] + ba, C[mf][nf][1] + bb);
                lgB[c >> 1] = pk(C[mf][nf][2] + ba, C[mf][nf][3] + bb);
            }
        }
        __syncthreads();   /* all warps done reading t before next tile reuse */
    }
}

/* =========================================================================
 * K3: softmax over k + aggregate. block = point p, thread = channel f.
 * ========================================================================= */
__global__ void k_soft(const int* __restrict__ knn_idx,
                       float* __restrict__ out_attn)
{
    int p = blockIdx.x, f = threadIdx.x;
    int base = p * KNN, bb = p >> 14;
    const float scale = 0.0883883476483184406f;   /* 1/sqrt(128) */
    float acc[KNN];
    float m = -1e30f;
#pragma unroll
    for (int k = 0; k < KNN; k++) {
        u32 wv = d_lgp[(size_t)(base + k)*64 + (f >> 1)];
        unsigned short us = (f & 1) ? (unsigned short)(wv >> 16)
                                    : (unsigned short)(wv & 0xFFFF);
        __nv_bfloat16 hb = __ushort_as_bfloat16(us);
        acc[k] = __bfloat162float(hb) * scale;
        m = fmaxf(m, acc[k]);
    }
    float s = 0.0f;
#pragma unroll
    for (int k = 0; k < KNN; k++) { acc[k] = __expf(acc[k] - m); s += acc[k]; }
    float inv = 1.0f / s;
    float rv = 0.0f;
#pragma unroll
    for (int k = 0; k < KNN; k++) {
        float a = acc[k] * inv;
        int grow = base + k;
        out_attn[(size_t)grow*128 + f] = a;
        int gi = (bb << 14) + knn_idx[grow];
        rv = fmaf(a, d_x[(size_t)gi*128 + f] + d_pe[(size_t)grow*128 + f], rv);
    }
    d_r[p*128 + f] = rv;
}

/* =========================================================================
 * K4: res = r @ fc2 + fc2_b + x  (scalar FFMA2)
 * ========================================================================= */
__global__ void k_fc2(const float* __restrict__ w, const float* __restrict__ bias,
                      float* __restrict__ out_res)
{
    extern __shared__ float sm[];
    float* ws = sm;
    float* rs = sm + 128*128;
    int t = threadIdx.x, f = t & 127, rg = t >> 7, rb = rg * 32;
    for (int i = t; i < 128*128; i += 256) ws[i] = w[i];
    int r0 = blockIdx.x * 64;
    for (int idx = t; idx < 64*128; idx += 256) {
        int j = idx & 127, r = idx >> 7;
        rs[j*68 + r] = d_r[(r0 + r)*128 + j];
    }
    __syncthreads();
    float b = bias[f];
    u64 bp = pack2(b, b);
    u64 acc[16];
#pragma unroll
    for (int i = 0; i < 16; i++) acc[i] = bp;
#pragma unroll 2
    for (int j = 0; j < 128; j++) {
        float wv = ws[j*128 + f];
        u64 wvp = pack2(wv, wv);
        const ulonglong2* rowp = (const ulonglong2*)(rs + j*68 + rb);
#pragma unroll
        for (int q = 0; q < 8; q++) {
            ulonglong2 v = rowp[q];
            ffma2(acc[2*q+0], v.x, wvp);
            ffma2(acc[2*q+1], v.y, wvp);
        }
    }
#pragma unroll
    for (int i = 0; i < 16; i++) {
        float lo, hi; unpack2(acc[i], lo, hi);
        int row = r0 + rb + 2*i;
        out_res[ row     *128 + f] = lo + d_x[ row     *128 + f];
        out_res[(row + 1)*128 + f] = hi + d_x[(row + 1)*128 + f];
    }
}

/* ========================================================================= */
extern "C" void kernel_launch(void* const* d_in, const int* in_sizes, int n_in,
                              void* d_out, int out_size)
{
    const float* feat = (const float*)d_in[0];
    const float* xyz  = (const float*)d_in[1];
    const int*   knn  = (const int*  )d_in[2];
    const float* kxyz = (const float*)d_in[3];
    const float* fc1w = (const float*)d_in[4];
    const float* fc1b = (const float*)d_in[5];
    const float* fc2w = (const float*)d_in[6];
    const float* fc2b = (const float*)d_in[7];
    const float* d1w  = (const float*)d_in[8];
    const float* d1b  = (const float*)d_in[9];
    const float* d2w  = (const float*)d_in[10];
    const float* d2b  = (const float*)d_in[11];
    const float* g1w  = (const float*)d_in[12];
    const float* g1b  = (const float*)d_in[13];
    const float* g2w  = (const float*)d_in[14];
    const float* g2b  = (const float*)d_in[15];
    float* out = (float*)d_out;

    int sms = 148;
    cudaDeviceGetAttribute(&sms, cudaDevAttrMultiProcessorCount, 0);

    size_t sm1 = (size_t)(64*128 + 64*68) * 4;
    size_t sm5 = (size_t)(128*128 + 128*68) * 4;

    cudaFuncSetAttribute(k_fc1, cudaFuncAttributeMaxDynamicSharedMemorySize, (int)sm1);
    cudaFuncSetAttribute(k2a,   cudaFuncAttributeMaxDynamicSharedMemorySize, K2A_SZ);
    cudaFuncSetAttribute(k2b,   cudaFuncAttributeMaxDynamicSharedMemorySize, K2B_SZ);
    cudaFuncSetAttribute(k_fc2, cudaFuncAttributeMaxDynamicSharedMemorySize, (int)sm5);

    k_fc1 <<<NP/64, 256, sm1   >>>(feat, fc1w, fc1b);
    k2a   <<<sms,   256, K2A_SZ>>>(xyz, knn, kxyz, d1w, d1b, d2w, d2b);
    k2b   <<<sms,   256, K2B_SZ>>>(g1w, g1b, g2w, g2b);
    k_soft<<<NP,    128        >>>(knn, out + RES_ELEMS);
    k_fc2 <<<NP/64, 256, sm5   >>>(fc2w, fc2b, out);
}

// round 13
// speedup vs baseline: 6.6445x; 1.3119x over previous
#include <cuda_runtime.h>
#include <cuda_bf16.h>
#include <cstdint>

#define BATCH 2
#define NPTS  16384
#define KNN   24
#define DM    128
#define NP    (BATCH*NPTS)
#define NR    (NP*KNN)
#define RES_ELEMS (NP*DM)
#define NT    (NR/128)          /* 6144 tiles of 128 rows */

typedef unsigned long long u64;
typedef unsigned int       u32;

/* ===================== generic-PTX MMA helpers ========================== */
__device__ __forceinline__ u32 smem_u32(const void* p){
    u32 a; asm("{ .reg .u64 t; cvta.to.shared.u64 t, %1; cvt.u32.u64 %0, t; }"
               : "=r"(a) : "l"(p));
    return a;
}
__device__ __forceinline__ void ldmA(u32* a, u32 addr){
    asm volatile("ldmatrix.sync.aligned.m8n8.x4.shared.b16 {%0,%1,%2,%3}, [%4];"
        : "=r"(a[0]), "=r"(a[1]), "=r"(a[2]), "=r"(a[3]) : "r"(addr));
}
__device__ __forceinline__ void ldmB4(u32* b, u32 addr){
    asm volatile("ldmatrix.sync.aligned.m8n8.x4.shared.b16 {%0,%1,%2,%3}, [%4];"
        : "=r"(b[0]), "=r"(b[1]), "=r"(b[2]), "=r"(b[3]) : "r"(addr));
}
__device__ __forceinline__ void mma16816(float* c, const u32* a, const u32* b){
    asm volatile("mma.sync.aligned.m16n8k16.row.col.f32.bf16.bf16.f32 "
        "{%0,%1,%2,%3}, {%4,%5,%6,%7}, {%8,%9}, {%0,%1,%2,%3};"
        : "+f"(c[0]), "+f"(c[1]), "+f"(c[2]), "+f"(c[3])
        : "r"(a[0]), "r"(a[1]), "r"(a[2]), "r"(a[3]), "r"(b[0]), "r"(b[1]));
}

/* pack two fp32 into bf16x2 word (round-to-nearest) */
__device__ __forceinline__ u32 pk(float a, float b){
    return (u32)__bfloat16_as_ushort(__float2bfloat16(a))
        | ((u32)__bfloat16_as_ushort(__float2bfloat16(b)) << 16);
}
__device__ __forceinline__ float bf_lo(u32 w){
    return __bfloat162float(__ushort_as_bfloat16((unsigned short)(w & 0xFFFF)));
}
__device__ __forceinline__ float bf_hi(u32 w){
    return __bfloat162float(__ushort_as_bfloat16((unsigned short)(w >> 16)));
}

/* weight [K x 128] row-major -> Bsm[n][k] bf16 hi only, row stride `stride` */
__device__ __forceinline__ void load_wt_hi(const float* __restrict__ w, int K, int stride,
                                           char* bh, int tid)
{
    for (int i = tid; i < K*128; i += 256) {
        int k = i >> 7, n = i & 127;
        int off = (n*stride + k)*2;
        *(__nv_bfloat16*)(bh + off) = __float2bfloat16(w[i]);
    }
}

/* 1-pass warp GEMM: C = A*B^T, pure bf16 */
template<int KSTEPS, int AST, int BST>
__device__ __forceinline__ void wgemm1(u32 aH, u32 bH,
                                       int m0, int n0, int lane, float C[2][8][4])
{
#pragma unroll
    for (int i = 0; i < 2; i++)
#pragma unroll
        for (int j = 0; j < 8; j++)
#pragma unroll
            for (int k = 0; k < 4; k++) C[i][j][k] = 0.0f;
    int arow = lane & 15, ach = lane >> 4;
    int brow4 = ((lane >> 4) & 1)*8 + (lane & 7);
    int bk4   = ((lane >> 3) & 1)*8;
#pragma unroll
    for (int ks = 0; ks < KSTEPS; ks++) {
        u32 Ah[2][4];
#pragma unroll
        for (int mf = 0; mf < 2; mf++) {
            u32 off = (u32)(((m0 + mf*16 + arow)*AST + ks*16 + ach*8)*2);
            ldmA(Ah[mf], aH + off);
        }
        u32 Bh[8][2];
#pragma unroll
        for (int nfp = 0; nfp < 4; nfp++) {
            u32 off = (u32)(((n0 + nfp*16 + brow4)*BST + ks*16 + bk4)*2);
            ldmB4(&Bh[nfp*2][0], bH + off);
        }
#pragma unroll
        for (int nf = 0; nf < 8; nf++)
#pragma unroll
            for (int mf = 0; mf < 2; mf++)
                mma16816(C[mf][nf], Ah[mf], Bh[nf]);
    }
}

/* ---- packed dual-fp32 FMA for scalar kernels ---- */
__device__ __forceinline__ u64 pack2(float x, float y){
    u64 r; asm("mov.b64 %0, {%1, %2};" : "=l"(r)
               : "r"(__float_as_uint(x)), "r"(__float_as_uint(y)));
    return r;
}
__device__ __forceinline__ void unpack2(u64 v, float& x, float& y){
    unsigned lo, hi; asm("mov.b64 {%0, %1}, %2;" : "=r"(lo), "=r"(hi) : "l"(v));
    x = __uint_as_float(lo); y = __uint_as_float(hi);
}
__device__ __forceinline__ void ffma2(u64& d, u64 a, u64 b){
    asm("fma.rn.f32x2 %0, %1, %2, %0;" : "+l"(d) : "l"(a), "l"(b));
}

/* ---- scratch ---- */
__device__ float d_x  [NP*DM];
__device__ u32   d_pe [(size_t)NR*64];     /* pe as bf16x2          */
__device__ u32   d_hh [(size_t)NR*64];     /* h as bf16x2           */
__device__ u32   d_lgp[(size_t)NR*64];     /* logits as bf16x2      */
__device__ float d_r  [NP*DM];

__constant__ float c_omega[10] = {
  1.0f, 0.398107170553497250f, 0.158489319246111348f, 0.063095734448019331f,
  0.025118864315095794f, 0.01f, 0.003981071705534973f, 0.001584893192461114f,
  0.000630957344480193f, 0.000251188643150958f };

/* =========================================================================
 * K1: x = features @ fc1_w + fc1_b  (scalar FFMA2)
 * ========================================================================= */
__global__ void k_fc1(const float* __restrict__ feat,
                      const float* __restrict__ w,
                      const float* __restrict__ bias)
{
    extern __shared__ float sm[];
    float* ws = sm;
    float* fs = sm + 64*128;
    int t = threadIdx.x, f = t & 127, rg = t >> 7, rb = rg * 32;
    for (int i = t; i < 64*128; i += 256) ws[i] = w[i];
    int r0 = blockIdx.x * 64;
    for (int idx = t; idx < 64*64; idx += 256) {
        int j = idx & 63, r = idx >> 6;
        fs[j*68 + r] = feat[(r0 + r)*64 + j];
    }
    __syncthreads();
    float b = bias[f];
    u64 bp = pack2(b, b);
    u64 acc[16];
#pragma unroll
    for (int i = 0; i < 16; i++) acc[i] = bp;
#pragma unroll 2
    for (int j = 0; j < 64; j++) {
        float wv = ws[j*128 + f];
        u64 wvp = pack2(wv, wv);
        const ulonglong2* rowp = (const ulonglong2*)(fs + j*68 + rb);
#pragma unroll
        for (int q = 0; q < 8; q++) {
            ulonglong2 v = rowp[q];
            ffma2(acc[2*q+0], v.x, wvp);
            ffma2(acc[2*q+1], v.y, wvp);
        }
    }
#pragma unroll
    for (int i = 0; i < 16; i++) {
        float lo, hi; unpack2(acc[i], lo, hi);
        d_x[(r0 + rb + 2*i    )*128 + f] = lo;
        d_x[(r0 + rb + 2*i + 1)*128 + f] = hi;
    }
}

/* ======================= smem layout offsets ============================ */
#define K2A_D1H 0
#define K2A_D2H 18432
#define K2A_EH  53248
#define K2A_TH  71680
#define K2A_B1  106496
#define K2A_B2  107008
#define K2A_SZ  107520

#define K2B_G1H 0
#define K2B_G2H 34816
#define K2B_H0  69632
#define K2B_H1  104448
#define K2B_B3  139264
#define K2B_B4  139776
#define K2B_SZ  140288

/* =========================================================================
 * K2a: per 128-row tile: embed -> G1(relu, 1-pass) -> G2(1-pass)
 *      -> pe(bf16x2) + h(bf16x2).  2 CTAs/SM.
 * ========================================================================= */
__global__ void __launch_bounds__(256, 2)
k2a(const float* __restrict__ xyz, const int* __restrict__ knn_idx,
    const float* __restrict__ kxyz,
    const float* __restrict__ d1w, const float* __restrict__ d1b,
    const float* __restrict__ d2w, const float* __restrict__ d2b)
{
    extern __shared__ __align__(128) char smem[];
    int tid = threadIdx.x, lane = tid & 31, w = tid >> 5;
    int m0 = (w >> 1) * 32, n0 = (w & 1) * 64;
    float* b1s = (float*)(smem + K2A_B1);
    float* b2s = (float*)(smem + K2A_B2);

    load_wt_hi(d1w, 60, 72, smem + K2A_D1H, tid);
    for (int i = tid; i < 128*4; i += 256) {
        int n = i >> 2, k = 60 + (i & 3);
        *(__nv_bfloat16*)(smem + K2A_D1H + (n*72 + k)*2) = __float2bfloat16(0.0f);
    }
    load_wt_hi(d2w, 128, 136, smem + K2A_D2H, tid);
    if (tid < 128) { b1s[tid] = d1b[tid]; b2s[tid] = d2b[tid]; }
    __syncthreads();

    u32 EH = smem_u32(smem + K2A_EH);
    u32 TH = smem_u32(smem + K2A_TH);
    u32 D1H = smem_u32(smem + K2A_D1H);
    u32 D2H = smem_u32(smem + K2A_D2H);

    for (int tile = blockIdx.x; tile < NT; tile += gridDim.x) {
        /* ---- embedding: 128 threads, one row each (bf16 hi only) ---- */
        if (tid < 128) {
            int r = tid, grow = tile*128 + r;
            int p = grow / KNN;
            float e[64];
            e[60] = e[61] = e[62] = e[63] = 0.0f;
#pragma unroll
            for (int c = 0; c < 3; c++) {
                float g = xyz[p*3 + c] - kxyz[(size_t)grow*3 + c];
#pragma unroll
                for (int j = 0; j < 10; j++) {
                    float a = g * c_omega[j];
                    e[c*20 + j]      = __sinf(a);
                    e[c*20 + 10 + j] = __cosf(a);
                }
            }
#pragma unroll
            for (int q = 0; q < 32; q++)
                *(u32*)(smem + K2A_EH + r*144 + 4*q) = pk(e[2*q], e[2*q+1]);
        }
        __syncthreads();

        float C[2][8][4];
        /* ---- G1: t1 = relu(e @ d1 + b1), 1-pass ---- */
        wgemm1<4, 72, 72>(EH, D1H, m0, n0, lane, C);
#pragma unroll
        for (int mf = 0; mf < 2; mf++) {
            int r1 = m0 + mf*16 + (lane >> 2);
#pragma unroll
            for (int nf = 0; nf < 8; nf++) {
                int c = n0 + nf*8 + (lane & 3)*2;
                float ba = b1s[c], bb = b1s[c+1];
                *(u32*)(smem + K2A_TH + r1*272 + 2*c) =
                    pk(fmaxf(C[mf][nf][0] + ba, 0.0f), fmaxf(C[mf][nf][1] + bb, 0.0f));
                *(u32*)(smem + K2A_TH + (r1+8)*272 + 2*c) =
                    pk(fmaxf(C[mf][nf][2] + ba, 0.0f), fmaxf(C[mf][nf][3] + bb, 0.0f));
            }
        }
        __syncthreads();

        /* ---- G2: pe = t1 @ d2 + b2, 1-pass ---- */
        wgemm1<8, 136, 136>(TH, D2H, m0, n0, lane, C);
#pragma unroll
        for (int mf = 0; mf < 2; mf++) {
            int rA = m0 + mf*16 + (lane >> 2), rB = rA + 8;
            int gA = tile*128 + rA, gB = tile*128 + rB;
            int pA = gA / KNN, pB = gB / KNN;
            int iA = ((pA >> 14) << 14) + knn_idx[gA];
            int iB = ((pB >> 14) << 14) + knn_idx[gB];
            const float* xpA = d_x + (size_t)pA*128;
            const float* xgA = d_x + (size_t)iA*128;
            const float* xpB = d_x + (size_t)pB*128;
            const float* xgB = d_x + (size_t)iB*128;
            u32* peA = d_pe + (size_t)gA*64;
            u32* peB = d_pe + (size_t)gB*64;
            u32* hhA = d_hh + (size_t)gA*64;
            u32* hhB = d_hh + (size_t)gB*64;
#pragma unroll
            for (int nf = 0; nf < 8; nf++) {
                int c = n0 + nf*8 + (lane & 3)*2;
                float ba = b2s[c], bb = b2s[c+1];
                float p0 = C[mf][nf][0] + ba, p1 = C[mf][nf][1] + bb;
                peA[c >> 1] = pk(p0, p1);
                hhA[c >> 1] = pk(xpA[c] - xgA[c] + p0, xpA[c+1] - xgA[c+1] + p1);
                float p2 = C[mf][nf][2] + ba, p3 = C[mf][nf][3] + bb;
                peB[c >> 1] = pk(p2, p3);
                hhB[c >> 1] = pk(xpB[c] - xgB[c] + p2, xpB[c+1] - xgB[c+1] + p3);
            }
        }
        __syncthreads();
    }
}

/* ---- cp.async prefetch of one h tile (32 KB) into smem buffer ---- */
__device__ __forceinline__ void prefetch_h(char* dst, int tile, int tid)
{
    const u32* src = d_hh + (size_t)tile * 8192;
#pragma unroll
    for (int j = 0; j < 8; j++) {
        int wi = tid + j*256;                       /* 0..2047 16B chunks */
        u32 daddr = smem_u32(dst + (wi >> 4)*272 + (wi & 15)*16);
        asm volatile("cp.async.ca.shared.global [%0], [%1], 16;"
                     :: "r"(daddr), "l"(src + wi*4) : "memory");
    }
    asm volatile("cp.async.commit_group;" ::: "memory");
}

/* =========================================================================
 * K2b: per 128-row tile: h -> G3(relu, 1-pass) -> G4(1-pass) -> logits bf16
 * double-buffered cp.async h prefetch.
 * ========================================================================= */
__global__ void __launch_bounds__(256, 1)
k2b(const float* __restrict__ g1w, const float* __restrict__ g1b,
    const float* __restrict__ g2w, const float* __restrict__ g2b)
{
    extern __shared__ __align__(128) char smem[];
    int tid = threadIdx.x, lane = tid & 31, w = tid >> 5;
    int m0 = (w >> 1) * 32, n0 = (w & 1) * 64;
    float* b3s = (float*)(smem + K2B_B3);
    float* b4s = (float*)(smem + K2B_B4);

    load_wt_hi(g1w, 128, 136, smem + K2B_G1H, tid);
    load_wt_hi(g2w, 128, 136, smem + K2B_G2H, tid);
    if (tid < 128) { b3s[tid] = g1b[tid]; b4s[tid] = g2b[tid]; }

    u32 G1H = smem_u32(smem + K2B_G1H);
    u32 G2H = smem_u32(smem + K2B_G2H);
    char* hbuf[2] = { smem + K2B_H0, smem + K2B_H1 };
    u32 hadr[2] = { smem_u32(smem + K2B_H0), smem_u32(smem + K2B_H1) };

    int tile = blockIdx.x;
    if (tile < NT) prefetch_h(hbuf[0], tile, tid);
    __syncthreads();
    int cur = 0;

    for (; tile < NT; tile += gridDim.x, cur ^= 1) {
        asm volatile("cp.async.wait_group 0;" ::: "memory");
        __syncthreads();
        int nxt = tile + gridDim.x;
        if (nxt < NT) prefetch_h(hbuf[cur ^ 1], nxt, tid);

        float C[2][8][4];
        /* ---- G3: t = relu(h @ g1 + b3), 1-pass ---- */
        wgemm1<8, 136, 136>(hadr[cur], G1H, m0, n0, lane, C);
        __syncthreads();   /* all warps done reading h before overwrite */
#pragma unroll
        for (int mf = 0; mf < 2; mf++) {
            int r1 = m0 + mf*16 + (lane >> 2);
#pragma unroll
            for (int nf = 0; nf < 8; nf++) {
                int c = n0 + nf*8 + (lane & 3)*2;
                float ba = b3s[c], bb = b3s[c+1];
                *(u32*)(hbuf[cur] + r1*272 + 2*c) =
                    pk(fmaxf(C[mf][nf][0] + ba, 0.0f), fmaxf(C[mf][nf][1] + bb, 0.0f));
                *(u32*)(hbuf[cur] + (r1+8)*272 + 2*c) =
                    pk(fmaxf(C[mf][nf][2] + ba, 0.0f), fmaxf(C[mf][nf][3] + bb, 0.0f));
            }
        }
        __syncthreads();

        /* ---- G4: logits = t @ g2 + b4, 1-pass -> bf16x2 gmem ---- */
        wgemm1<8, 136, 136>(hadr[cur], G2H, m0, n0, lane, C);
#pragma unroll
        for (int mf = 0; mf < 2; mf++) {
            int rA = m0 + mf*16 + (lane >> 2), rB = rA + 8;
            u32* lgA = d_lgp + (size_t)(tile*128 + rA)*64;
            u32* lgB = d_lgp + (size_t)(tile*128 + rB)*64;
#pragma unroll
            for (int nf = 0; nf < 8; nf++) {
                int c = n0 + nf*8 + (lane & 3)*2;
                float ba = b4s[c], bb = b4s[c+1];
                lgA[c >> 1] = pk(C[mf][nf][0] + ba, C[mf][nf][1] + bb);
                lgB[c >> 1] = pk(C[mf][nf][2] + ba, C[mf][nf][3] + bb);
            }
        }
        __syncthreads();   /* all warps done reading t before next tile reuse */
    }
}

/* =========================================================================
 * K3: softmax over k + aggregate. block = point p, thread = channel f.
 * ========================================================================= */
__global__ void k_soft(const int* __restrict__ knn_idx,
                       float* __restrict__ out_attn)
{
    int p = blockIdx.x, f = threadIdx.x;
    int base = p * KNN, bb = p >> 14;
    const float scale = 0.0883883476483184406f;   /* 1/sqrt(128) */
    float acc[KNN];
    float m = -1e30f;
#pragma unroll
    for (int k = 0; k < KNN; k++) {
        u32 wv = d_lgp[(size_t)(base + k)*64 + (f >> 1)];
        acc[k] = ((f & 1) ? bf_hi(wv) : bf_lo(wv)) * scale;
        m = fmaxf(m, acc[k]);
    }
    float s = 0.0f;
#pragma unroll
    for (int k = 0; k < KNN; k++) { acc[k] = __expf(acc[k] - m); s += acc[k]; }
    float inv = 1.0f / s;
    float rv = 0.0f;
#pragma unroll
    for (int k = 0; k < KNN; k++) {
        float a = acc[k] * inv;
        int grow = base + k;
        out_attn[(size_t)grow*128 + f] = a;
        int gi = (bb << 14) + knn_idx[grow];
        u32 pw = d_pe[(size_t)grow*64 + (f >> 1)];
        float pe = (f & 1) ? bf_hi(pw) : bf_lo(pw);
        rv = fmaf(a, d_x[(size_t)gi*128 + f] + pe, rv);
    }
    d_r[p*128 + f] = rv;
}

/* =========================================================================
 * K4: res = r @ fc2 + fc2_b + x  (scalar FFMA2)
 * ========================================================================= */
__global__ void k_fc2(const float* __restrict__ w, const float* __restrict__ bias,
                      float* __restrict__ out_res)
{
    extern __shared__ float sm[];
    float* ws = sm;
    float* rs = sm + 128*128;
    int t = threadIdx.x, f = t & 127, rg = t >> 7, rb = rg * 32;
    for (int i = t; i < 128*128; i += 256) ws[i] = w[i];
    int r0 = blockIdx.x * 64;
    for (int idx = t; idx < 64*128; idx += 256) {
        int j = idx & 127, r = idx >> 7;
        rs[j*68 + r] = d_r[(r0 + r)*128 + j];
    }
    __syncthreads();
    float b = bias[f];
    u64 bp = pack2(b, b);
    u64 acc[16];
#pragma unroll
    for (int i = 0; i < 16; i++) acc[i] = bp;
#pragma unroll 2
    for (int j = 0; j < 128; j++) {
        float wv = ws[j*128 + f];
        u64 wvp = pack2(wv, wv);
        const ulonglong2* rowp = (const ulonglong2*)(rs + j*68 + rb);
#pragma unroll
        for (int q = 0; q < 8; q++) {
            ulonglong2 v = rowp[q];
            ffma2(acc[2*q+0], v.x, wvp);
            ffma2(acc[2*q+1], v.y, wvp);
        }
    }
#pragma unroll
    for (int i = 0; i < 16; i++) {
        float lo, hi; unpack2(acc[i], lo, hi);
        int row = r0 + rb + 2*i;
        out_res[ row     *128 + f] = lo + d_x[ row     *128 + f];
        out_res[(row + 1)*128 + f] = hi + d_x[(row + 1)*128 + f];
    }
}

/* ========================================================================= */
extern "C" void kernel_launch(void* const* d_in, const int* in_sizes, int n_in,
                              void* d_out, int out_size)
{
    const float* feat = (const float*)d_in[0];
    const float* xyz  = (const float*)d_in[1];
    const int*   knn  = (const int*  )d_in[2];
    const float* kxyz = (const float*)d_in[3];
    const float* fc1w = (const float*)d_in[4];
    const float* fc1b = (const float*)d_in[5];
    const float* fc2w = (const float*)d_in[6];
    const float* fc2b = (const float*)d_in[7];
    const float* d1w  = (const float*)d_in[8];
    const float* d1b  = (const float*)d_in[9];
    const float* d2w  = (const float*)d_in[10];
    const float* d2b  = (const float*)d_in[11];
    const float* g1w  = (const float*)d_in[12];
    const float* g1b  = (const float*)d_in[13];
    const float* g2w  = (const float*)d_in[14];
    const float* g2b  = (const float*)d_in[15];
    float* out = (float*)d_out;

    int sms = 148;
    cudaDeviceGetAttribute(&sms, cudaDevAttrMultiProcessorCount, 0);

    size_t sm1 = (size_t)(64*128 + 64*68) * 4;
    size_t sm5 = (size_t)(128*128 + 128*68) * 4;

    cudaFuncSetAttribute(k_fc1, cudaFuncAttributeMaxDynamicSharedMemorySize, (int)sm1);
    cudaFuncSetAttribute(k2a,   cudaFuncAttributeMaxDynamicSharedMemorySize, K2A_SZ);
    cudaFuncSetAttribute(k2b,   cudaFuncAttributeMaxDynamicSharedMemorySize, K2B_SZ);
    cudaFuncSetAttribute(k_fc2, cudaFuncAttributeMaxDynamicSharedMemorySize, (int)sm5);

    k_fc1 <<<NP/64,  256, sm1   >>>(feat, fc1w, fc1b);
    k2a   <<<2*sms,  256, K2A_SZ>>>(xyz, knn, kxyz, d1w, d1b, d2w, d2b);
    k2b   <<<sms,    256, K2B_SZ>>>(g1w, g1b, g2w, g2b);
    k_soft<<<NP,     128        >>>(knn, out + RES_ELEMS);
    k_fc2 <<<NP/64,  256, sm5   >>>(fc2w, fc2b, out);
}

// round 14
// speedup vs baseline: 7.4983x; 1.1285x over previous
#include <cuda_runtime.h>
#include <cuda_bf16.h>
#include <cstdint>

#define BATCH 2
#define NPTS  16384
#define KNN   24
#define DM    128
#define NP    (BATCH*NPTS)
#define NR    (NP*KNN)
#define RES_ELEMS (NP*DM)
#define NT    (NR/128)          /* 6144 tiles of 128 rows */
#define NT2   (NP/128)          /* 256 tiles for fc kernels */

typedef unsigned long long u64;
typedef unsigned int       u32;

/* ===================== generic-PTX MMA helpers ========================== */
__device__ __forceinline__ u32 smem_u32(const void* p){
    u32 a; asm("{ .reg .u64 t; cvta.to.shared.u64 t, %1; cvt.u32.u64 %0, t; }"
               : "=r"(a) : "l"(p));
    return a;
}
__device__ __forceinline__ void ldmA(u32* a, u32 addr){
    asm volatile("ldmatrix.sync.aligned.m8n8.x4.shared.b16 {%0,%1,%2,%3}, [%4];"
        : "=r"(a[0]), "=r"(a[1]), "=r"(a[2]), "=r"(a[3]) : "r"(addr));
}
__device__ __forceinline__ void ldmB4(u32* b, u32 addr){
    asm volatile("ldmatrix.sync.aligned.m8n8.x4.shared.b16 {%0,%1,%2,%3}, [%4];"
        : "=r"(b[0]), "=r"(b[1]), "=r"(b[2]), "=r"(b[3]) : "r"(addr));
}
__device__ __forceinline__ void mma16816(float* c, const u32* a, const u32* b){
    asm volatile("mma.sync.aligned.m16n8k16.row.col.f32.bf16.bf16.f32 "
        "{%0,%1,%2,%3}, {%4,%5,%6,%7}, {%8,%9}, {%0,%1,%2,%3};"
        : "+f"(c[0]), "+f"(c[1]), "+f"(c[2]), "+f"(c[3])
        : "r"(a[0]), "r"(a[1]), "r"(a[2]), "r"(a[3]), "r"(b[0]), "r"(b[1]));
}

/* pack two fp32 into bf16x2 word: single sm_90+ instruction, RN rounding */
__device__ __forceinline__ u32 pk(float a, float b){
    u32 r; asm("cvt.rn.bf16x2.f32 %0, %1, %2;" : "=r"(r) : "f"(b), "f"(a));
    return r;
}
__device__ __forceinline__ float bf_lo(u32 w){
    return __bfloat162float(__ushort_as_bfloat16((unsigned short)(w & 0xFFFF)));
}
__device__ __forceinline__ float bf_hi(u32 w){
    return __bfloat162float(__ushort_as_bfloat16((unsigned short)(w >> 16)));
}
/* split fp32 pair into bf16x2 hi word + bf16x2 lo (residual) word */
__device__ __forceinline__ void split2(float a, float b, u32& hi, u32& lo){
    __nv_bfloat16 ah = __float2bfloat16(a), bh = __float2bfloat16(b);
    hi = (u32)__bfloat16_as_ushort(ah) | ((u32)__bfloat16_as_ushort(bh) << 16);
    lo = pk(a - __bfloat162float(ah), b - __bfloat162float(bh));
}

/* weight [K x 128] row-major -> Bsm[n][k] bf16 hi/lo, row stride `stride` */
__device__ __forceinline__ void load_wt(const float* __restrict__ w, int K, int stride,
                                        char* bh, char* bl, int tid)
{
    for (int i = tid; i < K*128; i += 256) {
        int k = i >> 7, n = i & 127;
        float v = w[i];
        __nv_bfloat16 vh = __float2bfloat16(v);
        float vl = v - __bfloat162float(vh);
        int off = (n*stride + k)*2;
        *(__nv_bfloat16*)(bh + off) = vh;
        *(__nv_bfloat16*)(bl + off) = __float2bfloat16(vl);
    }
}
/* weight [K x 128] row-major -> Bsm[n][k] bf16 hi only */
__device__ __forceinline__ void load_wt_hi(const float* __restrict__ w, int K, int stride,
                                           char* bh, int tid)
{
    for (int i = tid; i < K*128; i += 256) {
        int k = i >> 7, n = i & 127;
        int off = (n*stride + k)*2;
        *(__nv_bfloat16*)(bh + off) = __float2bfloat16(w[i]);
    }
}

/* 1-pass warp GEMM: C = A*B^T, pure bf16 */
template<int KSTEPS, int AST, int BST>
__device__ __forceinline__ void wgemm1(u32 aH, u32 bH,
                                       int m0, int n0, int lane, float C[2][8][4])
{
#pragma unroll
    for (int i = 0; i < 2; i++)
#pragma unroll
        for (int j = 0; j < 8; j++)
#pragma unroll
            for (int k = 0; k < 4; k++) C[i][j][k] = 0.0f;
    int arow = lane & 15, ach = lane >> 4;
    int brow4 = ((lane >> 4) & 1)*8 + (lane & 7);
    int bk4   = ((lane >> 3) & 1)*8;
#pragma unroll
    for (int ks = 0; ks < KSTEPS; ks++) {
        u32 Ah[2][4];
#pragma unroll
        for (int mf = 0; mf < 2; mf++) {
            u32 off = (u32)(((m0 + mf*16 + arow)*AST + ks*16 + ach*8)*2);
            ldmA(Ah[mf], aH + off);
        }
        u32 Bh[8][2];
#pragma unroll
        for (int nfp = 0; nfp < 4; nfp++) {
            u32 off = (u32)(((n0 + nfp*16 + brow4)*BST + ks*16 + bk4)*2);
            ldmB4(&Bh[nfp*2][0], bH + off);
        }
#pragma unroll
        for (int nf = 0; nf < 8; nf++)
#pragma unroll
            for (int mf = 0; mf < 2; mf++)
                mma16816(C[mf][nf], Ah[mf], Bh[nf]);
    }
}

/* 3-pass warp GEMM: C = A*B^T, A split (hi/lo), B split (hi/lo):
 * Ah*Bh + Ah*Bl + Al*Bh (Al*Bl dropped) */
template<int KSTEPS, int AST, int BST>
__device__ __forceinline__ void wgemm3(u32 aH, u32 aL, u32 bH, u32 bL,
                                       int m0, int n0, int lane, float C[2][8][4])
{
#pragma unroll
    for (int i = 0; i < 2; i++)
#pragma unroll
        for (int j = 0; j < 8; j++)
#pragma unroll
            for (int k = 0; k < 4; k++) C[i][j][k] = 0.0f;
    int arow = lane & 15, ach = lane >> 4;
    int brow4 = ((lane >> 4) & 1)*8 + (lane & 7);
    int bk4   = ((lane >> 3) & 1)*8;
#pragma unroll
    for (int ks = 0; ks < KSTEPS; ks++) {
        u32 Ah[2][4], Al[2][4];
#pragma unroll
        for (int mf = 0; mf < 2; mf++) {
            u32 off = (u32)(((m0 + mf*16 + arow)*AST + ks*16 + ach*8)*2);
            ldmA(Ah[mf], aH + off);
            ldmA(Al[mf], aL + off);
        }
        u32 Bh[8][2], Bl[8][2];
#pragma unroll
        for (int nfp = 0; nfp < 4; nfp++) {
            u32 off = (u32)(((n0 + nfp*16 + brow4)*BST + ks*16 + bk4)*2);
            ldmB4(&Bh[nfp*2][0], bH + off);
            ldmB4(&Bl[nfp*2][0], bL + off);
        }
#pragma unroll
        for (int nf = 0; nf < 8; nf++)
#pragma unroll
            for (int mf = 0; mf < 2; mf++) {
                mma16816(C[mf][nf], Ah[mf], Bh[nf]);
                mma16816(C[mf][nf], Ah[mf], Bl[nf]);
                mma16816(C[mf][nf], Al[mf], Bh[nf]);
            }
    }
}

/* ---- scratch ---- */
__device__ float d_x  [NP*DM];
__device__ u32   d_pe [(size_t)NR*64];     /* pe as bf16x2          */
__device__ u32   d_hh [(size_t)NR*64];     /* h as bf16x2           */
__device__ u32   d_lgp[(size_t)NR*64];     /* logits as bf16x2      */
__device__ float d_r  [NP*DM];

__constant__ float c_omega[10] = {
  1.0f, 0.398107170553497250f, 0.158489319246111348f, 0.063095734448019331f,
  0.025118864315095794f, 0.01f, 0.003981071705534973f, 0.001584893192461114f,
  0.000630957344480193f, 0.000251188643150958f };

/* ======================= smem layout offsets ============================ */
#define F1_AH 0
#define F1_AL 18432
#define F1_BH 36864
#define F1_BL 55296
#define F1_B  73728
#define F1_SZ 74240

#define F2_AH 0
#define F2_AL 34816
#define F2_BH 69632
#define F2_BL 104448
#define F2_B  139264
#define F2_SZ 139776

#define K2A_D1H 0
#define K2A_D2H 18432
#define K2A_EH  53248
#define K2A_TH  71680
#define K2A_B1  106496
#define K2A_B2  107008
#define K2A_SZ  107520

#define K2B_G1H 0
#define K2B_G2H 34816
#define K2B_H0  69632
#define K2B_H1  104448
#define K2B_B3  139264
#define K2B_B4  139776
#define K2B_SZ  140288

/* =========================================================================
 * K1 (HMMA): x = features @ fc1_w + fc1_b, 3-pass split-bf16.
 * grid = 256 tiles of 128 rows, K = 64.
 * ========================================================================= */
__global__ void __launch_bounds__(256, 1)
k_fc1m(const float* __restrict__ feat,
       const float* __restrict__ w, const float* __restrict__ bias)
{
    extern __shared__ __align__(128) char smem[];
    int tid = threadIdx.x, lane = tid & 31, wp = tid >> 5;
    int m0 = (wp >> 1) * 32, n0 = (wp & 1) * 64;
    float* bs = (float*)(smem + F1_B);

    load_wt(w, 64, 72, smem + F1_BH, smem + F1_BL, tid);
    if (tid < 128) bs[tid] = bias[tid];

    int r0 = blockIdx.x * 128;
    for (int i = tid; i < 128*64; i += 256) {
        int r = i >> 6, k = i & 63;
        u32 hi, lo;
        float v = feat[(size_t)(r0 + r)*64 + k];
        __nv_bfloat16 vh = __float2bfloat16(v);
        hi = (u32)__bfloat16_as_ushort(vh);
        lo = (u32)__bfloat16_as_ushort(__float2bfloat16(v - __bfloat162float(vh)));
        *(unsigned short*)(smem + F1_AH + (r*72 + k)*2) = (unsigned short)hi;
        *(unsigned short*)(smem + F1_AL + (r*72 + k)*2) = (unsigned short)lo;
    }
    __syncthreads();

    float C[2][8][4];
    wgemm3<4, 72, 72>(smem_u32(smem + F1_AH), smem_u32(smem + F1_AL),
                      smem_u32(smem + F1_BH), smem_u32(smem + F1_BL),
                      m0, n0, lane, C);
#pragma unroll
    for (int mf = 0; mf < 2; mf++) {
        int rA = m0 + mf*16 + (lane >> 2);
        float* oA = d_x + (size_t)(r0 + rA)*128;
        float* oB = d_x + (size_t)(r0 + rA + 8)*128;
#pragma unroll
        for (int nf = 0; nf < 8; nf++) {
            int c = n0 + nf*8 + (lane & 3)*2;
            float ba = bs[c], bb = bs[c+1];
            *(float2*)(oA + c) = make_float2(C[mf][nf][0] + ba, C[mf][nf][1] + bb);
            *(float2*)(oB + c) = make_float2(C[mf][nf][2] + ba, C[mf][nf][3] + bb);
        }
    }
}

/* =========================================================================
 * K2a: per 128-row tile: embed -> G1(relu, 1-pass) -> G2(1-pass)
 *      -> pe(bf16x2) + h(bf16x2).  2 CTAs/SM.
 * ========================================================================= */
__global__ void __launch_bounds__(256, 2)
k2a(const float* __restrict__ xyz, const int* __restrict__ knn_idx,
    const float* __restrict__ kxyz,
    const float* __restrict__ d1w, const float* __restrict__ d1b,
    const float* __restrict__ d2w, const float* __restrict__ d2b)
{
    extern __shared__ __align__(128) char smem[];
    int tid = threadIdx.x, lane = tid & 31, wp = tid >> 5;
    int m0 = (wp >> 1) * 32, n0 = (wp & 1) * 64;
    float* b1s = (float*)(smem + K2A_B1);
    float* b2s = (float*)(smem + K2A_B2);

    load_wt_hi(d1w, 60, 72, smem + K2A_D1H, tid);
    for (int i = tid; i < 128*4; i += 256) {
        int n = i >> 2, k = 60 + (i & 3);
        *(__nv_bfloat16*)(smem + K2A_D1H + (n*72 + k)*2) = __float2bfloat16(0.0f);
    }
    load_wt_hi(d2w, 128, 136, smem + K2A_D2H, tid);
    if (tid < 128) { b1s[tid] = d1b[tid]; b2s[tid] = d2b[tid]; }
    __syncthreads();

    u32 EH = smem_u32(smem + K2A_EH);
    u32 TH = smem_u32(smem + K2A_TH);
    u32 D1H = smem_u32(smem + K2A_D1H);
    u32 D2H = smem_u32(smem + K2A_D2H);

    int er = tid & 127, eh = tid >> 7;   /* embed: row, sin/cos half */

    for (int tile = blockIdx.x; tile < NT; tile += gridDim.x) {
        /* ---- embedding: 256 threads; half sin pairs, half cos pairs ---- */
        {
            int grow = tile*128 + er;
            int p = grow / KNN;
#pragma unroll
            for (int c = 0; c < 3; c++) {
                float g = xyz[p*3 + c] - kxyz[(size_t)grow*3 + c];
#pragma unroll
                for (int jq = 0; jq < 5; jq++) {
                    float a0 = g * c_omega[2*jq], a1 = g * c_omega[2*jq+1];
                    u32 wv;
                    int q;
                    if (eh == 0) { wv = pk(__sinf(a0), __sinf(a1)); q = c*10 + jq; }
                    else         { wv = pk(__cosf(a0), __cosf(a1)); q = c*10 + 5 + jq; }
                    *(u32*)(smem + K2A_EH + er*144 + 4*q) = wv;
                }
            }
            if (eh == 0) {
                *(u32*)(smem + K2A_EH + er*144 + 4*30) = 0u;
                *(u32*)(smem + K2A_EH + er*144 + 4*31) = 0u;
            }
        }
        __syncthreads();

        float C[2][8][4];
        /* ---- G1: t1 = relu(e @ d1 + b1), 1-pass ---- */
        wgemm1<4, 72, 72>(EH, D1H, m0, n0, lane, C);
#pragma unroll
        for (int mf = 0; mf < 2; mf++) {
            int r1 = m0 + mf*16 + (lane >> 2);
#pragma unroll
            for (int nf = 0; nf < 8; nf++) {
                int c = n0 + nf*8 + (lane & 3)*2;
                float ba = b1s[c], bb = b1s[c+1];
                *(u32*)(smem + K2A_TH + r1*272 + 2*c) =
                    pk(fmaxf(C[mf][nf][0] + ba, 0.0f), fmaxf(C[mf][nf][1] + bb, 0.0f));
                *(u32*)(smem + K2A_TH + (r1+8)*272 + 2*c) =
                    pk(fmaxf(C[mf][nf][2] + ba, 0.0f), fmaxf(C[mf][nf][3] + bb, 0.0f));
            }
        }
        __syncthreads();

        /* ---- G2: pe = t1 @ d2 + b2, 1-pass ---- */
        wgemm1<8, 136, 136>(TH, D2H, m0, n0, lane, C);
#pragma unroll
        for (int mf = 0; mf < 2; mf++) {
            int rA = m0 + mf*16 + (lane >> 2), rB = rA + 8;
            int gA = tile*128 + rA, gB = tile*128 + rB;
            int pA = gA / KNN, pB = gB / KNN;
            int iA = ((pA >> 14) << 14) + knn_idx[gA];
            int iB = ((pB >> 14) << 14) + knn_idx[gB];
            const float* xpA = d_x + (size_t)pA*128;
            const float* xgA = d_x + (size_t)iA*128;
            const float* xpB = d_x + (size_t)pB*128;
            const float* xgB = d_x + (size_t)iB*128;
            u32* peA = d_pe + (size_t)gA*64;
            u32* peB = d_pe + (size_t)gB*64;
            u32* hhA = d_hh + (size_t)gA*64;
            u32* hhB = d_hh + (size_t)gB*64;
#pragma unroll
            for (int nf = 0; nf < 8; nf++) {
                int c = n0 + nf*8 + (lane & 3)*2;
                float ba = b2s[c], bb = b2s[c+1];
                float2 xa = *(const float2*)(xpA + c), ga = *(const float2*)(xgA + c);
                float2 xb = *(const float2*)(xpB + c), gb = *(const float2*)(xgB + c);
                float p0 = C[mf][nf][0] + ba, p1 = C[mf][nf][1] + bb;
                peA[c >> 1] = pk(p0, p1);
                hhA[c >> 1] = pk(xa.x - ga.x + p0, xa.y - ga.y + p1);
                float p2 = C[mf][nf][2] + ba, p3 = C[mf][nf][3] + bb;
                peB[c >> 1] = pk(p2, p3);
                hhB[c >> 1] = pk(xb.x - gb.x + p2, xb.y - gb.y + p3);
            }
        }
        __syncthreads();
    }
}

/* ---- cp.async prefetch of one h tile (32 KB) into smem buffer ---- */
__device__ __forceinline__ void prefetch_h(char* dst, int tile, int tid)
{
    const u32* src = d_hh + (size_t)tile * 8192;
#pragma unroll
    for (int j = 0; j < 8; j++) {
        int wi = tid + j*256;                       /* 0..2047 16B chunks */
        u32 daddr = smem_u32(dst + (wi >> 4)*272 + (wi & 15)*16);
        asm volatile("cp.async.ca.shared.global [%0], [%1], 16;"
                     :: "r"(daddr), "l"(src + wi*4) : "memory");
    }
    asm volatile("cp.async.commit_group;" ::: "memory");
}

/* =========================================================================
 * K2b: per 128-row tile: h -> G3(relu, 1-pass) -> G4(1-pass) -> logits bf16
 * double-buffered cp.async h prefetch.
 * ========================================================================= */
__global__ void __launch_bounds__(256, 1)
k2b(const float* __restrict__ g1w, const float* __restrict__ g1b,
    const float* __restrict__ g2w, const float* __restrict__ g2b)
{
    extern __shared__ __align__(128) char smem[];
    int tid = threadIdx.x, lane = tid & 31, wp = tid >> 5;
    int m0 = (wp >> 1) * 32, n0 = (wp & 1) * 64;
    float* b3s = (float*)(smem + K2B_B3);
    float* b4s = (float*)(smem + K2B_B4);

    load_wt_hi(g1w, 128, 136, smem + K2B_G1H, tid);
    load_wt_hi(g2w, 128, 136, smem + K2B_G2H, tid);
    if (tid < 128) { b3s[tid] = g1b[tid]; b4s[tid] = g2b[tid]; }

    u32 G1H = smem_u32(smem + K2B_G1H);
    u32 G2H = smem_u32(smem + K2B_G2H);
    char* hbuf[2] = { smem + K2B_H0, smem + K2B_H1 };
    u32 hadr[2] = { smem_u32(smem + K2B_H0), smem_u32(smem + K2B_H1) };

    int tile = blockIdx.x;
    if (tile < NT) prefetch_h(hbuf[0], tile, tid);
    __syncthreads();
    int cur = 0;

    for (; tile < NT; tile += gridDim.x, cur ^= 1) {
        asm volatile("cp.async.wait_group 0;" ::: "memory");
        __syncthreads();
        int nxt = tile + gridDim.x;
        if (nxt < NT) prefetch_h(hbuf[cur ^ 1], nxt, tid);

        float C[2][8][4];
        /* ---- G3: t = relu(h @ g1 + b3), 1-pass ---- */
        wgemm1<8, 136, 136>(hadr[cur], G1H, m0, n0, lane, C);
        __syncthreads();   /* all warps done reading h before overwrite */
#pragma unroll
        for (int mf = 0; mf < 2; mf++) {
            int r1 = m0 + mf*16 + (lane >> 2);
#pragma unroll
            for (int nf = 0; nf < 8; nf++) {
                int c = n0 + nf*8 + (lane & 3)*2;
                float ba = b3s[c], bb = b3s[c+1];
                *(u32*)(hbuf[cur] + r1*272 + 2*c) =
                    pk(fmaxf(C[mf][nf][0] + ba, 0.0f), fmaxf(C[mf][nf][1] + bb, 0.0f));
                *(u32*)(hbuf[cur] + (r1+8)*272 + 2*c) =
                    pk(fmaxf(C[mf][nf][2] + ba, 0.0f), fmaxf(C[mf][nf][3] + bb, 0.0f));
            }
        }
        __syncthreads();

        /* ---- G4: logits = t @ g2 + b4, 1-pass -> bf16x2 gmem ---- */
        wgemm1<8, 136, 136>(hadr[cur], G2H, m0, n0, lane, C);
#pragma unroll
        for (int mf = 0; mf < 2; mf++) {
            int rA = m0 + mf*16 + (lane >> 2), rB = rA + 8;
            u32* lgA = d_lgp + (size_t)(tile*128 + rA)*64;
            u32* lgB = d_lgp + (size_t)(tile*128 + rB)*64;
#pragma unroll
            for (int nf = 0; nf < 8; nf++) {
                int c = n0 + nf*8 + (lane & 3)*2;
                float ba = b4s[c], bb = b4s[c+1];
                lgA[c >> 1] = pk(C[mf][nf][0] + ba, C[mf][nf][1] + bb);
                lgB[c >> 1] = pk(C[mf][nf][2] + ba, C[mf][nf][3] + bb);
            }
        }
        __syncthreads();   /* all warps done reading t before next tile reuse */
    }
}

/* =========================================================================
 * K3: softmax over k + aggregate. block = point p, thread = channel f.
 * ========================================================================= */
__global__ void k_soft(const int* __restrict__ knn_idx,
                       float* __restrict__ out_attn)
{
    int p = blockIdx.x, f = threadIdx.x;
    int base = p * KNN, bb = p >> 14;
    const float scale = 0.0883883476483184406f;   /* 1/sqrt(128) */
    float acc[KNN];
    float m = -1e30f;
#pragma unroll
    for (int k = 0; k < KNN; k++) {
        u32 wv = d_lgp[(size_t)(base + k)*64 + (f >> 1)];
        acc[k] = ((f & 1) ? bf_hi(wv) : bf_lo(wv)) * scale;
        m = fmaxf(m, acc[k]);
    }
    float s = 0.0f;
#pragma unroll
    for (int k = 0; k < KNN; k++) { acc[k] = __expf(acc[k] - m); s += acc[k]; }
    float inv = 1.0f / s;
    float rv = 0.0f;
#pragma unroll
    for (int k = 0; k < KNN; k++) {
        float a = acc[k] * inv;
        int grow = base + k;
        out_attn[(size_t)grow*128 + f] = a;
        int gi = (bb << 14) + knn_idx[grow];
        u32 pw = d_pe[(size_t)grow*64 + (f >> 1)];
        float pe = (f & 1) ? bf_hi(pw) : bf_lo(pw);
        rv = fmaf(a, d_x[(size_t)gi*128 + f] + pe, rv);
    }
    d_r[p*128 + f] = rv;
}

/* =========================================================================
 * K4 (HMMA): res = r @ fc2 + fc2_b + x, 3-pass split-bf16.
 * ========================================================================= */
__global__ void __launch_bounds__(256, 1)
k_fc2m(const float* __restrict__ w, const float* __restrict__ bias,
       float* __restrict__ out_res)
{
    extern __shared__ __align__(128) char smem[];
    int tid = threadIdx.x, lane = tid & 31, wp = tid >> 5;
    int m0 = (wp >> 1) * 32, n0 = (wp & 1) * 64;
    float* bs = (float*)(smem + F2_B);

    load_wt(w, 128, 136, smem + F2_BH, smem + F2_BL, tid);
    if (tid < 128) bs[tid] = bias[tid];

    int r0 = blockIdx.x * 128;
    for (int i = tid; i < 128*128; i += 256) {
        int r = i >> 7, k = i & 127;
        float v = d_r[(size_t)(r0 + r)*128 + k];
        __nv_bfloat16 vh = __float2bfloat16(v);
        *(unsigned short*)(smem + F2_AH + (r*136 + k)*2) = __bfloat16_as_ushort(vh);
        *(unsigned short*)(smem + F2_AL + (r*136 + k)*2) =
            __bfloat16_as_ushort(__float2bfloat16(v - __bfloat162float(vh)));
    }
    __syncthreads();

    float C[2][8][4];
    wgemm3<8, 136, 136>(smem_u32(smem + F2_AH), smem_u32(smem + F2_AL),
                        smem_u32(smem + F2_BH), smem_u32(smem + F2_BL),
                        m0, n0, lane, C);
#pragma unroll
    for (int mf = 0; mf < 2; mf++) {
        int rA = m0 + mf*16 + (lane >> 2);
        const float* xA = d_x + (size_t)(r0 + rA)*128;
        const float* xB = d_x + (size_t)(r0 + rA + 8)*128;
        float* oA = out_res + (size_t)(r0 + rA)*128;
        float* oB = out_res + (size_t)(r0 + rA + 8)*128;
#pragma unroll
        for (int nf = 0; nf < 8; nf++) {
            int c = n0 + nf*8 + (lane & 3)*2;
            float ba = bs[c], bb = bs[c+1];
            float2 xa = *(const float2*)(xA + c);
            float2 xb = *(const float2*)(xB + c);
            *(float2*)(oA + c) = make_float2(C[mf][nf][0] + ba + xa.x,
                                             C[mf][nf][1] + bb + xa.y);
            *(float2*)(oB + c) = make_float2(C[mf][nf][2] + ba + xb.x,
                                             C[mf][nf][3] + bb + xb.y);
        }
    }
}

/* ========================================================================= */
extern "C" void kernel_launch(void* const* d_in, const int* in_sizes, int n_in,
                              void* d_out, int out_size)
{
    const float* feat = (const float*)d_in[0];
    const float* xyz  = (const float*)d_in[1];
    const int*   knn  = (const int*  )d_in[2];
    const float* kxyz = (const float*)d_in[3];
    const float* fc1w = (const float*)d_in[4];
    const float* fc1b = (const float*)d_in[5];
    const float* fc2w = (const float*)d_in[6];
    const float* fc2b = (const float*)d_in[7];
    const float* d1w  = (const float*)d_in[8];
    const float* d1b  = (const float*)d_in[9];
    const float* d2w  = (const float*)d_in[10];
    const float* d2b  = (const float*)d_in[11];
    const float* g1w  = (const float*)d_in[12];
    const float* g1b  = (const float*)d_in[13];
    const float* g2w  = (const float*)d_in[14];
    const float* g2b  = (const float*)d_in[15];
    float* out = (float*)d_out;

    int sms = 148;
    cudaDeviceGetAttribute(&sms, cudaDevAttrMultiProcessorCount, 0);

    cudaFuncSetAttribute(k_fc1m, cudaFuncAttributeMaxDynamicSharedMemorySize, F1_SZ);
    cudaFuncSetAttribute(k2a,    cudaFuncAttributeMaxDynamicSharedMemorySize, K2A_SZ);
    cudaFuncSetAttribute(k2b,    cudaFuncAttributeMaxDynamicSharedMemorySize, K2B_SZ);
    cudaFuncSetAttribute(k_fc2m, cudaFuncAttributeMaxDynamicSharedMemorySize, F2_SZ);

    k_fc1m<<<NT2,   256, F1_SZ >>>(feat, fc1w, fc1b);
    k2a   <<<2*sms, 256, K2A_SZ>>>(xyz, knn, kxyz, d1w, d1b, d2w, d2b);
    k2b   <<<sms,   256, K2B_SZ>>>(g1w, g1b, g2w, g2b);
    k_soft<<<NP,    128        >>>(knn, out + RES_ELEMS);
    k_fc2m<<<NT2,   256, F2_SZ >>>(fc2w, fc2b, out);
}

// round 15
// speedup vs baseline: 7.6840x; 1.0248x over previous
#include <cuda_runtime.h>
#include <cuda_bf16.h>
#include <cstdint>

#define BATCH 2
#define NPTS  16384
#define KNN   24
#define DM    128
#define NP    (BATCH*NPTS)
#define NR    (NP*KNN)
#define RES_ELEMS (NP*DM)
#define NT    (NR/128)          /* 6144 tiles of 128 rows */
#define NT2   (NP/128)          /* 256 tiles for fc kernels */

typedef unsigned long long u64;
typedef unsigned int       u32;

/* ===================== generic-PTX MMA helpers ========================== */
__device__ __forceinline__ u32 smem_u32(const void* p){
    u32 a; asm("{ .reg .u64 t; cvta.to.shared.u64 t, %1; cvt.u32.u64 %0, t; }"
               : "=r"(a) : "l"(p));
    return a;
}
__device__ __forceinline__ void ldmA(u32* a, u32 addr){
    asm volatile("ldmatrix.sync.aligned.m8n8.x4.shared.b16 {%0,%1,%2,%3}, [%4];"
        : "=r"(a[0]), "=r"(a[1]), "=r"(a[2]), "=r"(a[3]) : "r"(addr));
}
__device__ __forceinline__ void ldmB4(u32* b, u32 addr){
    asm volatile("ldmatrix.sync.aligned.m8n8.x4.shared.b16 {%0,%1,%2,%3}, [%4];"
        : "=r"(b[0]), "=r"(b[1]), "=r"(b[2]), "=r"(b[3]) : "r"(addr));
}
__device__ __forceinline__ void mma16816(float* c, const u32* a, const u32* b){
    asm volatile("mma.sync.aligned.m16n8k16.row.col.f32.bf16.bf16.f32 "
        "{%0,%1,%2,%3}, {%4,%5,%6,%7}, {%8,%9}, {%0,%1,%2,%3};"
        : "+f"(c[0]), "+f"(c[1]), "+f"(c[2]), "+f"(c[3])
        : "r"(a[0]), "r"(a[1]), "r"(a[2]), "r"(a[3]), "r"(b[0]), "r"(b[1]));
}

/* pack two fp32 into bf16x2 word: single sm_90+ instruction, RN rounding */
__device__ __forceinline__ u32 pk(float a, float b){
    u32 r; asm("cvt.rn.bf16x2.f32 %0, %1, %2;" : "=r"(r) : "f"(b), "f"(a));
    return r;
}
__device__ __forceinline__ float bf_lo(u32 w){
    return __bfloat162float(__ushort_as_bfloat16((unsigned short)(w & 0xFFFF)));
}
__device__ __forceinline__ float bf_hi(u32 w){
    return __bfloat162float(__ushort_as_bfloat16((unsigned short)(w >> 16)));
}

/* Taylor sin/cos for |x| <= ~1.2 (abs err < 1e-5, far under bf16 quantum) */
__device__ __forceinline__ float sinp(float a, float x2){
    float p = fmaf(x2, -1.984126984e-4f, 8.333333333e-3f);   /* -1/5040, 1/120 */
    p = fmaf(x2, p, -1.666666667e-1f);                        /* -1/6 */
    return fmaf(a*x2, p, a);
}
__device__ __forceinline__ float cosp(float x2){
    float p = fmaf(x2, 2.480158730e-5f, -1.388888889e-3f);    /* 1/40320, -1/720 */
    p = fmaf(x2, p, 4.166666667e-2f);                         /* 1/24 */
    p = fmaf(x2, p, -0.5f);
    return fmaf(x2, p, 1.0f);
}

/* weight [K x 128] row-major -> Bsm[n][k] bf16 hi/lo, row stride `stride` */
__device__ __forceinline__ void load_wt(const float* __restrict__ w, int K, int stride,
                                        char* bh, char* bl, int tid)
{
    for (int i = tid; i < K*128; i += 256) {
        int k = i >> 7, n = i & 127;
        float v = w[i];
        __nv_bfloat16 vh = __float2bfloat16(v);
        float vl = v - __bfloat162float(vh);
        int off = (n*stride + k)*2;
        *(__nv_bfloat16*)(bh + off) = vh;
        *(__nv_bfloat16*)(bl + off) = __float2bfloat16(vl);
    }
}
/* weight [K x 128] row-major -> Bsm[n][k] bf16 hi only */
__device__ __forceinline__ void load_wt_hi(const float* __restrict__ w, int K, int stride,
                                           char* bh, int tid)
{
    for (int i = tid; i < K*128; i += 256) {
        int k = i >> 7, n = i & 127;
        int off = (n*stride + k)*2;
        *(__nv_bfloat16*)(bh + off) = __float2bfloat16(w[i]);
    }
}

/* 1-pass warp GEMM: C = A*B^T, pure bf16 */
template<int KSTEPS, int AST, int BST>
__device__ __forceinline__ void wgemm1(u32 aH, u32 bH,
                                       int m0, int n0, int lane, float C[2][8][4])
{
#pragma unroll
    for (int i = 0; i < 2; i++)
#pragma unroll
        for (int j = 0; j < 8; j++)
#pragma unroll
            for (int k = 0; k < 4; k++) C[i][j][k] = 0.0f;
    int arow = lane & 15, ach = lane >> 4;
    int brow4 = ((lane >> 4) & 1)*8 + (lane & 7);
    int bk4   = ((lane >> 3) & 1)*8;
#pragma unroll
    for (int ks = 0; ks < KSTEPS; ks++) {
        u32 Ah[2][4];
#pragma unroll
        for (int mf = 0; mf < 2; mf++) {
            u32 off = (u32)(((m0 + mf*16 + arow)*AST + ks*16 + ach*8)*2);
            ldmA(Ah[mf], aH + off);
        }
        u32 Bh[8][2];
#pragma unroll
        for (int nfp = 0; nfp < 4; nfp++) {
            u32 off = (u32)(((n0 + nfp*16 + brow4)*BST + ks*16 + bk4)*2);
            ldmB4(&Bh[nfp*2][0], bH + off);
        }
#pragma unroll
        for (int nf = 0; nf < 8; nf++)
#pragma unroll
            for (int mf = 0; mf < 2; mf++)
                mma16816(C[mf][nf], Ah[mf], Bh[nf]);
    }
}

/* 3-pass warp GEMM: C = A*B^T, A split (hi/lo), B split (hi/lo):
 * Ah*Bh + Ah*Bl + Al*Bh (Al*Bl dropped) */
template<int KSTEPS, int AST, int BST>
__device__ __forceinline__ void wgemm3(u32 aH, u32 aL, u32 bH, u32 bL,
                                       int m0, int n0, int lane, float C[2][8][4])
{
#pragma unroll
    for (int i = 0; i < 2; i++)
#pragma unroll
        for (int j = 0; j < 8; j++)
#pragma unroll
            for (int k = 0; k < 4; k++) C[i][j][k] = 0.0f;
    int arow = lane & 15, ach = lane >> 4;
    int brow4 = ((lane >> 4) & 1)*8 + (lane & 7);
    int bk4   = ((lane >> 3) & 1)*8;
#pragma unroll
    for (int ks = 0; ks < KSTEPS; ks++) {
        u32 Ah[2][4], Al[2][4];
#pragma unroll
        for (int mf = 0; mf < 2; mf++) {
            u32 off = (u32)(((m0 + mf*16 + arow)*AST + ks*16 + ach*8)*2);
            ldmA(Ah[mf], aH + off);
            ldmA(Al[mf], aL + off);
        }
        u32 Bh[8][2], Bl[8][2];
#pragma unroll
        for (int nfp = 0; nfp < 4; nfp++) {
            u32 off = (u32)(((n0 + nfp*16 + brow4)*BST + ks*16 + bk4)*2);
            ldmB4(&Bh[nfp*2][0], bH + off);
            ldmB4(&Bl[nfp*2][0], bL + off);
        }
#pragma unroll
        for (int nf = 0; nf < 8; nf++)
#pragma unroll
            for (int mf = 0; mf < 2; mf++) {
                mma16816(C[mf][nf], Ah[mf], Bh[nf]);
                mma16816(C[mf][nf], Ah[mf], Bl[nf]);
                mma16816(C[mf][nf], Al[mf], Bh[nf]);
            }
    }
}

/* ---- scratch ---- */
__device__ float d_x  [NP*DM];
__device__ u32   d_pe [(size_t)NR*64];     /* pe as bf16x2          */
__device__ u32   d_lgp[(size_t)NR*64];     /* logits as bf16x2      */
__device__ float d_r  [NP*DM];

__constant__ float c_omega[10] = {
  1.0f, 0.398107170553497250f, 0.158489319246111348f, 0.063095734448019331f,
  0.025118864315095794f, 0.01f, 0.003981071705534973f, 0.001584893192461114f,
  0.000630957344480193f, 0.000251188643150958f };

/* ======================= smem layout offsets ============================ */
#define F1_AH 0
#define F1_AL 18432
#define F1_BH 36864
#define F1_BL 55296
#define F1_B  73728
#define F1_SZ 74240

#define F2_AH 0
#define F2_AL 34816
#define F2_BH 69632
#define F2_BL 104448
#define F2_B  139264
#define F2_SZ 139776

#define K2_D1H 0        /* 128x72  bf16 = 18432 */
#define K2_D2H 18432    /* 128x136 bf16 = 34816 */
#define K2_G1H 53248
#define K2_G2H 88064
#define K2_EH  122880   /* E: 128 x 144B        */
#define K2_TH  141312   /* t1/h/t: 128 x 272B   */
#define K2_B1  176128
#define K2_B2  176640
#define K2_B3  177152
#define K2_B4  177664
#define K2_SZ  178176

/* =========================================================================
 * K1 (HMMA): x = features @ fc1_w + fc1_b, 3-pass split-bf16.
 * ========================================================================= */
__global__ void __launch_bounds__(256, 1)
k_fc1m(const float* __restrict__ feat,
       const float* __restrict__ w, const float* __restrict__ bias)
{
    extern __shared__ __align__(128) char smem[];
    int tid = threadIdx.x, lane = tid & 31, wp = tid >> 5;
    int m0 = (wp >> 1) * 32, n0 = (wp & 1) * 64;
    float* bs = (float*)(smem + F1_B);

    load_wt(w, 64, 72, smem + F1_BH, smem + F1_BL, tid);
    if (tid < 128) bs[tid] = bias[tid];

    int r0 = blockIdx.x * 128;
    for (int i = tid; i < 128*64; i += 256) {
        int r = i >> 6, k = i & 63;
        float v = feat[(size_t)(r0 + r)*64 + k];
        __nv_bfloat16 vh = __float2bfloat16(v);
        *(unsigned short*)(smem + F1_AH + (r*72 + k)*2) = __bfloat16_as_ushort(vh);
        *(unsigned short*)(smem + F1_AL + (r*72 + k)*2) =
            __bfloat16_as_ushort(__float2bfloat16(v - __bfloat162float(vh)));
    }
    __syncthreads();

    float C[2][8][4];
    wgemm3<4, 72, 72>(smem_u32(smem + F1_AH), smem_u32(smem + F1_AL),
                      smem_u32(smem + F1_BH), smem_u32(smem + F1_BL),
                      m0, n0, lane, C);
#pragma unroll
    for (int mf = 0; mf < 2; mf++) {
        int rA = m0 + mf*16 + (lane >> 2);
        float* oA = d_x + (size_t)(r0 + rA)*128;
        float* oB = d_x + (size_t)(r0 + rA + 8)*128;
#pragma unroll
        for (int nf = 0; nf < 8; nf++) {
            int c = n0 + nf*8 + (lane & 3)*2;
            float ba = bs[c], bb = bs[c+1];
            *(float2*)(oA + c) = make_float2(C[mf][nf][0] + ba, C[mf][nf][1] + bb);
            *(float2*)(oB + c) = make_float2(C[mf][nf][2] + ba, C[mf][nf][3] + bb);
        }
    }
}

/* =========================================================================
 * K2 (fused): per 128-row tile:
 *   embed(poly) -> G1(relu) -> G2 -> pe(bf16 out) + h(smem)
 *   -> G3(relu) -> G4 -> logits(bf16 out).   1 CTA/SM, 172 KB smem.
 * ========================================================================= */
__global__ void __launch_bounds__(256, 1)
k2(const float* __restrict__ xyz, const int* __restrict__ knn_idx,
   const float* __restrict__ kxyz,
   const float* __restrict__ d1w, const float* __restrict__ d1b,
   const float* __restrict__ d2w, const float* __restrict__ d2b,
   const float* __restrict__ g1w, const float* __restrict__ g1b,
   const float* __restrict__ g2w, const float* __restrict__ g2b)
{
    extern __shared__ __align__(128) char smem[];
    int tid = threadIdx.x, lane = tid & 31, wp = tid >> 5;
    int m0 = (wp >> 1) * 32, n0 = (wp & 1) * 64;
    float* b1s = (float*)(smem + K2_B1);
    float* b2s = (float*)(smem + K2_B2);
    float* b3s = (float*)(smem + K2_B3);
    float* b4s = (float*)(smem + K2_B4);

    load_wt_hi(d1w, 60, 72, smem + K2_D1H, tid);
    for (int i = tid; i < 128*4; i += 256) {
        int n = i >> 2, k = 60 + (i & 3);
        *(__nv_bfloat16*)(smem + K2_D1H + (n*72 + k)*2) = __float2bfloat16(0.0f);
    }
    load_wt_hi(d2w, 128, 136, smem + K2_D2H, tid);
    load_wt_hi(g1w, 128, 136, smem + K2_G1H, tid);
    load_wt_hi(g2w, 128, 136, smem + K2_G2H, tid);
    if (tid < 128) {
        b1s[tid] = d1b[tid]; b2s[tid] = d2b[tid];
        b3s[tid] = g1b[tid]; b4s[tid] = g2b[tid];
    }
    __syncthreads();

    u32 EH  = smem_u32(smem + K2_EH);
    u32 TH  = smem_u32(smem + K2_TH);
    u32 D1H = smem_u32(smem + K2_D1H);
    u32 D2H = smem_u32(smem + K2_D2H);
    u32 G1H = smem_u32(smem + K2_G1H);
    u32 G2H = smem_u32(smem + K2_G2H);

    int er = tid & 127, eh = tid >> 7;   /* embed: row, sin/cos half */

    for (int tile = blockIdx.x; tile < NT; tile += gridDim.x) {
        /* ---- embedding: MUFU for j=0,1; Taylor poly for j=2..9 ---- */
        {
            int grow = tile*128 + er;
            int p = grow / KNN;
            int qb0 = eh ? 5 : 0;
#pragma unroll
            for (int c = 0; c < 3; c++) {
                float g = xyz[p*3 + c] - kxyz[(size_t)grow*3 + c];
                float a1 = g * c_omega[1];
                u32 w0 = eh ? pk(__cosf(g), __cosf(a1))
                            : pk(__sinf(g), __sinf(a1));
                *(u32*)(smem + K2_EH + er*144 + 4*(c*10 + qb0)) = w0;
#pragma unroll
                for (int jq = 1; jq < 5; jq++) {
                    float x0 = g * c_omega[2*jq], x1 = g * c_omega[2*jq+1];
                    float s0 = x0*x0, s1 = x1*x1;
                    u32 wv = eh ? pk(cosp(s0), cosp(s1))
                                : pk(sinp(x0, s0), sinp(x1, s1));
                    *(u32*)(smem + K2_EH + er*144 + 4*(c*10 + qb0 + jq)) = wv;
                }
            }
            if (eh == 0) {
                *(u32*)(smem + K2_EH + er*144 + 4*30) = 0u;
                *(u32*)(smem + K2_EH + er*144 + 4*31) = 0u;
            }
        }
        __syncthreads();                       /* E ready */

        float C[2][8][4];
        /* ---- G1: t1 = relu(e @ d1 + b1) -> TH ---- */
        wgemm1<4, 72, 72>(EH, D1H, m0, n0, lane, C);
#pragma unroll
        for (int mf = 0; mf < 2; mf++) {
            int r1 = m0 + mf*16 + (lane >> 2);
#pragma unroll
            for (int nf = 0; nf < 8; nf++) {
                int c = n0 + nf*8 + (lane & 3)*2;
                float ba = b1s[c], bb = b1s[c+1];
                *(u32*)(smem + K2_TH + r1*272 + 2*c) =
                    pk(fmaxf(C[mf][nf][0] + ba, 0.0f), fmaxf(C[mf][nf][1] + bb, 0.0f));
                *(u32*)(smem + K2_TH + (r1+8)*272 + 2*c) =
                    pk(fmaxf(C[mf][nf][2] + ba, 0.0f), fmaxf(C[mf][nf][3] + bb, 0.0f));
            }
        }
        __syncthreads();                       /* t1 ready */

        /* ---- G2: pe = t1 @ d2 + b2 ---- */
        wgemm1<8, 136, 136>(TH, D2H, m0, n0, lane, C);
        __syncthreads();                       /* all t1 reads done */

        /* ---- ep2: pe -> gmem (bf16), h = x[p]-x[gi]+pe -> TH ---- */
#pragma unroll
        for (int mf = 0; mf < 2; mf++) {
            int rA = m0 + mf*16 + (lane >> 2), rB = rA + 8;
            int gA = tile*128 + rA, gB = tile*128 + rB;
            int pA = gA / KNN, pB = gB / KNN;
            int iA = ((pA >> 14) << 14) + knn_idx[gA];
            int iB = ((pB >> 14) << 14) + knn_idx[gB];
            const float* xpA = d_x + (size_t)pA*128;
            const float* xgA = d_x + (size_t)iA*128;
            const float* xpB = d_x + (size_t)pB*128;
            const float* xgB = d_x + (size_t)iB*128;
            u32* peA = d_pe + (size_t)gA*64;
            u32* peB = d_pe + (size_t)gB*64;
#pragma unroll
            for (int nf = 0; nf < 8; nf++) {
                int c = n0 + nf*8 + (lane & 3)*2;
                float ba = b2s[c], bb = b2s[c+1];
                float2 xa = *(const float2*)(xpA + c), ga = *(const float2*)(xgA + c);
                float2 xb = *(const float2*)(xpB + c), gb = *(const float2*)(xgB + c);
                float p0 = C[mf][nf][0] + ba, p1 = C[mf][nf][1] + bb;
                peA[c >> 1] = pk(p0, p1);
                *(u32*)(smem + K2_TH + rA*272 + 2*c) =
                    pk(xa.x - ga.x + p0, xa.y - ga.y + p1);
                float p2 = C[mf][nf][2] + ba, p3 = C[mf][nf][3] + bb;
                peB[c >> 1] = pk(p2, p3);
                *(u32*)(smem + K2_TH + rB*272 + 2*c) =
                    pk(xb.x - gb.x + p2, xb.y - gb.y + p3);
            }
        }
        __syncthreads();                       /* h ready */

        /* ---- G3: t = relu(h @ g1 + b3) ---- */
        wgemm1<8, 136, 136>(TH, G1H, m0, n0, lane, C);
        __syncthreads();                       /* all h reads done */
#pragma unroll
        for (int mf = 0; mf < 2; mf++) {
            int r1 = m0 + mf*16 + (lane >> 2);
#pragma unroll
            for (int nf = 0; nf < 8; nf++) {
                int c = n0 + nf*8 + (lane & 3)*2;
                float ba = b3s[c], bb = b3s[c+1];
                *(u32*)(smem + K2_TH + r1*272 + 2*c) =
                    pk(fmaxf(C[mf][nf][0] + ba, 0.0f), fmaxf(C[mf][nf][1] + bb, 0.0f));
                *(u32*)(smem + K2_TH + (r1+8)*272 + 2*c) =
                    pk(fmaxf(C[mf][nf][2] + ba, 0.0f), fmaxf(C[mf][nf][3] + bb, 0.0f));
            }
        }
        __syncthreads();                       /* t ready */

        /* ---- G4: logits = t @ g2 + b4 -> bf16x2 gmem ---- */
        wgemm1<8, 136, 136>(TH, G2H, m0, n0, lane, C);
#pragma unroll
        for (int mf = 0; mf < 2; mf++) {
            int rA = m0 + mf*16 + (lane >> 2), rB = rA + 8;
            u32* lgA = d_lgp + (size_t)(tile*128 + rA)*64;
            u32* lgB = d_lgp + (size_t)(tile*128 + rB)*64;
#pragma unroll
            for (int nf = 0; nf < 8; nf++) {
                int c = n0 + nf*8 + (lane & 3)*2;
                float ba = b4s[c], bb = b4s[c+1];
                lgA[c >> 1] = pk(C[mf][nf][0] + ba, C[mf][nf][1] + bb);
                lgB[c >> 1] = pk(C[mf][nf][2] + ba, C[mf][nf][3] + bb);
            }
        }
        /* next write to TH happens after the embed __syncthreads */
    }
}

/* =========================================================================
 * K3: softmax over k + aggregate. block = point p, thread = channel f.
 * ========================================================================= */
__global__ void k_soft(const int* __restrict__ knn_idx,
                       float* __restrict__ out_attn)
{
    int p = blockIdx.x, f = threadIdx.x;
    int base = p * KNN, bb = p >> 14;
    const float scale = 0.0883883476483184406f;   /* 1/sqrt(128) */
    float acc[KNN];
    float m = -1e30f;
#pragma unroll
    for (int k = 0; k < KNN; k++) {
        u32 wv = d_lgp[(size_t)(base + k)*64 + (f >> 1)];
        acc[k] = ((f & 1) ? bf_hi(wv) : bf_lo(wv)) * scale;
        m = fmaxf(m, acc[k]);
    }
    float s = 0.0f;
#pragma unroll
    for (int k = 0; k < KNN; k++) { acc[k] = __expf(acc[k] - m); s += acc[k]; }
    float inv = 1.0f / s;
    float rv = 0.0f;
#pragma unroll
    for (int k = 0; k < KNN; k++) {
        float a = acc[k] * inv;
        int grow = base + k;
        out_attn[(size_t)grow*128 + f] = a;
        int gi = (bb << 14) + knn_idx[grow];
        u32 pw = d_pe[(size_t)grow*64 + (f >> 1)];
        float pe = (f & 1) ? bf_hi(pw) : bf_lo(pw);
        rv = fmaf(a, d_x[(size_t)gi*128 + f] + pe, rv);
    }
    d_r[p*128 + f] = rv;
}

/* =========================================================================
 * K4 (HMMA): res = r @ fc2 + fc2_b + x, 3-pass split-bf16.
 * ========================================================================= */
__global__ void __launch_bounds__(256, 1)
k_fc2m(const float* __restrict__ w, const float* __restrict__ bias,
       float* __restrict__ out_res)
{
    extern __shared__ __align__(128) char smem[];
    int tid = threadIdx.x, lane = tid & 31, wp = tid >> 5;
    int m0 = (wp >> 1) * 32, n0 = (wp & 1) * 64;
    float* bs = (float*)(smem + F2_B);

    load_wt(w, 128, 136, smem + F2_BH, smem + F2_BL, tid);
    if (tid < 128) bs[tid] = bias[tid];

    int r0 = blockIdx.x * 128;
    for (int i = tid; i < 128*128; i += 256) {
        int r = i >> 7, k = i & 127;
        float v = d_r[(size_t)(r0 + r)*128 + k];
        __nv_bfloat16 vh = __float2bfloat16(v);
        *(unsigned short*)(smem + F2_AH + (r*136 + k)*2) = __bfloat16_as_ushort(vh);
        *(unsigned short*)(smem + F2_AL + (r*136 + k)*2) =
            __bfloat16_as_ushort(__float2bfloat16(v - __bfloat162float(vh)));
    }
    __syncthreads();

    float C[2][8][4];
    wgemm3<8, 136, 136>(smem_u32(smem + F2_AH), smem_u32(smem + F2_AL),
                        smem_u32(smem + F2_BH), smem_u32(smem + F2_BL),
                        m0, n0, lane, C);
#pragma unroll
    for (int mf = 0; mf < 2; mf++) {
        int rA = m0 + mf*16 + (lane >> 2);
        const float* xA = d_x + (size_t)(r0 + rA)*128;
        const float* xB = d_x + (size_t)(r0 + rA + 8)*128;
        float* oA = out_res + (size_t)(r0 + rA)*128;
        float* oB = out_res + (size_t)(r0 + rA + 8)*128;
#pragma unroll
        for (int nf = 0; nf < 8; nf++) {
            int c = n0 + nf*8 + (lane & 3)*2;
            float ba = bs[c], bb = bs[c+1];
            float2 xa = *(const float2*)(xA + c);
            float2 xb = *(const float2*)(xB + c);
            *(float2*)(oA + c) = make_float2(C[mf][nf][0] + ba + xa.x,
                                             C[mf][nf][1] + bb + xa.y);
            *(float2*)(oB + c) = make_float2(C[mf][nf][2] + ba + xb.x,
                                             C[mf][nf][3] + bb + xb.y);
        }
    }
}

/* ========================================================================= */
extern "C" void kernel_launch(void* const* d_in, const int* in_sizes, int n_in,
                              void* d_out, int out_size)
{
    const float* feat = (const float*)d_in[0];
    const float* xyz  = (const float*)d_in[1];
    const int*   knn  = (const int*  )d_in[2];
    const float* kxyz = (const float*)d_in[3];
    const float* fc1w = (const float*)d_in[4];
    const float* fc1b = (const float*)d_in[5];
    const float* fc2w = (const float*)d_in[6];
    const float* fc2b = (const float*)d_in[7];
    const float* d1w  = (const float*)d_in[8];
    const float* d1b  = (const float*)d_in[9];
    const float* d2w  = (const float*)d_in[10];
    const float* d2b  = (const float*)d_in[11];
    const float* g1w  = (const float*)d_in[12];
    const float* g1b  = (const float*)d_in[13];
    const float* g2w  = (const float*)d_in[14];
    const float* g2b  = (const float*)d_in[15];
    float* out = (float*)d_out;

    int sms = 148;
    cudaDeviceGetAttribute(&sms, cudaDevAttrMultiProcessorCount, 0);

    cudaFuncSetAttribute(k_fc1m, cudaFuncAttributeMaxDynamicSharedMemorySize, F1_SZ);
    cudaFuncSetAttribute(k2,     cudaFuncAttributeMaxDynamicSharedMemorySize, K2_SZ);
    cudaFuncSetAttribute(k_fc2m, cudaFuncAttributeMaxDynamicSharedMemorySize, F2_SZ);

    k_fc1m<<<NT2, 256, F1_SZ>>>(feat, fc1w, fc1b);
    k2    <<<sms, 256, K2_SZ>>>(xyz, knn, kxyz, d1w, d1b, d2w, d2b,
                                g1w, g1b, g2w, g2b);
    k_soft<<<NP,  128       >>>(knn, out + RES_ELEMS);
    k_fc2m<<<NT2, 256, F2_SZ>>>(fc2w, fc2b, out);
}